// round 9
// baseline (speedup 1.0000x reference)
#include <cuda_runtime.h>

#define NTOK 16384
#define DM   512
#define FFD  2048
#define QKVD 1536
#define CHD  128
#define XFD  4096
#define NB   512

// ---------------- scratch (device globals; no cudaMalloc allowed) ----------
__device__ float g_x   [NTOK*DM];
__device__ float g_h   [NTOK*DM];
__device__ float g_qkv [NTOK*QKVD];
__device__ float g_attn[NTOK*DM];
__device__ float g_ff  [NTOK*FFD];
__device__ float g_xf  [NTOK*CHD];     // == (512, 4096) row-major
__device__ float g_A   [NB*1024];
__device__ float g_W   [NB*1024];
__device__ float g_nx  [NB];
__device__ float g_np  [NB];
__device__ float g_rmax[NB];
__device__ float g_rsum[NB];
__device__ float g_cmax[1024];
__device__ float g_csum[1024];
__device__ float g_part[256];

// ---------------- block reductions ----------------------------------------
__device__ __forceinline__ float block_reduce_sum(float v, float* sh) {
    int lane = threadIdx.x & 31, w = threadIdx.x >> 5;
    #pragma unroll
    for (int off = 16; off; off >>= 1) v += __shfl_xor_sync(0xffffffffu, v, off);
    if (lane == 0) sh[w] = v;
    __syncthreads();
    int nw = blockDim.x >> 5;
    if (w == 0) {
        float r = (lane < nw) ? sh[lane] : 0.f;
        #pragma unroll
        for (int off = 4; off; off >>= 1) r += __shfl_xor_sync(0xffffffffu, r, off);
        if (lane == 0) sh[0] = r;
    }
    __syncthreads();
    float res = sh[0];
    __syncthreads();
    return res;
}

__device__ __forceinline__ float block_reduce_max(float v, float* sh) {
    int lane = threadIdx.x & 31, w = threadIdx.x >> 5;
    #pragma unroll
    for (int off = 16; off; off >>= 1) v = fmaxf(v, __shfl_xor_sync(0xffffffffu, v, off));
    if (lane == 0) sh[w] = v;
    __syncthreads();
    int nw = blockDim.x >> 5;
    if (w == 0) {
        float r = (lane < nw) ? sh[lane] : -1e30f;
        #pragma unroll
        for (int off = 4; off; off >>= 1) r = fmaxf(r, __shfl_xor_sync(0xffffffffu, r, off));
        if (lane == 0) sh[0] = r;
    }
    __syncthreads();
    float res = sh[0];
    __syncthreads();
    return res;
}

// ---------------- tiled SGEMM: C = A(NxK) @ Bw(MxK)^T + epilogue ----------
// EPI 0: +bias  | 1: relu(+bias) | 2: +bias+resid | 3: cdist->A (-sqrt, diag)
#define BM 128
#define BN 64
#define BK 16
#define PAD_A (BM+4)
#define PAD_B (BN+4)

template<int EPI>
__global__ void __launch_bounds__(256)
gemm_tn(const float* __restrict__ A, const float* __restrict__ Bw,
        const float* __restrict__ bias, const float* resid,
        float* C, int N, int M, int K,
        const float* __restrict__ B2,
        const float* __restrict__ nx, const float* __restrict__ ny,
        const float* __restrict__ ny2)
{
    __shared__ float As[BK][PAD_A];
    __shared__ float Bs[BK][PAD_B];
    const int tid = threadIdx.x;
    const int tx = tid & 15, ty = tid >> 4;
    const int n0 = blockIdx.y * BM;
    const int m0 = blockIdx.x * BN;

    const int ar0 = tid >> 2;
    const int ac4 = (tid & 3) << 2;
    const float* aptr0 = A + (size_t)(n0 + ar0)      * K + ac4;
    const float* aptr1 = A + (size_t)(n0 + ar0 + 64) * K + ac4;

    const int brow = tid >> 2;
    const int bc4  = (tid & 3) << 2;
    const int m_ld = m0 + brow;
    const float* bptr;
    if (EPI == 3 && m_ld >= 512)
        bptr = B2 + (size_t)(m_ld - 512) * K + bc4;
    else
        bptr = Bw + (size_t)m_ld * K + bc4;

    float acc[8][4];
    #pragma unroll
    for (int i = 0; i < 8; i++)
        #pragma unroll
        for (int j = 0; j < 4; j++) acc[i][j] = 0.f;

    for (int k0 = 0; k0 < K; k0 += BK) {
        float4 a0 = *reinterpret_cast<const float4*>(aptr0 + k0);
        float4 a1 = *reinterpret_cast<const float4*>(aptr1 + k0);
        float4 b0 = *reinterpret_cast<const float4*>(bptr + k0);
        As[ac4+0][ar0]    = a0.x; As[ac4+1][ar0]    = a0.y; As[ac4+2][ar0]    = a0.z; As[ac4+3][ar0]    = a0.w;
        As[ac4+0][ar0+64] = a1.x; As[ac4+1][ar0+64] = a1.y; As[ac4+2][ar0+64] = a1.z; As[ac4+3][ar0+64] = a1.w;
        Bs[bc4+0][brow] = b0.x; Bs[bc4+1][brow] = b0.y; Bs[bc4+2][brow] = b0.z; Bs[bc4+3][brow] = b0.w;
        __syncthreads();
        #pragma unroll
        for (int k = 0; k < BK; k++) {
            float4 af0 = *reinterpret_cast<const float4*>(&As[k][ty*8]);
            float4 af1 = *reinterpret_cast<const float4*>(&As[k][ty*8+4]);
            float4 bf  = *reinterpret_cast<const float4*>(&Bs[k][tx*4]);
            float a_[8] = {af0.x, af0.y, af0.z, af0.w, af1.x, af1.y, af1.z, af1.w};
            float b_[4] = {bf.x, bf.y, bf.z, bf.w};
            #pragma unroll
            for (int i = 0; i < 8; i++)
                #pragma unroll
                for (int j = 0; j < 4; j++) acc[i][j] += a_[i] * b_[j];
        }
        __syncthreads();
    }

    const int nr0 = n0 + ty * 8;
    const int mc0 = m0 + tx * 4;
    float4 bv = make_float4(0.f, 0.f, 0.f, 0.f);
    if (EPI != 3) bv = *reinterpret_cast<const float4*>(bias + mc0);

    #pragma unroll
    for (int i = 0; i < 8; i++) {
        int n = nr0 + i;
        float4 out;
        if (EPI == 3) {
            float nxi = nx[n];
            float r[4];
            #pragma unroll
            for (int j = 0; j < 4; j++) {
                int m = mc0 + j;
                float nyv = (m < 512) ? ny[m] : ny2[m - 512];
                float d2 = nxi + nyv - 2.f * acc[i][j];
                float a = -sqrtf(fmaxf(d2, 0.f));
                if (m >= 512 && (m - 512) == n) a -= 1e6f;
                r[j] = a;
            }
            out = make_float4(r[0], r[1], r[2], r[3]);
        } else {
            out = make_float4(acc[i][0] + bv.x, acc[i][1] + bv.y,
                              acc[i][2] + bv.z, acc[i][3] + bv.w);
            if (EPI == 1) {
                out.x = fmaxf(out.x, 0.f); out.y = fmaxf(out.y, 0.f);
                out.z = fmaxf(out.z, 0.f); out.w = fmaxf(out.w, 0.f);
            }
            if (EPI == 2) {
                float4 rv = *reinterpret_cast<const float4*>(resid + (size_t)n * M + mc0);
                out.x += rv.x; out.y += rv.y; out.z += rv.z; out.w += rv.w;
            }
        }
        *reinterpret_cast<float4*>(C + (size_t)n * M + mc0) = out;
    }
}

// ---------------- NN GEMM with fused squared-sum: V = W @ Y, sum(V^2) ------
__global__ void __launch_bounds__(256)
vgemm_sq(const float* __restrict__ W, const float* __restrict__ P,
         const float* __restrict__ XF, float* __restrict__ part)
{
    const int K = 1024, M = XFD;
    __shared__ float As[BK][PAD_A];
    __shared__ float Bs[BK][PAD_B];
    __shared__ float shred[32];
    const int tid = threadIdx.x;
    const int tx = tid & 15, ty = tid >> 4;
    const int n0 = blockIdx.y * BM;
    const int m0 = blockIdx.x * BN;

    const int ar0 = tid >> 2;
    const int ac4 = (tid & 3) << 2;
    const float* aptr0 = W + (size_t)(n0 + ar0)      * K + ac4;
    const float* aptr1 = W + (size_t)(n0 + ar0 + 64) * K + ac4;
    const int brow = tid >> 4;          // 0..15 (k)
    const int bc4  = (tid & 15) << 2;   // 0..60 (m)

    float acc[8][4];
    #pragma unroll
    for (int i = 0; i < 8; i++)
        #pragma unroll
        for (int j = 0; j < 4; j++) acc[i][j] = 0.f;

    for (int k0 = 0; k0 < K; k0 += BK) {
        float4 a0 = *reinterpret_cast<const float4*>(aptr0 + k0);
        float4 a1 = *reinterpret_cast<const float4*>(aptr1 + k0);
        int krow = k0 + brow;
        const float* ysrc = (krow < 512) ? P + (size_t)krow * M
                                         : XF + (size_t)(krow - 512) * M;
        float4 b0 = *reinterpret_cast<const float4*>(ysrc + m0 + bc4);
        As[ac4+0][ar0]    = a0.x; As[ac4+1][ar0]    = a0.y; As[ac4+2][ar0]    = a0.z; As[ac4+3][ar0]    = a0.w;
        As[ac4+0][ar0+64] = a1.x; As[ac4+1][ar0+64] = a1.y; As[ac4+2][ar0+64] = a1.z; As[ac4+3][ar0+64] = a1.w;
        *reinterpret_cast<float4*>(&Bs[brow][bc4]) = b0;
        __syncthreads();
        #pragma unroll
        for (int k = 0; k < BK; k++) {
            float4 af0 = *reinterpret_cast<const float4*>(&As[k][ty*8]);
            float4 af1 = *reinterpret_cast<const float4*>(&As[k][ty*8+4]);
            float4 bf  = *reinterpret_cast<const float4*>(&Bs[k][tx*4]);
            float a_[8] = {af0.x, af0.y, af0.z, af0.w, af1.x, af1.y, af1.z, af1.w};
            float b_[4] = {bf.x, bf.y, bf.z, bf.w};
            #pragma unroll
            for (int i = 0; i < 8; i++)
                #pragma unroll
                for (int j = 0; j < 4; j++) acc[i][j] += a_[i] * b_[j];
        }
        __syncthreads();
    }

    float ss = 0.f;
    #pragma unroll
    for (int i = 0; i < 8; i++)
        #pragma unroll
        for (int j = 0; j < 4; j++) ss += acc[i][j] * acc[i][j];
    float tot = block_reduce_sum(ss, shred);
    if (tid == 0) part[blockIdx.y * gridDim.x + blockIdx.x] = tot;
}

// ---------------- LayerNorm (one token per block, 128 threads) -------------
__global__ void __launch_bounds__(128)
ln_kernel(const float* __restrict__ x, const float* __restrict__ g,
          const float* __restrict__ b, float* __restrict__ out)
{
    int t = blockIdx.x;
    int tid = threadIdx.x;
    const float* xr = x + (size_t)t * DM;
    float4 v = *reinterpret_cast<const float4*>(xr + tid * 4);
    float s  = v.x + v.y + v.z + v.w;
    float sq = v.x*v.x + v.y*v.y + v.z*v.z + v.w*v.w;
    int lane = tid & 31, w = tid >> 5;
    #pragma unroll
    for (int off = 16; off; off >>= 1) {
        s  += __shfl_xor_sync(0xffffffffu, s,  off);
        sq += __shfl_xor_sync(0xffffffffu, sq, off);
    }
    __shared__ float shs[4], shq[4];
    if (lane == 0) { shs[w] = s; shq[w] = sq; }
    __syncthreads();
    s  = shs[0] + shs[1] + shs[2] + shs[3];
    sq = shq[0] + shq[1] + shq[2] + shq[3];
    float mean = s * (1.f / 512.f);
    float var  = sq * (1.f / 512.f) - mean * mean;
    float inv  = rsqrtf(var + 1e-5f);
    float4 gv = *reinterpret_cast<const float4*>(g + tid * 4);
    float4 bv = *reinterpret_cast<const float4*>(b + tid * 4);
    float4 o;
    o.x = (v.x - mean) * inv * gv.x + bv.x;
    o.y = (v.y - mean) * inv * gv.y + bv.y;
    o.z = (v.z - mean) * inv * gv.z + bv.z;
    o.w = (v.w - mean) * inv * gv.w + bv.w;
    *reinterpret_cast<float4*>(out + (size_t)t * DM + tid * 4) = o;
}

// ---------------- attention: one (batch, head) per block --------------------
__global__ void __launch_bounds__(256)
attn_kernel(const float* __restrict__ qkv, float* __restrict__ o)
{
    __shared__ float qs[32][64];
    __shared__ float ks[32][65];
    __shared__ float vs[32][64];
    __shared__ float ps[32][33];
    int bh = blockIdx.x;
    int b = bh >> 3, h = bh & 7;
    int tid = threadIdx.x;
    size_t base = (size_t)(b * 32) * QKVD + h * 64;
    #pragma unroll
    for (int l = 0; l < 2; l++) {
        int idx = tid + l * 256;
        int i = idx >> 4;
        int c = (idx & 15) << 2;
        float4 qv = *reinterpret_cast<const float4*>(qkv + base + (size_t)i * QKVD + c);
        float4 kv = *reinterpret_cast<const float4*>(qkv + base + (size_t)i * QKVD + 512 + c);
        float4 vv = *reinterpret_cast<const float4*>(qkv + base + (size_t)i * QKVD + 1024 + c);
        *reinterpret_cast<float4*>(&qs[i][c]) = qv;
        ks[i][c] = kv.x; ks[i][c+1] = kv.y; ks[i][c+2] = kv.z; ks[i][c+3] = kv.w;
        *reinterpret_cast<float4*>(&vs[i][c]) = vv;
    }
    __syncthreads();
    {   // scores, scaled by 1/sqrt(64)
        int i = tid >> 3;
        int j0 = (tid & 7) << 2;
        float s0 = 0.f, s1 = 0.f, s2 = 0.f, s3 = 0.f;
        #pragma unroll
        for (int d = 0; d < 64; d++) {
            float q = qs[i][d];
            s0 += q * ks[j0+0][d];
            s1 += q * ks[j0+1][d];
            s2 += q * ks[j0+2][d];
            s3 += q * ks[j0+3][d];
        }
        ps[i][j0]   = s0 * 0.125f;
        ps[i][j0+1] = s1 * 0.125f;
        ps[i][j0+2] = s2 * 0.125f;
        ps[i][j0+3] = s3 * 0.125f;
    }
    __syncthreads();
    {   // softmax per row (one warp handles 4 rows)
        int w = tid >> 5, lane = tid & 31;
        #pragma unroll
        for (int r = 0; r < 4; r++) {
            int i = w + (r << 3);
            float v = ps[i][lane];
            float mx = v;
            #pragma unroll
            for (int off = 16; off; off >>= 1) mx = fmaxf(mx, __shfl_xor_sync(0xffffffffu, mx, off));
            float e = __expf(v - mx);
            float sm = e;
            #pragma unroll
            for (int off = 16; off; off >>= 1) sm += __shfl_xor_sync(0xffffffffu, sm, off);
            ps[i][lane] = e / sm;
        }
    }
    __syncthreads();
    {   // o = p @ v
        int i = tid >> 3;
        int d0 = (tid & 7) << 3;
        float acc[8] = {0.f,0.f,0.f,0.f,0.f,0.f,0.f,0.f};
        #pragma unroll
        for (int j = 0; j < 32; j++) {
            float pv = ps[i][j];
            #pragma unroll
            for (int dd = 0; dd < 8; dd++) acc[dd] += pv * vs[j][d0 + dd];
        }
        float* op = o + (size_t)(b * 32 + i) * DM + h * 64 + d0;
        *reinterpret_cast<float4*>(op)     = make_float4(acc[0], acc[1], acc[2], acc[3]);
        *reinterpret_cast<float4*>(op + 4) = make_float4(acc[4], acc[5], acc[6], acc[7]);
    }
}

// ---------------- squared norms of xf rows and p rows -----------------------
__global__ void __launch_bounds__(256)
sqnorm_kernel(const float* __restrict__ xf, const float* __restrict__ p,
              float* __restrict__ nx, float* __restrict__ np)
{
    int r = blockIdx.x;
    const float* src = (r < 512) ? xf + (size_t)r * XFD : p + (size_t)(r - 512) * XFD;
    float s = 0.f;
    for (int c = threadIdx.x * 4; c < XFD; c += 256 * 4) {
        float4 v = *reinterpret_cast<const float4*>(src + c);
        s += v.x*v.x + v.y*v.y + v.z*v.z + v.w*v.w;
    }
    __shared__ float sh[32];
    float tot = block_reduce_sum(s, sh);
    if (threadIdx.x == 0) { if (r < 512) nx[r] = tot; else np[r - 512] = tot; }
}

// ---------------- row stats of A (max, sum of exp) ---------------------------
__global__ void __launch_bounds__(256)
rowstats_kernel(const float* __restrict__ A, float* __restrict__ rmax,
                float* __restrict__ rsum)
{
    int r = blockIdx.x;
    const float* ar = A + (size_t)r * 1024;
    float v[4];
    float mx = -1e30f;
    #pragma unroll
    for (int l = 0; l < 4; l++) { v[l] = ar[threadIdx.x + l * 256]; mx = fmaxf(mx, v[l]); }
    __shared__ float sh[32];
    mx = block_reduce_max(mx, sh);
    float s = 0.f;
    #pragma unroll
    for (int l = 0; l < 4; l++) s += __expf(v[l] - mx);
    s = block_reduce_sum(s, sh);
    if (threadIdx.x == 0) { rmax[r] = mx; rsum[r] = s; }
}

// ---------------- column stats of A ----------------------------------------
__global__ void __launch_bounds__(256)
colstats_kernel(const float* __restrict__ A, float* __restrict__ cmax,
                float* __restrict__ csum)
{
    int c = blockIdx.x * 256 + threadIdx.x;
    float mx = -1e30f;
    for (int i = 0; i < 512; i++) mx = fmaxf(mx, A[(size_t)i * 1024 + c]);
    float s = 0.f;
    for (int i = 0; i < 512; i++) s += __expf(A[(size_t)i * 1024 + c] - mx);
    cmax[c] = mx; csum[c] = s;
}

// ---------------- build W = [A_pos*sneg | -(A_neg*spos)] --------------------
__global__ void __launch_bounds__(256)
wbuild_kernel(const float* __restrict__ A, const float* __restrict__ rmax,
              const float* __restrict__ rsum, const float* __restrict__ cmax,
              const float* __restrict__ csum, float* __restrict__ W)
{
    int r = blockIdx.x;
    int j0 = threadIdx.x * 4;
    float rm = rmax[r];
    float rs = rsum[r];
    float4 a = *reinterpret_cast<const float4*>(A + (size_t)r * 1024 + j0);
    float av[4] = {a.x, a.y, a.z, a.w};
    float soft[4];
    float lsum = 0.f;
    #pragma unroll
    for (int l = 0; l < 4; l++) {
        int j = j0 + l;
        float s = __expf(av[l] - 0.5f * (rm + cmax[j])) * rsqrtf(rs * csum[j]);
        soft[l] = s;
        lsum += s;
    }
    bool isneg = (threadIdx.x >= 128);   // j0 >= 512
    __shared__ float sh[32];
    float sp = block_reduce_sum(isneg ? 0.f : lsum, sh);
    float sn = block_reduce_sum(isneg ? lsum : 0.f, sh);
    float scale = isneg ? -(sp * sn) : sn;
    float4 o = make_float4(soft[0]*scale, soft[1]*scale, soft[2]*scale, soft[3]*scale);
    *reinterpret_cast<float4*>(W + (size_t)r * 1024 + j0) = o;
}

// ---------------- final reduce → mean(V^2) ----------------------------------
__global__ void __launch_bounds__(256)
finalize_kernel(const float* __restrict__ part, float* __restrict__ out)
{
    __shared__ float sh[32];
    float v = part[threadIdx.x];
    float tot = block_reduce_sum(v, sh);
    if (threadIdx.x == 0) out[0] = tot * (1.f / (512.f * 4096.f));
}

// ---------------- host launch ------------------------------------------------
extern "C" void kernel_launch(void* const* d_in, const int* in_sizes, int n_in,
                              void* d_out, int out_size)
{
    (void)in_sizes; (void)n_in; (void)out_size;
    const float* p     = (const float*)d_in[0];
    const float* eps   = (const float*)d_in[1];
    const float* in_w  = (const float*)d_in[2];
    const float* in_b  = (const float*)d_in[3];
    const float* Wqkv  = (const float*)d_in[4];
    const float* bqkv  = (const float*)d_in[5];
    const float* Wo    = (const float*)d_in[6];
    const float* bo    = (const float*)d_in[7];
    const float* ln1g  = (const float*)d_in[8];
    const float* ln1b  = (const float*)d_in[9];
    const float* W1    = (const float*)d_in[10];
    const float* b1    = (const float*)d_in[11];
    const float* W2    = (const float*)d_in[12];
    const float* b2    = (const float*)d_in[13];
    const float* ln2g  = (const float*)d_in[14];
    const float* ln2b  = (const float*)d_in[15];
    const float* out_w = (const float*)d_in[16];
    const float* out_b = (const float*)d_in[17];
    float* out = (float*)d_out;

    float *px, *ph, *pqkv, *pattn, *pff, *pxf, *pA, *pW;
    float *pnx, *pnp, *prmax, *prsum, *pcmax, *pcsum, *ppart;
    cudaGetSymbolAddress((void**)&px,    g_x);
    cudaGetSymbolAddress((void**)&ph,    g_h);
    cudaGetSymbolAddress((void**)&pqkv,  g_qkv);
    cudaGetSymbolAddress((void**)&pattn, g_attn);
    cudaGetSymbolAddress((void**)&pff,   g_ff);
    cudaGetSymbolAddress((void**)&pxf,   g_xf);
    cudaGetSymbolAddress((void**)&pA,    g_A);
    cudaGetSymbolAddress((void**)&pW,    g_W);
    cudaGetSymbolAddress((void**)&pnx,   g_nx);
    cudaGetSymbolAddress((void**)&pnp,   g_np);
    cudaGetSymbolAddress((void**)&prmax, g_rmax);
    cudaGetSymbolAddress((void**)&prsum, g_rsum);
    cudaGetSymbolAddress((void**)&pcmax, g_cmax);
    cudaGetSymbolAddress((void**)&pcsum, g_csum);
    cudaGetSymbolAddress((void**)&ppart, g_part);

    dim3 blk(256);

    // x = eps @ in_w^T + in_b
    gemm_tn<0><<<dim3(DM/BN, NTOK/BM), blk>>>(eps, in_w, in_b, nullptr, px,
                                              NTOK, DM, CHD, nullptr, nullptr, nullptr, nullptr);
    for (int i = 0; i < 4; i++) {
        ln_kernel<<<NTOK, 128>>>(px, ln1g + i*DM, ln1b + i*DM, ph);
        gemm_tn<0><<<dim3(QKVD/BN, NTOK/BM), blk>>>(ph, Wqkv + (size_t)i*QKVD*DM,
                                                    bqkv + (size_t)i*QKVD, nullptr, pqkv,
                                                    NTOK, QKVD, DM, nullptr, nullptr, nullptr, nullptr);
        attn_kernel<<<4096, 256>>>(pqkv, pattn);
        gemm_tn<2><<<dim3(DM/BN, NTOK/BM), blk>>>(pattn, Wo + (size_t)i*DM*DM,
                                                  bo + (size_t)i*DM, px, px,
                                                  NTOK, DM, DM, nullptr, nullptr, nullptr, nullptr);
        ln_kernel<<<NTOK, 128>>>(px, ln2g + i*DM, ln2b + i*DM, ph);
        gemm_tn<1><<<dim3(FFD/BN, NTOK/BM), blk>>>(ph, W1 + (size_t)i*FFD*DM,
                                                   b1 + (size_t)i*FFD, nullptr, pff,
                                                   NTOK, FFD, DM, nullptr, nullptr, nullptr, nullptr);
        gemm_tn<2><<<dim3(DM/BN, NTOK/BM), blk>>>(pff, W2 + (size_t)i*DM*FFD,
                                                  b2 + (size_t)i*DM, px, px,
                                                  NTOK, DM, FFD, nullptr, nullptr, nullptr, nullptr);
    }
    // xf = x @ out_w^T + out_b   (16384x128 == 512x4096)
    gemm_tn<0><<<dim3(CHD/BN, NTOK/BM), blk>>>(px, out_w, out_b, nullptr, pxf,
                                               NTOK, CHD, DM, nullptr, nullptr, nullptr, nullptr);

    // compute_V
    sqnorm_kernel<<<1024, 256>>>(pxf, p, pnx, pnp);
    // A = [-cdist(xf,p) | -cdist(xf,xf) - eye*1e6]
    gemm_tn<3><<<dim3(1024/BN, NB/BM), blk>>>(pxf, p, nullptr, nullptr, pA,
                                              NB, 1024, XFD, pxf, pnx, pnp, pnx);
    rowstats_kernel<<<NB, 256>>>(pA, prmax, prsum);
    colstats_kernel<<<4, 256>>>(pA, pcmax, pcsum);
    wbuild_kernel<<<NB, 256>>>(pA, prmax, prsum, pcmax, pcsum, pW);
    // V = W @ [p; xf], fused sum(V^2)
    vgemm_sq<<<dim3(XFD/BN, NB/BM), blk>>>(pW, p, pxf, ppart);
    finalize_kernel<<<1, 256>>>(ppart, out);
}

// round 12
// speedup vs baseline: 2.5699x; 2.5699x over previous
#include <cuda_runtime.h>
#include <cstdint>

#define NTOK 16384
#define DM   512
#define FFD  2048
#define QKVD 1536
#define CHD  128
#define XFD  4096
#define NB   512

// ---------------- scratch (device globals; no cudaMalloc allowed) ----------
__device__ float g_x   [NTOK*DM];
__device__ float g_h   [NTOK*DM];
__device__ float g_qkv [NTOK*QKVD];
__device__ float g_attn[NTOK*DM];
__device__ float g_ff  [NTOK*FFD];     // also rounded-eps scratch early
__device__ float g_xf  [NTOK*CHD];     // == (512, 4096) row-major
__device__ float g_A   [NB*1024];
__device__ float g_W   [NB*1024];
__device__ float g_nx  [NB];
__device__ float g_np  [NB];
__device__ float g_rmax[NB];
__device__ float g_rsum[NB];
__device__ float g_cmax[1024];
__device__ float g_csum[1024];
__device__ float g_part[256];
// rounded weights: in_w | Wqkv | Wo | W1 | W2 | out_w
#define R_INW  0
#define R_QKV  65536
#define R_WO   (R_QKV + 4*QKVD*DM)
#define R_W1   (R_WO  + 4*DM*DM)
#define R_W2   (R_W1  + 4*FFD*DM)
#define R_OUTW (R_W2  + 4*DM*FFD)
#define R_TOT  (R_OUTW + CHD*DM)
__device__ float g_wts[R_TOT];

// ---------------- tf32 round-to-nearest -----------------------------------
__device__ __forceinline__ float rnd_tf32(float x) {
    uint32_t u;
    asm("cvt.rna.tf32.f32 %0, %1;" : "=r"(u) : "f"(x));
    return __uint_as_float(u);
}

__global__ void __launch_bounds__(256)
round_tf32_kernel(const float* __restrict__ src, float* __restrict__ dst, int n)
{
    int i = (blockIdx.x * 256 + threadIdx.x) * 4;
    if (i < n) {
        float4 v = *reinterpret_cast<const float4*>(src + i);
        v.x = rnd_tf32(v.x); v.y = rnd_tf32(v.y);
        v.z = rnd_tf32(v.z); v.w = rnd_tf32(v.w);
        *reinterpret_cast<float4*>(dst + i) = v;
    }
}

__device__ __forceinline__ uint32_t smem_u32(const void* p) {
    uint32_t a;
    asm("{ .reg .u64 t; cvta.to.shared.u64 t, %1; cvt.u32.u64 %0, t; }" : "=r"(a) : "l"(p));
    return a;
}

#define MMA_TF32(c, a, b)                                                     \
    asm volatile("mma.sync.aligned.m16n8k8.row.col.f32.tf32.tf32.f32 "        \
        "{%0,%1,%2,%3}, {%4,%5,%6,%7}, {%8,%9}, {%0,%1,%2,%3};"               \
        : "+f"((c)[0]), "+f"((c)[1]), "+f"((c)[2]), "+f"((c)[3])              \
        : "r"((a)[0]), "r"((a)[1]), "r"((a)[2]), "r"((a)[3]),                 \
          "r"((b)[0]), "r"((b)[1]))

// ---------------- tf32 mma.sync GEMM: C = A(NxK) @ Bw(MxK)^T ---------------
// block tile 128 (tokens) x 128 (features) x 32, 8 warps, warp tile 64x32
// EPI 0: +bias | 1: relu(+bias) rounded to tf32 | 2: +bias+resid
#define TROW 36
#define TILE_F (128*TROW)
#define MM_SMEM (4*TILE_F*4)   // 73728 bytes

template<int EPI>
__global__ void __launch_bounds__(256)
mma_gemm(const float* __restrict__ A, const float* __restrict__ Bw,
         const float* __restrict__ bias, const float* resid,
         float* __restrict__ C, int M, int K)
{
    extern __shared__ float sm[];
    float* As = sm;               // [2][TILE_F]
    float* Bs = sm + 2*TILE_F;    // [2][TILE_F]

    const int tid  = threadIdx.x;
    const int w    = tid >> 5;
    const int lane = tid & 31;
    const int g    = lane >> 2;
    const int tig  = lane & 3;
    const int wm   = (w & 1) * 64;     // warp row block (tokens)
    const int wn   = (w >> 1) * 32;    // warp col block (features)
    const int n0   = blockIdx.y * 128;
    const int m0   = blockIdx.x * 128;

    // cp.async geometry: 8 chunks(16B) per row, 32 rows per thread-wave
    const int rb = tid >> 3;          // 0..31
    const int cc = (tid & 7) * 4;     // float col of chunk

    float acc[4][4][4];
    #pragma unroll
    for (int mt = 0; mt < 4; mt++)
        #pragma unroll
        for (int nt = 0; nt < 4; nt++)
            #pragma unroll
            for (int r = 0; r < 4; r++) acc[mt][nt][r] = 0.f;

    auto preload = [&](int kt, int buf) {
        float* sa = As + buf * TILE_F;
        float* sb = Bs + buf * TILE_F;
        const float* gA = A  + (size_t)(n0 + rb) * K + kt * 32 + cc;
        const float* gB = Bw + (size_t)(m0 + rb) * K + kt * 32 + cc;
        #pragma unroll
        for (int i = 0; i < 4; i++) {
            uint32_t da = smem_u32(sa + (rb + i*32) * TROW + cc);
            uint32_t db = smem_u32(sb + (rb + i*32) * TROW + cc);
            asm volatile("cp.async.cg.shared.global [%0], [%1], 16;"
                         :: "r"(da), "l"(gA + (size_t)i * 32 * K));
            asm volatile("cp.async.cg.shared.global [%0], [%1], 16;"
                         :: "r"(db), "l"(gB + (size_t)i * 32 * K));
        }
        asm volatile("cp.async.commit_group;" ::: "memory");
    };

    const int KT = K >> 5;
    preload(0, 0);
    for (int kt = 0; kt < KT; kt++) {
        const int buf = kt & 1;
        if (kt + 1 < KT) {
            preload(kt + 1, buf ^ 1);
            asm volatile("cp.async.wait_group 1;" ::: "memory");
        } else {
            asm volatile("cp.async.wait_group 0;" ::: "memory");
        }
        __syncthreads();

        const float* a_s = As + buf * TILE_F + wm * TROW;
        const float* b_s = Bs + buf * TILE_F + wn * TROW;
        #pragma unroll
        for (int ks = 0; ks < 4; ks++) {
            const int kc = ks * 8;
            uint32_t af[4][4], bf[4][2];
            #pragma unroll
            for (int mt = 0; mt < 4; mt++) {
                const float* ap = a_s + (mt * 16) * TROW + kc;
                af[mt][0] = __float_as_uint(ap[(g)     * TROW + tig]);
                af[mt][1] = __float_as_uint(ap[(g + 8) * TROW + tig]);
                af[mt][2] = __float_as_uint(ap[(g)     * TROW + tig + 4]);
                af[mt][3] = __float_as_uint(ap[(g + 8) * TROW + tig + 4]);
            }
            #pragma unroll
            for (int nt = 0; nt < 4; nt++) {
                const float* bp = b_s + (nt * 8 + g) * TROW + kc;
                bf[nt][0] = __float_as_uint(bp[tig]);
                bf[nt][1] = __float_as_uint(bp[tig + 4]);
            }
            #pragma unroll
            for (int mt = 0; mt < 4; mt++)
                #pragma unroll
                for (int nt = 0; nt < 4; nt++)
                    MMA_TF32(acc[mt][nt], af[mt], bf[nt]);
        }
        __syncthreads();
    }

    // epilogue
    #pragma unroll
    for (int mt = 0; mt < 4; mt++) {
        const int r0 = n0 + wm + mt * 16 + g;
        #pragma unroll
        for (int nt = 0; nt < 4; nt++) {
            const int c = m0 + wn + nt * 8 + 2 * tig;
            const float2 bv = *reinterpret_cast<const float2*>(bias + c);
            float v00 = acc[mt][nt][0] + bv.x;
            float v01 = acc[mt][nt][1] + bv.y;
            float v10 = acc[mt][nt][2] + bv.x;
            float v11 = acc[mt][nt][3] + bv.y;
            if (EPI == 1) {
                v00 = rnd_tf32(fmaxf(v00, 0.f)); v01 = rnd_tf32(fmaxf(v01, 0.f));
                v10 = rnd_tf32(fmaxf(v10, 0.f)); v11 = rnd_tf32(fmaxf(v11, 0.f));
            }
            if (EPI == 2) {
                float2 q0 = *reinterpret_cast<const float2*>(resid + (size_t)r0 * M + c);
                float2 q1 = *reinterpret_cast<const float2*>(resid + (size_t)(r0 + 8) * M + c);
                v00 += q0.x; v01 += q0.y; v10 += q1.x; v11 += q1.y;
            }
            *reinterpret_cast<float2*>(C + (size_t)r0 * M + c)       = make_float2(v00, v01);
            *reinterpret_cast<float2*>(C + (size_t)(r0 + 8) * M + c) = make_float2(v10, v11);
        }
    }
}

// ---------------- block reductions ----------------------------------------
__device__ __forceinline__ float block_reduce_sum(float v, float* sh) {
    int lane = threadIdx.x & 31, w = threadIdx.x >> 5;
    #pragma unroll
    for (int off = 16; off; off >>= 1) v += __shfl_xor_sync(0xffffffffu, v, off);
    if (lane == 0) sh[w] = v;
    __syncthreads();
    int nw = blockDim.x >> 5;
    if (w == 0) {
        float r = (lane < nw) ? sh[lane] : 0.f;
        #pragma unroll
        for (int off = 4; off; off >>= 1) r += __shfl_xor_sync(0xffffffffu, r, off);
        if (lane == 0) sh[0] = r;
    }
    __syncthreads();
    float res = sh[0];
    __syncthreads();
    return res;
}

__device__ __forceinline__ float block_reduce_max(float v, float* sh) {
    int lane = threadIdx.x & 31, w = threadIdx.x >> 5;
    #pragma unroll
    for (int off = 16; off; off >>= 1) v = fmaxf(v, __shfl_xor_sync(0xffffffffu, v, off));
    if (lane == 0) sh[w] = v;
    __syncthreads();
    int nw = blockDim.x >> 5;
    if (w == 0) {
        float r = (lane < nw) ? sh[lane] : -1e30f;
        #pragma unroll
        for (int off = 4; off; off >>= 1) r = fmaxf(r, __shfl_xor_sync(0xffffffffu, r, off));
        if (lane == 0) sh[0] = r;
    }
    __syncthreads();
    float res = sh[0];
    __syncthreads();
    return res;
}

// ---------------- fp32 SIMT GEMM kept for the cdist epilogue ---------------
#define BM 128
#define BN 64
#define BK 16
#define PAD_A (BM+4)
#define PAD_B (BN+4)

__global__ void __launch_bounds__(256)
gemm_cdist(const float* __restrict__ A, const float* __restrict__ Bw,
           float* C, int N, int M, int K,
           const float* __restrict__ B2,
           const float* __restrict__ nx, const float* __restrict__ ny,
           const float* __restrict__ ny2)
{
    __shared__ float As[BK][PAD_A];
    __shared__ float Bs[BK][PAD_B];
    const int tid = threadIdx.x;
    const int tx = tid & 15, ty = tid >> 4;
    const int n0 = blockIdx.y * BM;
    const int m0 = blockIdx.x * BN;

    const int ar0 = tid >> 2;
    const int ac4 = (tid & 3) << 2;
    const float* aptr0 = A + (size_t)(n0 + ar0)      * K + ac4;
    const float* aptr1 = A + (size_t)(n0 + ar0 + 64) * K + ac4;

    const int brow = tid >> 2;
    const int bc4  = (tid & 3) << 2;
    const int m_ld = m0 + brow;
    const float* bptr = (m_ld >= 512) ? B2 + (size_t)(m_ld - 512) * K + bc4
                                      : Bw + (size_t)m_ld * K + bc4;

    float acc[8][4];
    #pragma unroll
    for (int i = 0; i < 8; i++)
        #pragma unroll
        for (int j = 0; j < 4; j++) acc[i][j] = 0.f;

    for (int k0 = 0; k0 < K; k0 += BK) {
        float4 a0 = *reinterpret_cast<const float4*>(aptr0 + k0);
        float4 a1 = *reinterpret_cast<const float4*>(aptr1 + k0);
        float4 b0 = *reinterpret_cast<const float4*>(bptr + k0);
        As[ac4+0][ar0]    = a0.x; As[ac4+1][ar0]    = a0.y; As[ac4+2][ar0]    = a0.z; As[ac4+3][ar0]    = a0.w;
        As[ac4+0][ar0+64] = a1.x; As[ac4+1][ar0+64] = a1.y; As[ac4+2][ar0+64] = a1.z; As[ac4+3][ar0+64] = a1.w;
        Bs[bc4+0][brow] = b0.x; Bs[bc4+1][brow] = b0.y; Bs[bc4+2][brow] = b0.z; Bs[bc4+3][brow] = b0.w;
        __syncthreads();
        #pragma unroll
        for (int k = 0; k < BK; k++) {
            float4 af0 = *reinterpret_cast<const float4*>(&As[k][ty*8]);
            float4 af1 = *reinterpret_cast<const float4*>(&As[k][ty*8+4]);
            float4 bf  = *reinterpret_cast<const float4*>(&Bs[k][tx*4]);
            float a_[8] = {af0.x, af0.y, af0.z, af0.w, af1.x, af1.y, af1.z, af1.w};
            float b_[4] = {bf.x, bf.y, bf.z, bf.w};
            #pragma unroll
            for (int i = 0; i < 8; i++)
                #pragma unroll
                for (int j = 0; j < 4; j++) acc[i][j] += a_[i] * b_[j];
        }
        __syncthreads();
    }

    const int nr0 = n0 + ty * 8;
    const int mc0 = m0 + tx * 4;
    #pragma unroll
    for (int i = 0; i < 8; i++) {
        int nn = nr0 + i;
        float nxi = nx[nn];
        float rr[4];
        #pragma unroll
        for (int j = 0; j < 4; j++) {
            int m = mc0 + j;
            float nyv = (m < 512) ? ny[m] : ny2[m - 512];
            float d2 = nxi + nyv - 2.f * acc[i][j];
            float a = -sqrtf(fmaxf(d2, 0.f));
            if (m >= 512 && (m - 512) == nn) a -= 1e6f;
            rr[j] = a;
        }
        *reinterpret_cast<float4*>(C + (size_t)nn * M + mc0) =
            make_float4(rr[0], rr[1], rr[2], rr[3]);
    }
}

// ---------------- NN GEMM with fused squared-sum: V = W @ Y, sum(V^2) ------
__global__ void __launch_bounds__(256)
vgemm_sq(const float* __restrict__ W, const float* __restrict__ P,
         const float* __restrict__ XF, float* __restrict__ part)
{
    const int K = 1024, M = XFD;
    __shared__ float As[BK][PAD_A];
    __shared__ float Bs[BK][PAD_B];
    __shared__ float shred[32];
    const int tid = threadIdx.x;
    const int tx = tid & 15, ty = tid >> 4;
    const int n0 = blockIdx.y * BM;
    const int m0 = blockIdx.x * BN;

    const int ar0 = tid >> 2;
    const int ac4 = (tid & 3) << 2;
    const float* aptr0 = W + (size_t)(n0 + ar0)      * K + ac4;
    const float* aptr1 = W + (size_t)(n0 + ar0 + 64) * K + ac4;
    const int brow = tid >> 4;
    const int bc4  = (tid & 15) << 2;

    float acc[8][4];
    #pragma unroll
    for (int i = 0; i < 8; i++)
        #pragma unroll
        for (int j = 0; j < 4; j++) acc[i][j] = 0.f;

    for (int k0 = 0; k0 < K; k0 += BK) {
        float4 a0 = *reinterpret_cast<const float4*>(aptr0 + k0);
        float4 a1 = *reinterpret_cast<const float4*>(aptr1 + k0);
        int krow = k0 + brow;
        const float* ysrc = (krow < 512) ? P + (size_t)krow * M
                                         : XF + (size_t)(krow - 512) * M;
        float4 b0 = *reinterpret_cast<const float4*>(ysrc + m0 + bc4);
        As[ac4+0][ar0]    = a0.x; As[ac4+1][ar0]    = a0.y; As[ac4+2][ar0]    = a0.z; As[ac4+3][ar0]    = a0.w;
        As[ac4+0][ar0+64] = a1.x; As[ac4+1][ar0+64] = a1.y; As[ac4+2][ar0+64] = a1.z; As[ac4+3][ar0+64] = a1.w;
        *reinterpret_cast<float4*>(&Bs[brow][bc4]) = b0;
        __syncthreads();
        #pragma unroll
        for (int k = 0; k < BK; k++) {
            float4 af0 = *reinterpret_cast<const float4*>(&As[k][ty*8]);
            float4 af1 = *reinterpret_cast<const float4*>(&As[k][ty*8+4]);
            float4 bf  = *reinterpret_cast<const float4*>(&Bs[k][tx*4]);
            float a_[8] = {af0.x, af0.y, af0.z, af0.w, af1.x, af1.y, af1.z, af1.w};
            float b_[4] = {bf.x, bf.y, bf.z, bf.w};
            #pragma unroll
            for (int i = 0; i < 8; i++)
                #pragma unroll
                for (int j = 0; j < 4; j++) acc[i][j] += a_[i] * b_[j];
        }
        __syncthreads();
    }

    float ss = 0.f;
    #pragma unroll
    for (int i = 0; i < 8; i++)
        #pragma unroll
        for (int j = 0; j < 4; j++) ss += acc[i][j] * acc[i][j];
    float tot = block_reduce_sum(ss, shred);
    if (tid == 0) part[blockIdx.y * gridDim.x + blockIdx.x] = tot;
}

// ---------------- LayerNorm (rounded output feeds tf32 MMA) ----------------
__global__ void __launch_bounds__(128)
ln_kernel(const float* __restrict__ x, const float* __restrict__ g,
          const float* __restrict__ b, float* __restrict__ out)
{
    int t = blockIdx.x;
    int tid = threadIdx.x;
    const float* xr = x + (size_t)t * DM;
    float4 v = *reinterpret_cast<const float4*>(xr + tid * 4);
    float s  = v.x + v.y + v.z + v.w;
    float sq = v.x*v.x + v.y*v.y + v.z*v.z + v.w*v.w;
    int lane = tid & 31, w = tid >> 5;
    #pragma unroll
    for (int off = 16; off; off >>= 1) {
        s  += __shfl_xor_sync(0xffffffffu, s,  off);
        sq += __shfl_xor_sync(0xffffffffu, sq, off);
    }
    __shared__ float shs[4], shq[4];
    if (lane == 0) { shs[w] = s; shq[w] = sq; }
    __syncthreads();
    s  = shs[0] + shs[1] + shs[2] + shs[3];
    sq = shq[0] + shq[1] + shq[2] + shq[3];
    float mean = s * (1.f / 512.f);
    float var  = sq * (1.f / 512.f) - mean * mean;
    float inv  = rsqrtf(var + 1e-5f);
    float4 gv = *reinterpret_cast<const float4*>(g + tid * 4);
    float4 bv = *reinterpret_cast<const float4*>(b + tid * 4);
    float4 o;
    o.x = rnd_tf32((v.x - mean) * inv * gv.x + bv.x);
    o.y = rnd_tf32((v.y - mean) * inv * gv.y + bv.y);
    o.z = rnd_tf32((v.z - mean) * inv * gv.z + bv.z);
    o.w = rnd_tf32((v.w - mean) * inv * gv.w + bv.w);
    *reinterpret_cast<float4*>(out + (size_t)t * DM + tid * 4) = o;
}

// ---------------- attention: one (batch, head) per block --------------------
__global__ void __launch_bounds__(256)
attn_kernel(const float* __restrict__ qkv, float* __restrict__ o)
{
    __shared__ float qs[32][64];
    __shared__ float ks[32][65];
    __shared__ float vs[32][64];
    __shared__ float ps[32][33];
    int bh = blockIdx.x;
    int b = bh >> 3, h = bh & 7;
    int tid = threadIdx.x;
    size_t base = (size_t)(b * 32) * QKVD + h * 64;
    #pragma unroll
    for (int l = 0; l < 2; l++) {
        int idx = tid + l * 256;
        int i = idx >> 4;
        int c = (idx & 15) << 2;
        float4 qv = *reinterpret_cast<const float4*>(qkv + base + (size_t)i * QKVD + c);
        float4 kv = *reinterpret_cast<const float4*>(qkv + base + (size_t)i * QKVD + 512 + c);
        float4 vv = *reinterpret_cast<const float4*>(qkv + base + (size_t)i * QKVD + 1024 + c);
        *reinterpret_cast<float4*>(&qs[i][c]) = qv;
        ks[i][c] = kv.x; ks[i][c+1] = kv.y; ks[i][c+2] = kv.z; ks[i][c+3] = kv.w;
        *reinterpret_cast<float4*>(&vs[i][c]) = vv;
    }
    __syncthreads();
    {
        int i = tid >> 3;
        int j0 = (tid & 7) << 2;
        float s0 = 0.f, s1 = 0.f, s2 = 0.f, s3 = 0.f;
        #pragma unroll
        for (int d = 0; d < 64; d++) {
            float q = qs[i][d];
            s0 += q * ks[j0+0][d];
            s1 += q * ks[j0+1][d];
            s2 += q * ks[j0+2][d];
            s3 += q * ks[j0+3][d];
        }
        ps[i][j0]   = s0 * 0.125f;
        ps[i][j0+1] = s1 * 0.125f;
        ps[i][j0+2] = s2 * 0.125f;
        ps[i][j0+3] = s3 * 0.125f;
    }
    __syncthreads();
    {
        int w = tid >> 5, lane = tid & 31;
        #pragma unroll
        for (int r = 0; r < 4; r++) {
            int i = w + (r << 3);
            float v = ps[i][lane];
            float mx = v;
            #pragma unroll
            for (int off = 16; off; off >>= 1) mx = fmaxf(mx, __shfl_xor_sync(0xffffffffu, mx, off));
            float e = __expf(v - mx);
            float sm = e;
            #pragma unroll
            for (int off = 16; off; off >>= 1) sm += __shfl_xor_sync(0xffffffffu, sm, off);
            ps[i][lane] = e / sm;
        }
    }
    __syncthreads();
    {
        int i = tid >> 3;
        int d0 = (tid & 7) << 3;
        float acc[8] = {0.f,0.f,0.f,0.f,0.f,0.f,0.f,0.f};
        #pragma unroll
        for (int j = 0; j < 32; j++) {
            float pv = ps[i][j];
            #pragma unroll
            for (int dd = 0; dd < 8; dd++) acc[dd] += pv * vs[j][d0 + dd];
        }
        #pragma unroll
        for (int dd = 0; dd < 8; dd++) acc[dd] = rnd_tf32(acc[dd]);
        float* op = o + (size_t)(b * 32 + i) * DM + h * 64 + d0;
        *reinterpret_cast<float4*>(op)     = make_float4(acc[0], acc[1], acc[2], acc[3]);
        *reinterpret_cast<float4*>(op + 4) = make_float4(acc[4], acc[5], acc[6], acc[7]);
    }
}

// ---------------- squared norms of xf rows and p rows -----------------------
__global__ void __launch_bounds__(256)
sqnorm_kernel(const float* __restrict__ xf, const float* __restrict__ p,
              float* __restrict__ nx, float* __restrict__ np)
{
    int r = blockIdx.x;
    const float* src = (r < 512) ? xf + (size_t)r * XFD : p + (size_t)(r - 512) * XFD;
    float s = 0.f;
    for (int c = threadIdx.x * 4; c < XFD; c += 256 * 4) {
        float4 v = *reinterpret_cast<const float4*>(src + c);
        s += v.x*v.x + v.y*v.y + v.z*v.z + v.w*v.w;
    }
    __shared__ float sh[32];
    float tot = block_reduce_sum(s, sh);
    if (threadIdx.x == 0) { if (r < 512) nx[r] = tot; else np[r - 512] = tot; }
}

// ---------------- row stats of A (max, sum of exp) ---------------------------
__global__ void __launch_bounds__(256)
rowstats_kernel(const float* __restrict__ A, float* __restrict__ rmax,
                float* __restrict__ rsum)
{
    int r = blockIdx.x;
    const float* ar = A + (size_t)r * 1024;
    float v[4];
    float mx = -1e30f;
    #pragma unroll
    for (int l = 0; l < 4; l++) { v[l] = ar[threadIdx.x + l * 256]; mx = fmaxf(mx, v[l]); }
    __shared__ float sh[32];
    mx = block_reduce_max(mx, sh);
    float s = 0.f;
    #pragma unroll
    for (int l = 0; l < 4; l++) s += __expf(v[l] - mx);
    s = block_reduce_sum(s, sh);
    if (threadIdx.x == 0) { rmax[r] = mx; rsum[r] = s; }
}

// ---------------- column stats of A ----------------------------------------
__global__ void __launch_bounds__(256)
colstats_kernel(const float* __restrict__ A, float* __restrict__ cmax,
                float* __restrict__ csum)
{
    int c = blockIdx.x * 256 + threadIdx.x;
    float mx = -1e30f;
    for (int i = 0; i < 512; i++) mx = fmaxf(mx, A[(size_t)i * 1024 + c]);
    float s = 0.f;
    for (int i = 0; i < 512; i++) s += __expf(A[(size_t)i * 1024 + c] - mx);
    cmax[c] = mx; csum[c] = s;
}

// ---------------- build W = [A_pos*sneg | -(A_neg*spos)] --------------------
__global__ void __launch_bounds__(256)
wbuild_kernel(const float* __restrict__ A, const float* __restrict__ rmax,
              const float* __restrict__ rsum, const float* __restrict__ cmax,
              const float* __restrict__ csum, float* __restrict__ W)
{
    int r = blockIdx.x;
    int j0 = threadIdx.x * 4;
    float rm = rmax[r];
    float rs = rsum[r];
    float4 a = *reinterpret_cast<const float4*>(A + (size_t)r * 1024 + j0);
    float av[4] = {a.x, a.y, a.z, a.w};
    float soft[4];
    float lsum = 0.f;
    #pragma unroll
    for (int l = 0; l < 4; l++) {
        int j = j0 + l;
        float s = __expf(av[l] - 0.5f * (rm + cmax[j])) * rsqrtf(rs * csum[j]);
        soft[l] = s;
        lsum += s;
    }
    bool isneg = (threadIdx.x >= 128);
    __shared__ float sh[32];
    float sp = block_reduce_sum(isneg ? 0.f : lsum, sh);
    float sn = block_reduce_sum(isneg ? lsum : 0.f, sh);
    float scale = isneg ? -(sp * sn) : sn;
    float4 o = make_float4(soft[0]*scale, soft[1]*scale, soft[2]*scale, soft[3]*scale);
    *reinterpret_cast<float4*>(W + (size_t)r * 1024 + j0) = o;
}

// ---------------- final reduce → mean(V^2) ----------------------------------
__global__ void __launch_bounds__(256)
finalize_kernel(const float* __restrict__ part, float* __restrict__ out)
{
    __shared__ float sh[32];
    float v = part[threadIdx.x];
    float tot = block_reduce_sum(v, sh);
    if (threadIdx.x == 0) out[0] = tot * (1.f / (512.f * 4096.f));
}

// ---------------- host launch ------------------------------------------------
extern "C" void kernel_launch(void* const* d_in, const int* in_sizes, int n_in,
                              void* d_out, int out_size)
{
    (void)in_sizes; (void)n_in; (void)out_size;
    const float* p     = (const float*)d_in[0];
    const float* eps   = (const float*)d_in[1];
    const float* in_w  = (const float*)d_in[2];
    const float* in_b  = (const float*)d_in[3];
    const float* Wqkv  = (const float*)d_in[4];
    const float* bqkv  = (const float*)d_in[5];
    const float* Wo    = (const float*)d_in[6];
    const float* bo    = (const float*)d_in[7];
    const float* ln1g  = (const float*)d_in[8];
    const float* ln1b  = (const float*)d_in[9];
    const float* W1    = (const float*)d_in[10];
    const float* b1    = (const float*)d_in[11];
    const float* W2    = (const float*)d_in[12];
    const float* b2    = (const float*)d_in[13];
    const float* ln2g  = (const float*)d_in[14];
    const float* ln2b  = (const float*)d_in[15];
    const float* out_w = (const float*)d_in[16];
    const float* out_b = (const float*)d_in[17];
    float* out = (float*)d_out;

    float *px, *ph, *pqkv, *pattn, *pff, *pxf, *pA, *pW, *pwts;
    float *pnx, *pnp, *prmax, *prsum, *pcmax, *pcsum, *ppart;
    cudaGetSymbolAddress((void**)&px,    g_x);
    cudaGetSymbolAddress((void**)&ph,    g_h);
    cudaGetSymbolAddress((void**)&pqkv,  g_qkv);
    cudaGetSymbolAddress((void**)&pattn, g_attn);
    cudaGetSymbolAddress((void**)&pff,   g_ff);
    cudaGetSymbolAddress((void**)&pxf,   g_xf);
    cudaGetSymbolAddress((void**)&pA,    g_A);
    cudaGetSymbolAddress((void**)&pW,    g_W);
    cudaGetSymbolAddress((void**)&pwts,  g_wts);
    cudaGetSymbolAddress((void**)&pnx,   g_nx);
    cudaGetSymbolAddress((void**)&pnp,   g_np);
    cudaGetSymbolAddress((void**)&prmax, g_rmax);
    cudaGetSymbolAddress((void**)&prsum, g_rsum);
    cudaGetSymbolAddress((void**)&pcmax, g_cmax);
    cudaGetSymbolAddress((void**)&pcsum, g_csum);
    cudaGetSymbolAddress((void**)&ppart, g_part);

    cudaFuncSetAttribute(mma_gemm<0>, cudaFuncAttributeMaxDynamicSharedMemorySize, MM_SMEM);
    cudaFuncSetAttribute(mma_gemm<1>, cudaFuncAttributeMaxDynamicSharedMemorySize, MM_SMEM);
    cudaFuncSetAttribute(mma_gemm<2>, cudaFuncAttributeMaxDynamicSharedMemorySize, MM_SMEM);

    dim3 blk(256);
    auto rblocks = [](int n) { return (n / 4 + 255) / 256; };

    // round weights + eps to tf32-nearest (removes truncation bias)
    round_tf32_kernel<<<rblocks(DM*CHD),    blk>>>(in_w,  pwts + R_INW,  DM*CHD);
    round_tf32_kernel<<<rblocks(4*QKVD*DM), blk>>>(Wqkv,  pwts + R_QKV,  4*QKVD*DM);
    round_tf32_kernel<<<rblocks(4*DM*DM),   blk>>>(Wo,    pwts + R_WO,   4*DM*DM);
    round_tf32_kernel<<<rblocks(4*FFD*DM),  blk>>>(W1,    pwts + R_W1,   4*FFD*DM);
    round_tf32_kernel<<<rblocks(4*DM*FFD),  blk>>>(W2,    pwts + R_W2,   4*DM*FFD);
    round_tf32_kernel<<<rblocks(CHD*DM),    blk>>>(out_w, pwts + R_OUTW, CHD*DM);
    round_tf32_kernel<<<rblocks(NTOK*CHD),  blk>>>(eps,   pff,           NTOK*CHD);

    // x = eps @ in_w^T + in_b
    mma_gemm<0><<<dim3(DM/128, NTOK/128), blk, MM_SMEM>>>(pff, pwts + R_INW, in_b,
                                                          nullptr, px, DM, CHD);
    for (int i = 0; i < 4; i++) {
        ln_kernel<<<NTOK, 128>>>(px, ln1g + i*DM, ln1b + i*DM, ph);
        mma_gemm<0><<<dim3(QKVD/128, NTOK/128), blk, MM_SMEM>>>(
            ph, pwts + R_QKV + (size_t)i*QKVD*DM, bqkv + (size_t)i*QKVD,
            nullptr, pqkv, QKVD, DM);
        attn_kernel<<<4096, 256>>>(pqkv, pattn);
        mma_gemm<2><<<dim3(DM/128, NTOK/128), blk, MM_SMEM>>>(
            pattn, pwts + R_WO + (size_t)i*DM*DM, bo + (size_t)i*DM,
            px, px, DM, DM);
        ln_kernel<<<NTOK, 128>>>(px, ln2g + i*DM, ln2b + i*DM, ph);
        mma_gemm<1><<<dim3(FFD/128, NTOK/128), blk, MM_SMEM>>>(
            ph, pwts + R_W1 + (size_t)i*FFD*DM, b1 + (size_t)i*FFD,
            nullptr, pff, FFD, DM);
        mma_gemm<2><<<dim3(DM/128, NTOK/128), blk, MM_SMEM>>>(
            pff, pwts + R_W2 + (size_t)i*DM*FFD, b2 + (size_t)i*DM,
            px, px, DM, FFD);
    }
    // xf = x @ out_w^T + out_b : round x first (it feeds the MMA directly)
    round_tf32_kernel<<<rblocks(NTOK*DM), blk>>>(px, ph, NTOK*DM);
    mma_gemm<0><<<dim3(CHD/128, NTOK/128), blk, MM_SMEM>>>(ph, pwts + R_OUTW, out_b,
                                                           nullptr, pxf, CHD, DM);

    // compute_V  (exact fp32 path)
    sqnorm_kernel<<<1024, 256>>>(pxf, p, pnx, pnp);
    gemm_cdist<<<dim3(1024/BN, NB/BM), blk>>>(pxf, p, pA, NB, 1024, XFD,
                                              pxf, pnx, pnp, pnx);
    rowstats_kernel<<<NB, 256>>>(pA, prmax, prsum);
    colstats_kernel<<<4, 256>>>(pA, pcmax, pcsum);
    wbuild_kernel<<<NB, 256>>>(pA, prmax, prsum, pcmax, pcsum, pW);
    vgemm_sq<<<dim3(XFD/BN, NB/BM), blk>>>(pW, p, pxf, ppart);
    finalize_kernel<<<1, 256>>>(ppart, out);
}

// round 13
// speedup vs baseline: 3.6053x; 1.4029x over previous
#include <cuda_runtime.h>
#include <cuda_bf16.h>
#include <cstdint>

#define NTOK 16384
#define DM   512
#define FFD  2048
#define QKVD 1536
#define CHD  128
#define XFD  4096
#define NB   512

// ---------------- scratch (device globals; no cudaMalloc allowed) ----------
__device__ float g_x   [NTOK*DM];      // fp32 residual stream
__device__ float g_xf  [NTOK*CHD];     // == (512, 4096) row-major
__device__ float g_A   [NB*1024];
__device__ float g_W   [NB*1024];
__device__ float g_nx  [NB];
__device__ float g_np  [NB];
__device__ float g_rmax[NB];
__device__ float g_rsum[NB];
__device__ float g_cmax[1024];
__device__ float g_csum[1024];
__device__ float g_part[256];
// bf16 activation buffers
__device__ __nv_bfloat16 b_eps [NTOK*CHD];
__device__ __nv_bfloat16 b_h   [NTOK*DM];
__device__ __nv_bfloat16 b_attn[NTOK*DM];
__device__ __nv_bfloat16 b_qkv [NTOK*QKVD];
__device__ __nv_bfloat16 b_ff  [NTOK*FFD];
__device__ __nv_bfloat16 b_x   [NTOK*DM];
// bf16 weights: in_w | Wqkv | Wo | W1 | W2 | out_w
#define R_INW  0
#define R_QKV  65536
#define R_WO   (R_QKV + 4*QKVD*DM)
#define R_W1   (R_WO  + 4*DM*DM)
#define R_W2   (R_W1  + 4*FFD*DM)
#define R_OUTW (R_W2  + 4*DM*FFD)
#define R_TOT  (R_OUTW + CHD*DM)
__device__ __nv_bfloat16 b_wts[R_TOT];

// ---------------- fp32 -> bf16 conversion ----------------------------------
__global__ void __launch_bounds__(256)
cvt_bf16_kernel(const float* __restrict__ src, __nv_bfloat16* __restrict__ dst, int n)
{
    int i = (blockIdx.x * 256 + threadIdx.x) * 4;
    if (i < n) {
        float4 v = *reinterpret_cast<const float4*>(src + i);
        __nv_bfloat162 p0 = __floats2bfloat162_rn(v.x, v.y);
        __nv_bfloat162 p1 = __floats2bfloat162_rn(v.z, v.w);
        uint2 pk;
        pk.x = *reinterpret_cast<uint32_t*>(&p0);
        pk.y = *reinterpret_cast<uint32_t*>(&p1);
        *reinterpret_cast<uint2*>(dst + i) = pk;
    }
}

__device__ __forceinline__ uint32_t smem_u32(const void* p) {
    uint32_t a;
    asm("{ .reg .u64 t; cvta.to.shared.u64 t, %1; cvt.u32.u64 %0, t; }" : "=r"(a) : "l"(p));
    return a;
}

#define MMA_BF16(c, a, b)                                                     \
    asm volatile("mma.sync.aligned.m16n8k16.row.col.f32.bf16.bf16.f32 "       \
        "{%0,%1,%2,%3}, {%4,%5,%6,%7}, {%8,%9}, {%0,%1,%2,%3};"               \
        : "+f"((c)[0]), "+f"((c)[1]), "+f"((c)[2]), "+f"((c)[3])              \
        : "r"((a)[0]), "r"((a)[1]), "r"((a)[2]), "r"((a)[3]),                 \
          "r"((b)[0]), "r"((b)[1]))

// ---------------- bf16 mma.sync GEMM: C = A(NxK) @ Bw(MxK)^T ---------------
// block tile 128 (tokens) x 128 (features) x 32, 8 warps, warp tile 64x32
// EPI 0: +bias->f32 | 1: relu(+bias)->bf16 | 2: +bias+resid->f32 | 3: +bias->bf16
#define TRB 40               // bf16 per smem row (32 data + 8 pad), 80 bytes
#define TILEB (128*TRB)

template<int EPI>
__global__ void __launch_bounds__(256)
mma_gemm(const __nv_bfloat16* __restrict__ A, const __nv_bfloat16* __restrict__ Bw,
         const float* __restrict__ bias, const float* resid,
         float* __restrict__ Cf, __nv_bfloat16* __restrict__ Cb, int M, int K)
{
    __shared__ __nv_bfloat16 sm[4*TILEB];   // [2 stages][A,B] = 40960 bytes
    __nv_bfloat16* As = sm;
    __nv_bfloat16* Bs = sm + 2*TILEB;

    const int tid  = threadIdx.x;
    const int w    = tid >> 5;
    const int lane = tid & 31;
    const int g    = lane >> 2;
    const int tig  = lane & 3;
    const int wm   = (w & 1) * 64;
    const int wn   = (w >> 1) * 32;
    const int n0   = blockIdx.y * 128;
    const int m0   = blockIdx.x * 128;

    // cp.async geometry: each k-tile row = 32 bf16 = 64B = 4 x 16B chunks
    const int rb = tid >> 2;          // 0..63
    const int cc = (tid & 3) * 8;     // bf16 col of chunk

    float acc[4][4][4];
    #pragma unroll
    for (int mt = 0; mt < 4; mt++)
        #pragma unroll
        for (int nt = 0; nt < 4; nt++)
            #pragma unroll
            for (int r = 0; r < 4; r++) acc[mt][nt][r] = 0.f;

    auto preload = [&](int kt, int buf) {
        __nv_bfloat16* sa = As + buf * TILEB;
        __nv_bfloat16* sb = Bs + buf * TILEB;
        const __nv_bfloat16* gA = A  + (size_t)(n0 + rb) * K + kt * 32 + cc;
        const __nv_bfloat16* gB = Bw + (size_t)(m0 + rb) * K + kt * 32 + cc;
        #pragma unroll
        for (int i = 0; i < 2; i++) {
            uint32_t da = smem_u32(sa + (rb + i*64) * TRB + cc);
            uint32_t db = smem_u32(sb + (rb + i*64) * TRB + cc);
            asm volatile("cp.async.cg.shared.global [%0], [%1], 16;"
                         :: "r"(da), "l"(gA + (size_t)i * 64 * K));
            asm volatile("cp.async.cg.shared.global [%0], [%1], 16;"
                         :: "r"(db), "l"(gB + (size_t)i * 64 * K));
        }
        asm volatile("cp.async.commit_group;" ::: "memory");
    };

    const int KT = K >> 5;
    preload(0, 0);
    for (int kt = 0; kt < KT; kt++) {
        const int buf = kt & 1;
        if (kt + 1 < KT) {
            preload(kt + 1, buf ^ 1);
            asm volatile("cp.async.wait_group 1;" ::: "memory");
        } else {
            asm volatile("cp.async.wait_group 0;" ::: "memory");
        }
        __syncthreads();

        const __nv_bfloat16* a_s = As + buf * TILEB + wm * TRB;
        const __nv_bfloat16* b_s = Bs + buf * TILEB + wn * TRB;
        #pragma unroll
        for (int ks = 0; ks < 2; ks++) {
            const int kc = ks * 16;
            uint32_t af[4][4], bf[4][2];
            #pragma unroll
            for (int mt = 0; mt < 4; mt++) {
                const __nv_bfloat16* ap = a_s + (mt*16 + g) * TRB + kc + tig*2;
                af[mt][0] = *reinterpret_cast<const uint32_t*>(ap);
                af[mt][1] = *reinterpret_cast<const uint32_t*>(ap + 8*TRB);
                af[mt][2] = *reinterpret_cast<const uint32_t*>(ap + 8);
                af[mt][3] = *reinterpret_cast<const uint32_t*>(ap + 8*TRB + 8);
            }
            #pragma unroll
            for (int nt = 0; nt < 4; nt++) {
                const __nv_bfloat16* bp = b_s + (nt*8 + g) * TRB + kc + tig*2;
                bf[nt][0] = *reinterpret_cast<const uint32_t*>(bp);
                bf[nt][1] = *reinterpret_cast<const uint32_t*>(bp + 8);
            }
            #pragma unroll
            for (int mt = 0; mt < 4; mt++)
                #pragma unroll
                for (int nt = 0; nt < 4; nt++)
                    MMA_BF16(acc[mt][nt], af[mt], bf[nt]);
        }
        __syncthreads();
    }

    // epilogue
    #pragma unroll
    for (int mt = 0; mt < 4; mt++) {
        const int r0 = n0 + wm + mt * 16 + g;
        #pragma unroll
        for (int nt = 0; nt < 4; nt++) {
            const int c = m0 + wn + nt * 8 + 2 * tig;
            const float2 bv = *reinterpret_cast<const float2*>(bias + c);
            float v00 = acc[mt][nt][0] + bv.x;
            float v01 = acc[mt][nt][1] + bv.y;
            float v10 = acc[mt][nt][2] + bv.x;
            float v11 = acc[mt][nt][3] + bv.y;
            if (EPI == 1) {
                v00 = fmaxf(v00, 0.f); v01 = fmaxf(v01, 0.f);
                v10 = fmaxf(v10, 0.f); v11 = fmaxf(v11, 0.f);
            }
            if (EPI == 2) {
                float2 q0 = *reinterpret_cast<const float2*>(resid + (size_t)r0 * M + c);
                float2 q1 = *reinterpret_cast<const float2*>(resid + (size_t)(r0 + 8) * M + c);
                v00 += q0.x; v01 += q0.y; v10 += q1.x; v11 += q1.y;
            }
            if (EPI == 1 || EPI == 3) {
                __nv_bfloat162 z0 = __floats2bfloat162_rn(v00, v01);
                __nv_bfloat162 z1 = __floats2bfloat162_rn(v10, v11);
                *reinterpret_cast<__nv_bfloat162*>(Cb + (size_t)r0 * M + c)       = z0;
                *reinterpret_cast<__nv_bfloat162*>(Cb + (size_t)(r0 + 8) * M + c) = z1;
            } else {
                *reinterpret_cast<float2*>(Cf + (size_t)r0 * M + c)       = make_float2(v00, v01);
                *reinterpret_cast<float2*>(Cf + (size_t)(r0 + 8) * M + c) = make_float2(v10, v11);
            }
        }
    }
}

// ---------------- block reductions ----------------------------------------
__device__ __forceinline__ float block_reduce_sum(float v, float* sh) {
    int lane = threadIdx.x & 31, w = threadIdx.x >> 5;
    #pragma unroll
    for (int off = 16; off; off >>= 1) v += __shfl_xor_sync(0xffffffffu, v, off);
    if (lane == 0) sh[w] = v;
    __syncthreads();
    int nw = blockDim.x >> 5;
    if (w == 0) {
        float r = (lane < nw) ? sh[lane] : 0.f;
        #pragma unroll
        for (int off = 4; off; off >>= 1) r += __shfl_xor_sync(0xffffffffu, r, off);
        if (lane == 0) sh[0] = r;
    }
    __syncthreads();
    float res = sh[0];
    __syncthreads();
    return res;
}

__device__ __forceinline__ float block_reduce_max(float v, float* sh) {
    int lane = threadIdx.x & 31, w = threadIdx.x >> 5;
    #pragma unroll
    for (int off = 16; off; off >>= 1) v = fmaxf(v, __shfl_xor_sync(0xffffffffu, v, off));
    if (lane == 0) sh[w] = v;
    __syncthreads();
    int nw = blockDim.x >> 5;
    if (w == 0) {
        float r = (lane < nw) ? sh[lane] : -1e30f;
        #pragma unroll
        for (int off = 4; off; off >>= 1) r = fmaxf(r, __shfl_xor_sync(0xffffffffu, r, off));
        if (lane == 0) sh[0] = r;
    }
    __syncthreads();
    float res = sh[0];
    __syncthreads();
    return res;
}

// ---------------- fp32 SIMT GEMM for the cdist epilogue ---------------------
#define BM 128
#define BN 64
#define BK 16
#define PAD_A (BM+4)
#define PAD_B (BN+4)

__global__ void __launch_bounds__(256)
gemm_cdist(const float* __restrict__ A, const float* __restrict__ Bw,
           float* C, int N, int M, int K,
           const float* __restrict__ B2,
           const float* __restrict__ nx, const float* __restrict__ ny,
           const float* __restrict__ ny2)
{
    __shared__ float As[BK][PAD_A];
    __shared__ float Bs[BK][PAD_B];
    const int tid = threadIdx.x;
    const int tx = tid & 15, ty = tid >> 4;
    const int n0 = blockIdx.y * BM;
    const int m0 = blockIdx.x * BN;

    const int ar0 = tid >> 2;
    const int ac4 = (tid & 3) << 2;
    const float* aptr0 = A + (size_t)(n0 + ar0)      * K + ac4;
    const float* aptr1 = A + (size_t)(n0 + ar0 + 64) * K + ac4;

    const int brow = tid >> 2;
    const int bc4  = (tid & 3) << 2;
    const int m_ld = m0 + brow;
    const float* bptr = (m_ld >= 512) ? B2 + (size_t)(m_ld - 512) * K + bc4
                                      : Bw + (size_t)m_ld * K + bc4;

    float acc[8][4];
    #pragma unroll
    for (int i = 0; i < 8; i++)
        #pragma unroll
        for (int j = 0; j < 4; j++) acc[i][j] = 0.f;

    for (int k0 = 0; k0 < K; k0 += BK) {
        float4 a0 = *reinterpret_cast<const float4*>(aptr0 + k0);
        float4 a1 = *reinterpret_cast<const float4*>(aptr1 + k0);
        float4 b0 = *reinterpret_cast<const float4*>(bptr + k0);
        As[ac4+0][ar0]    = a0.x; As[ac4+1][ar0]    = a0.y; As[ac4+2][ar0]    = a0.z; As[ac4+3][ar0]    = a0.w;
        As[ac4+0][ar0+64] = a1.x; As[ac4+1][ar0+64] = a1.y; As[ac4+2][ar0+64] = a1.z; As[ac4+3][ar0+64] = a1.w;
        Bs[bc4+0][brow] = b0.x; Bs[bc4+1][brow] = b0.y; Bs[bc4+2][brow] = b0.z; Bs[bc4+3][brow] = b0.w;
        __syncthreads();
        #pragma unroll
        for (int k = 0; k < BK; k++) {
            float4 af0 = *reinterpret_cast<const float4*>(&As[k][ty*8]);
            float4 af1 = *reinterpret_cast<const float4*>(&As[k][ty*8+4]);
            float4 bf  = *reinterpret_cast<const float4*>(&Bs[k][tx*4]);
            float a_[8] = {af0.x, af0.y, af0.z, af0.w, af1.x, af1.y, af1.z, af1.w};
            float b_[4] = {bf.x, bf.y, bf.z, bf.w};
            #pragma unroll
            for (int i = 0; i < 8; i++)
                #pragma unroll
                for (int j = 0; j < 4; j++) acc[i][j] += a_[i] * b_[j];
        }
        __syncthreads();
    }

    const int nr0 = n0 + ty * 8;
    const int mc0 = m0 + tx * 4;
    #pragma unroll
    for (int i = 0; i < 8; i++) {
        int nn = nr0 + i;
        float nxi = nx[nn];
        float rr[4];
        #pragma unroll
        for (int j = 0; j < 4; j++) {
            int m = mc0 + j;
            float nyv = (m < 512) ? ny[m] : ny2[m - 512];
            float d2 = nxi + nyv - 2.f * acc[i][j];
            float a = -sqrtf(fmaxf(d2, 0.f));
            if (m >= 512 && (m - 512) == nn) a -= 1e6f;
            rr[j] = a;
        }
        *reinterpret_cast<float4*>(C + (size_t)nn * M + mc0) =
            make_float4(rr[0], rr[1], rr[2], rr[3]);
    }
}

// ---------------- NN GEMM with fused squared-sum: V = W @ Y, sum(V^2) ------
__global__ void __launch_bounds__(256)
vgemm_sq(const float* __restrict__ W, const float* __restrict__ P,
         const float* __restrict__ XF, float* __restrict__ part)
{
    const int K = 1024, M = XFD;
    __shared__ float As[BK][PAD_A];
    __shared__ float Bs[BK][PAD_B];
    __shared__ float shred[32];
    const int tid = threadIdx.x;
    const int tx = tid & 15, ty = tid >> 4;
    const int n0 = blockIdx.y * BM;
    const int m0 = blockIdx.x * BN;

    const int ar0 = tid >> 2;
    const int ac4 = (tid & 3) << 2;
    const float* aptr0 = W + (size_t)(n0 + ar0)      * K + ac4;
    const float* aptr1 = W + (size_t)(n0 + ar0 + 64) * K + ac4;
    const int brow = tid >> 4;
    const int bc4  = (tid & 15) << 2;

    float acc[8][4];
    #pragma unroll
    for (int i = 0; i < 8; i++)
        #pragma unroll
        for (int j = 0; j < 4; j++) acc[i][j] = 0.f;

    for (int k0 = 0; k0 < K; k0 += BK) {
        float4 a0 = *reinterpret_cast<const float4*>(aptr0 + k0);
        float4 a1 = *reinterpret_cast<const float4*>(aptr1 + k0);
        int krow = k0 + brow;
        const float* ysrc = (krow < 512) ? P + (size_t)krow * M
                                         : XF + (size_t)(krow - 512) * M;
        float4 b0 = *reinterpret_cast<const float4*>(ysrc + m0 + bc4);
        As[ac4+0][ar0]    = a0.x; As[ac4+1][ar0]    = a0.y; As[ac4+2][ar0]    = a0.z; As[ac4+3][ar0]    = a0.w;
        As[ac4+0][ar0+64] = a1.x; As[ac4+1][ar0+64] = a1.y; As[ac4+2][ar0+64] = a1.z; As[ac4+3][ar0+64] = a1.w;
        *reinterpret_cast<float4*>(&Bs[brow][bc4]) = b0;
        __syncthreads();
        #pragma unroll
        for (int k = 0; k < BK; k++) {
            float4 af0 = *reinterpret_cast<const float4*>(&As[k][ty*8]);
            float4 af1 = *reinterpret_cast<const float4*>(&As[k][ty*8+4]);
            float4 bf  = *reinterpret_cast<const float4*>(&Bs[k][tx*4]);
            float a_[8] = {af0.x, af0.y, af0.z, af0.w, af1.x, af1.y, af1.z, af1.w};
            float b_[4] = {bf.x, bf.y, bf.z, bf.w};
            #pragma unroll
            for (int i = 0; i < 8; i++)
                #pragma unroll
                for (int j = 0; j < 4; j++) acc[i][j] += a_[i] * b_[j];
        }
        __syncthreads();
    }

    float ss = 0.f;
    #pragma unroll
    for (int i = 0; i < 8; i++)
        #pragma unroll
        for (int j = 0; j < 4; j++) ss += acc[i][j] * acc[i][j];
    float tot = block_reduce_sum(ss, shred);
    if (tid == 0) part[blockIdx.y * gridDim.x + blockIdx.x] = tot;
}

// ---------------- LayerNorm (bf16 output feeds MMA) ------------------------
__global__ void __launch_bounds__(128)
ln_kernel(const float* __restrict__ x, const float* __restrict__ g,
          const float* __restrict__ b, __nv_bfloat16* __restrict__ out)
{
    int t = blockIdx.x;
    int tid = threadIdx.x;
    const float* xr = x + (size_t)t * DM;
    float4 v = *reinterpret_cast<const float4*>(xr + tid * 4);
    float s  = v.x + v.y + v.z + v.w;
    float sq = v.x*v.x + v.y*v.y + v.z*v.z + v.w*v.w;
    int lane = tid & 31, w = tid >> 5;
    #pragma unroll
    for (int off = 16; off; off >>= 1) {
        s  += __shfl_xor_sync(0xffffffffu, s,  off);
        sq += __shfl_xor_sync(0xffffffffu, sq, off);
    }
    __shared__ float shs[4], shq[4];
    if (lane == 0) { shs[w] = s; shq[w] = sq; }
    __syncthreads();
    s  = shs[0] + shs[1] + shs[2] + shs[3];
    sq = shq[0] + shq[1] + shq[2] + shq[3];
    float mean = s * (1.f / 512.f);
    float var  = sq * (1.f / 512.f) - mean * mean;
    float inv  = rsqrtf(var + 1e-5f);
    float4 gv = *reinterpret_cast<const float4*>(g + tid * 4);
    float4 bv = *reinterpret_cast<const float4*>(b + tid * 4);
    __nv_bfloat162 p0 = __floats2bfloat162_rn((v.x - mean) * inv * gv.x + bv.x,
                                              (v.y - mean) * inv * gv.y + bv.y);
    __nv_bfloat162 p1 = __floats2bfloat162_rn((v.z - mean) * inv * gv.z + bv.z,
                                              (v.w - mean) * inv * gv.w + bv.w);
    uint2 pk;
    pk.x = *reinterpret_cast<uint32_t*>(&p0);
    pk.y = *reinterpret_cast<uint32_t*>(&p1);
    *reinterpret_cast<uint2*>(out + (size_t)t * DM + tid * 4) = pk;
}

// ---------------- attention: one (batch, head) per block --------------------
__global__ void __launch_bounds__(256)
attn_kernel(const __nv_bfloat16* __restrict__ qkv, __nv_bfloat16* __restrict__ o)
{
    __shared__ float qs[32][68];
    __shared__ float kt[64][36];   // transposed: kt[d][j]
    __shared__ float vs[32][64];
    __shared__ float ps[32][33];
    int bh = blockIdx.x;
    int b = bh >> 3, h = bh & 7;
    int tid = threadIdx.x;
    size_t base = (size_t)(b * 32) * QKVD + h * 64;
    #pragma unroll
    for (int l = 0; l < 2; l++) {
        int idx = tid + l * 256;
        int i = idx >> 4;
        int c = (idx & 15) << 2;
        uint2 qv = *reinterpret_cast<const uint2*>(qkv + base + (size_t)i * QKVD + c);
        uint2 kv = *reinterpret_cast<const uint2*>(qkv + base + (size_t)i * QKVD + 512 + c);
        uint2 vv = *reinterpret_cast<const uint2*>(qkv + base + (size_t)i * QKVD + 1024 + c);
        float2 q01 = __bfloat1622float2(*reinterpret_cast<__nv_bfloat162*>(&qv.x));
        float2 q23 = __bfloat1622float2(*reinterpret_cast<__nv_bfloat162*>(&qv.y));
        float2 k01 = __bfloat1622float2(*reinterpret_cast<__nv_bfloat162*>(&kv.x));
        float2 k23 = __bfloat1622float2(*reinterpret_cast<__nv_bfloat162*>(&kv.y));
        float2 v01 = __bfloat1622float2(*reinterpret_cast<__nv_bfloat162*>(&vv.x));
        float2 v23 = __bfloat1622float2(*reinterpret_cast<__nv_bfloat162*>(&vv.y));
        qs[i][c] = q01.x; qs[i][c+1] = q01.y; qs[i][c+2] = q23.x; qs[i][c+3] = q23.y;
        kt[c][i] = k01.x; kt[c+1][i] = k01.y; kt[c+2][i] = k23.x; kt[c+3][i] = k23.y;
        vs[i][c] = v01.x; vs[i][c+1] = v01.y; vs[i][c+2] = v23.x; vs[i][c+3] = v23.y;
    }
    __syncthreads();
    {   // scores: thread (i, j0..j0+3)
        int i = tid >> 3;
        int j0 = (tid & 7) << 2;
        float s0 = 0.f, s1 = 0.f, s2 = 0.f, s3 = 0.f;
        #pragma unroll
        for (int d = 0; d < 64; d += 4) {
            float4 q  = *reinterpret_cast<const float4*>(&qs[i][d]);
            float4 k0 = *reinterpret_cast<const float4*>(&kt[d  ][j0]);
            float4 k1 = *reinterpret_cast<const float4*>(&kt[d+1][j0]);
            float4 k2 = *reinterpret_cast<const float4*>(&kt[d+2][j0]);
            float4 k3 = *reinterpret_cast<const float4*>(&kt[d+3][j0]);
            s0 += q.x*k0.x + q.y*k1.x + q.z*k2.x + q.w*k3.x;
            s1 += q.x*k0.y + q.y*k1.y + q.z*k2.y + q.w*k3.y;
            s2 += q.x*k0.z + q.y*k1.z + q.z*k2.z + q.w*k3.z;
            s3 += q.x*k0.w + q.y*k1.w + q.z*k2.w + q.w*k3.w;
        }
        ps[i][j0]   = s0 * 0.125f;
        ps[i][j0+1] = s1 * 0.125f;
        ps[i][j0+2] = s2 * 0.125f;
        ps[i][j0+3] = s3 * 0.125f;
    }
    __syncthreads();
    {   // softmax per row
        int w = tid >> 5, lane = tid & 31;
        #pragma unroll
        for (int r = 0; r < 4; r++) {
            int i = w + (r << 3);
            float v = ps[i][lane];
            float mx = v;
            #pragma unroll
            for (int off = 16; off; off >>= 1) mx = fmaxf(mx, __shfl_xor_sync(0xffffffffu, mx, off));
            float e = __expf(v - mx);
            float sm = e;
            #pragma unroll
            for (int off = 16; off; off >>= 1) sm += __shfl_xor_sync(0xffffffffu, sm, off);
            ps[i][lane] = e / sm;
        }
    }
    __syncthreads();
    {   // o = p @ v
        int i = tid >> 3;
        int d0 = (tid & 7) << 3;
        float4 a0 = make_float4(0.f,0.f,0.f,0.f);
        float4 a1 = make_float4(0.f,0.f,0.f,0.f);
        #pragma unroll
        for (int j = 0; j < 32; j++) {
            float pv = ps[i][j];
            float4 v0 = *reinterpret_cast<const float4*>(&vs[j][d0]);
            float4 v1 = *reinterpret_cast<const float4*>(&vs[j][d0+4]);
            a0.x += pv*v0.x; a0.y += pv*v0.y; a0.z += pv*v0.z; a0.w += pv*v0.w;
            a1.x += pv*v1.x; a1.y += pv*v1.y; a1.z += pv*v1.z; a1.w += pv*v1.w;
        }
        __nv_bfloat162 c0 = __floats2bfloat162_rn(a0.x, a0.y);
        __nv_bfloat162 c1 = __floats2bfloat162_rn(a0.z, a0.w);
        __nv_bfloat162 c2 = __floats2bfloat162_rn(a1.x, a1.y);
        __nv_bfloat162 c3 = __floats2bfloat162_rn(a1.z, a1.w);
        uint4 pk;
        pk.x = *reinterpret_cast<uint32_t*>(&c0);
        pk.y = *reinterpret_cast<uint32_t*>(&c1);
        pk.z = *reinterpret_cast<uint32_t*>(&c2);
        pk.w = *reinterpret_cast<uint32_t*>(&c3);
        *reinterpret_cast<uint4*>(o + (size_t)(b * 32 + i) * DM + h * 64 + d0) = pk;
    }
}

// ---------------- squared norms of xf rows and p rows -----------------------
__global__ void __launch_bounds__(256)
sqnorm_kernel(const float* __restrict__ xf, const float* __restrict__ p,
              float* __restrict__ nx, float* __restrict__ np)
{
    int r = blockIdx.x;
    const float* src = (r < 512) ? xf + (size_t)r * XFD : p + (size_t)(r - 512) * XFD;
    float s = 0.f;
    for (int c = threadIdx.x * 4; c < XFD; c += 256 * 4) {
        float4 v = *reinterpret_cast<const float4*>(src + c);
        s += v.x*v.x + v.y*v.y + v.z*v.z + v.w*v.w;
    }
    __shared__ float sh[32];
    float tot = block_reduce_sum(s, sh);
    if (threadIdx.x == 0) { if (r < 512) nx[r] = tot; else np[r - 512] = tot; }
}

// ---------------- row stats of A (max, sum of exp) ---------------------------
__global__ void __launch_bounds__(256)
rowstats_kernel(const float* __restrict__ A, float* __restrict__ rmax,
                float* __restrict__ rsum)
{
    int r = blockIdx.x;
    const float* ar = A + (size_t)r * 1024;
    float v[4];
    float mx = -1e30f;
    #pragma unroll
    for (int l = 0; l < 4; l++) { v[l] = ar[threadIdx.x + l * 256]; mx = fmaxf(mx, v[l]); }
    __shared__ float sh[32];
    mx = block_reduce_max(mx, sh);
    float s = 0.f;
    #pragma unroll
    for (int l = 0; l < 4; l++) s += __expf(v[l] - mx);
    s = block_reduce_sum(s, sh);
    if (threadIdx.x == 0) { rmax[r] = mx; rsum[r] = s; }
}

// ---------------- column stats of A ----------------------------------------
__global__ void __launch_bounds__(256)
colstats_kernel(const float* __restrict__ A, float* __restrict__ cmax,
                float* __restrict__ csum)
{
    int c = blockIdx.x * 256 + threadIdx.x;
    float mx = -1e30f;
    for (int i = 0; i < 512; i++) mx = fmaxf(mx, A[(size_t)i * 1024 + c]);
    float s = 0.f;
    for (int i = 0; i < 512; i++) s += __expf(A[(size_t)i * 1024 + c] - mx);
    cmax[c] = mx; csum[c] = s;
}

// ---------------- build W = [A_pos*sneg | -(A_neg*spos)] --------------------
__global__ void __launch_bounds__(256)
wbuild_kernel(const float* __restrict__ A, const float* __restrict__ rmax,
              const float* __restrict__ rsum, const float* __restrict__ cmax,
              const float* __restrict__ csum, float* __restrict__ W)
{
    int r = blockIdx.x;
    int j0 = threadIdx.x * 4;
    float rm = rmax[r];
    float rs = rsum[r];
    float4 a = *reinterpret_cast<const float4*>(A + (size_t)r * 1024 + j0);
    float av[4] = {a.x, a.y, a.z, a.w};
    float soft[4];
    float lsum = 0.f;
    #pragma unroll
    for (int l = 0; l < 4; l++) {
        int j = j0 + l;
        float s = __expf(av[l] - 0.5f * (rm + cmax[j])) * rsqrtf(rs * csum[j]);
        soft[l] = s;
        lsum += s;
    }
    bool isneg = (threadIdx.x >= 128);
    __shared__ float sh[32];
    float sp = block_reduce_sum(isneg ? 0.f : lsum, sh);
    float sn = block_reduce_sum(isneg ? lsum : 0.f, sh);
    float scale = isneg ? -(sp * sn) : sn;
    float4 o = make_float4(soft[0]*scale, soft[1]*scale, soft[2]*scale, soft[3]*scale);
    *reinterpret_cast<float4*>(W + (size_t)r * 1024 + j0) = o;
}

// ---------------- final reduce → mean(V^2) ----------------------------------
__global__ void __launch_bounds__(256)
finalize_kernel(const float* __restrict__ part, float* __restrict__ out)
{
    __shared__ float sh[32];
    float v = part[threadIdx.x];
    float tot = block_reduce_sum(v, sh);
    if (threadIdx.x == 0) out[0] = tot * (1.f / (512.f * 4096.f));
}

// ---------------- host launch ------------------------------------------------
extern "C" void kernel_launch(void* const* d_in, const int* in_sizes, int n_in,
                              void* d_out, int out_size)
{
    (void)in_sizes; (void)n_in; (void)out_size;
    const float* p     = (const float*)d_in[0];
    const float* eps   = (const float*)d_in[1];
    const float* in_w  = (const float*)d_in[2];
    const float* in_b  = (const float*)d_in[3];
    const float* Wqkv  = (const float*)d_in[4];
    const float* bqkv  = (const float*)d_in[5];
    const float* Wo    = (const float*)d_in[6];
    const float* bo    = (const float*)d_in[7];
    const float* ln1g  = (const float*)d_in[8];
    const float* ln1b  = (const float*)d_in[9];
    const float* W1    = (const float*)d_in[10];
    const float* b1    = (const float*)d_in[11];
    const float* W2    = (const float*)d_in[12];
    const float* b2    = (const float*)d_in[13];
    const float* ln2g  = (const float*)d_in[14];
    const float* ln2b  = (const float*)d_in[15];
    const float* out_w = (const float*)d_in[16];
    const float* out_b = (const float*)d_in[17];
    float* out = (float*)d_out;

    float *px, *pxf, *pA, *pW;
    float *pnx, *pnp, *prmax, *prsum, *pcmax, *pcsum, *ppart;
    __nv_bfloat16 *peps, *phb, *pattn, *pqkvb, *pffb, *pxb, *pwb;
    cudaGetSymbolAddress((void**)&px,    g_x);
    cudaGetSymbolAddress((void**)&pxf,   g_xf);
    cudaGetSymbolAddress((void**)&pA,    g_A);
    cudaGetSymbolAddress((void**)&pW,    g_W);
    cudaGetSymbolAddress((void**)&pnx,   g_nx);
    cudaGetSymbolAddress((void**)&pnp,   g_np);
    cudaGetSymbolAddress((void**)&prmax, g_rmax);
    cudaGetSymbolAddress((void**)&prsum, g_rsum);
    cudaGetSymbolAddress((void**)&pcmax, g_cmax);
    cudaGetSymbolAddress((void**)&pcsum, g_csum);
    cudaGetSymbolAddress((void**)&ppart, g_part);
    cudaGetSymbolAddress((void**)&peps,  b_eps);
    cudaGetSymbolAddress((void**)&phb,   b_h);
    cudaGetSymbolAddress((void**)&pattn, b_attn);
    cudaGetSymbolAddress((void**)&pqkvb, b_qkv);
    cudaGetSymbolAddress((void**)&pffb,  b_ff);
    cudaGetSymbolAddress((void**)&pxb,   b_x);
    cudaGetSymbolAddress((void**)&pwb,   b_wts);

    dim3 blk(256);
    auto rblocks = [](int n) { return (n / 4 + 255) / 256; };

    // convert weights + eps to bf16 (round-nearest)
    cvt_bf16_kernel<<<rblocks(DM*CHD),    blk>>>(in_w,  pwb + R_INW,  DM*CHD);
    cvt_bf16_kernel<<<rblocks(4*QKVD*DM), blk>>>(Wqkv,  pwb + R_QKV,  4*QKVD*DM);
    cvt_bf16_kernel<<<rblocks(4*DM*DM),   blk>>>(Wo,    pwb + R_WO,   4*DM*DM);
    cvt_bf16_kernel<<<rblocks(4*FFD*DM),  blk>>>(W1,    pwb + R_W1,   4*FFD*DM);
    cvt_bf16_kernel<<<rblocks(4*DM*FFD),  blk>>>(W2,    pwb + R_W2,   4*DM*FFD);
    cvt_bf16_kernel<<<rblocks(CHD*DM),    blk>>>(out_w, pwb + R_OUTW, CHD*DM);
    cvt_bf16_kernel<<<rblocks(NTOK*CHD),  blk>>>(eps,   peps,         NTOK*CHD);

    // x = eps @ in_w^T + in_b   (fp32 out)
    mma_gemm<0><<<dim3(DM/128, NTOK/128), blk>>>(peps, pwb + R_INW, in_b,
                                                 nullptr, px, nullptr, DM, CHD);
    for (int i = 0; i < 4; i++) {
        ln_kernel<<<NTOK, 128>>>(px, ln1g + i*DM, ln1b + i*DM, phb);
        mma_gemm<3><<<dim3(QKVD/128, NTOK/128), blk>>>(
            phb, pwb + R_QKV + (size_t)i*QKVD*DM, bqkv + (size_t)i*QKVD,
            nullptr, nullptr, pqkvb, QKVD, DM);
        attn_kernel<<<4096, 256>>>(pqkvb, pattn);
        mma_gemm<2><<<dim3(DM/128, NTOK/128), blk>>>(
            pattn, pwb + R_WO + (size_t)i*DM*DM, bo + (size_t)i*DM,
            px, px, nullptr, DM, DM);
        ln_kernel<<<NTOK, 128>>>(px, ln2g + i*DM, ln2b + i*DM, phb);
        mma_gemm<1><<<dim3(FFD/128, NTOK/128), blk>>>(
            phb, pwb + R_W1 + (size_t)i*FFD*DM, b1 + (size_t)i*FFD,
            nullptr, nullptr, pffb, FFD, DM);
        mma_gemm<2><<<dim3(DM/128, NTOK/128), blk>>>(
            pffb, pwb + R_W2 + (size_t)i*DM*FFD, b2 + (size_t)i*DM,
            px, px, nullptr, DM, FFD);
    }
    // xf = x @ out_w^T + out_b
    cvt_bf16_kernel<<<rblocks(NTOK*DM), blk>>>(px, pxb, NTOK*DM);
    mma_gemm<0><<<dim3(CHD/128, NTOK/128), blk>>>(pxb, pwb + R_OUTW, out_b,
                                                  nullptr, pxf, nullptr, CHD, DM);

    // compute_V (exact fp32 path)
    sqnorm_kernel<<<1024, 256>>>(pxf, p, pnx, pnp);
    gemm_cdist<<<dim3(1024/BN, NB/BM), blk>>>(pxf, p, pA, NB, 1024, XFD,
                                              pxf, pnx, pnp, pnx);
    rowstats_kernel<<<NB, 256>>>(pA, prmax, prsum);
    colstats_kernel<<<4, 256>>>(pA, pcmax, pcsum);
    wbuild_kernel<<<NB, 256>>>(pA, prmax, prsum, pcmax, pcsum, pW);
    vgemm_sq<<<dim3(XFD/BN, NB/BM), blk>>>(pW, p, pxf, ppart);
    finalize_kernel<<<1, 256>>>(ppart, out);
}

// round 14
// speedup vs baseline: 3.6059x; 1.0002x over previous
#include <cuda_runtime.h>
#include <cuda_bf16.h>
#include <cstdint>

#define NTOK 16384
#define DM   512
#define FFD  2048
#define QKVD 1536
#define CHD  128
#define XFD  4096
#define NB   512

// ---------------- scratch (device globals; no cudaMalloc allowed) ----------
__device__ float g_x   [NTOK*DM];      // fp32 residual stream
__device__ float g_xf  [NTOK*CHD];     // == (512, 4096) row-major
__device__ float g_A   [NB*1024];
__device__ float g_W   [NB*1024];
__device__ float g_nx  [NB];
__device__ float g_np  [NB];
__device__ float g_rmax[NB];
__device__ float g_rsum[NB];
__device__ float g_cmax[1024];
__device__ float g_csum[1024];
__device__ float g_part[256];
// bf16 activation buffers
__device__ __nv_bfloat16 b_eps [NTOK*CHD];
__device__ __nv_bfloat16 b_h   [NTOK*DM];
__device__ __nv_bfloat16 b_attn[NTOK*DM];
__device__ __nv_bfloat16 b_qkv [NTOK*QKVD];
__device__ __nv_bfloat16 b_ff  [NTOK*FFD];
__device__ __nv_bfloat16 b_x   [NTOK*DM];
// bf16 weights: in_w | Wqkv | Wo | W1 | W2 | out_w
#define R_INW  0
#define R_QKV  65536
#define R_WO   (R_QKV + 4*QKVD*DM)
#define R_W1   (R_WO  + 4*DM*DM)
#define R_W2   (R_W1  + 4*FFD*DM)
#define R_OUTW (R_W2  + 4*DM*FFD)
#define R_TOT  (R_OUTW + CHD*DM)
__device__ __nv_bfloat16 b_wts[R_TOT];

// ---------------- fp32 -> bf16 conversion ----------------------------------
__global__ void __launch_bounds__(256)
cvt_bf16_kernel(const float* __restrict__ src, __nv_bfloat16* __restrict__ dst, int n)
{
    int i = (blockIdx.x * 256 + threadIdx.x) * 4;
    if (i < n) {
        float4 v = *reinterpret_cast<const float4*>(src + i);
        __nv_bfloat162 p0 = __floats2bfloat162_rn(v.x, v.y);
        __nv_bfloat162 p1 = __floats2bfloat162_rn(v.z, v.w);
        uint2 pk;
        pk.x = *reinterpret_cast<uint32_t*>(&p0);
        pk.y = *reinterpret_cast<uint32_t*>(&p1);
        *reinterpret_cast<uint2*>(dst + i) = pk;
    }
}

__device__ __forceinline__ uint32_t smem_u32(const void* p) {
    uint32_t a;
    asm("{ .reg .u64 t; cvta.to.shared.u64 t, %1; cvt.u32.u64 %0, t; }" : "=r"(a) : "l"(p));
    return a;
}

#define MMA_BF16(c, a, b)                                                     \
    asm volatile("mma.sync.aligned.m16n8k16.row.col.f32.bf16.bf16.f32 "       \
        "{%0,%1,%2,%3}, {%4,%5,%6,%7}, {%8,%9}, {%0,%1,%2,%3};"               \
        : "+f"((c)[0]), "+f"((c)[1]), "+f"((c)[2]), "+f"((c)[3])              \
        : "r"((a)[0]), "r"((a)[1]), "r"((a)[2]), "r"((a)[3]),                 \
          "r"((b)[0]), "r"((b)[1]))

// ---------------- bf16 mma.sync GEMM: C = A(NxK) @ Bw(MxK)^T ---------------
// block tile 128 (tokens) x 128 (features) x 32, 8 warps, warp tile 64x32
// EPI 0: +bias->f32 | 1: relu(+bias)->bf16 | 2: +bias+resid->f32 | 3: +bias->bf16
#define TRB 40               // bf16 per smem row (32 data + 8 pad), 80 bytes
#define TILEB (128*TRB)

template<int EPI>
__global__ void __launch_bounds__(256)
mma_gemm(const __nv_bfloat16* __restrict__ A, const __nv_bfloat16* __restrict__ Bw,
         const float* __restrict__ bias, const float* resid,
         float* __restrict__ Cf, __nv_bfloat16* __restrict__ Cb, int M, int K)
{
    __shared__ __nv_bfloat16 sm[4*TILEB];   // [2 stages][A,B] = 40960 bytes
    __nv_bfloat16* As = sm;
    __nv_bfloat16* Bs = sm + 2*TILEB;

    const int tid  = threadIdx.x;
    const int w    = tid >> 5;
    const int lane = tid & 31;
    const int g    = lane >> 2;
    const int tig  = lane & 3;
    const int wm   = (w & 1) * 64;
    const int wn   = (w >> 1) * 32;
    const int n0   = blockIdx.y * 128;
    const int m0   = blockIdx.x * 128;

    // cp.async geometry: each k-tile row = 32 bf16 = 64B = 4 x 16B chunks
    const int rb = tid >> 2;          // 0..63
    const int cc = (tid & 3) * 8;     // bf16 col of chunk

    float acc[4][4][4];
    #pragma unroll
    for (int mt = 0; mt < 4; mt++)
        #pragma unroll
        for (int nt = 0; nt < 4; nt++)
            #pragma unroll
            for (int r = 0; r < 4; r++) acc[mt][nt][r] = 0.f;

    auto preload = [&](int kt, int buf) {
        __nv_bfloat16* sa = As + buf * TILEB;
        __nv_bfloat16* sb = Bs + buf * TILEB;
        const __nv_bfloat16* gA = A  + (size_t)(n0 + rb) * K + kt * 32 + cc;
        const __nv_bfloat16* gB = Bw + (size_t)(m0 + rb) * K + kt * 32 + cc;
        #pragma unroll
        for (int i = 0; i < 2; i++) {
            uint32_t da = smem_u32(sa + (rb + i*64) * TRB + cc);
            uint32_t db = smem_u32(sb + (rb + i*64) * TRB + cc);
            asm volatile("cp.async.cg.shared.global [%0], [%1], 16;"
                         :: "r"(da), "l"(gA + (size_t)i * 64 * K));
            asm volatile("cp.async.cg.shared.global [%0], [%1], 16;"
                         :: "r"(db), "l"(gB + (size_t)i * 64 * K));
        }
        asm volatile("cp.async.commit_group;" ::: "memory");
    };

    const int KT = K >> 5;
    preload(0, 0);
    for (int kt = 0; kt < KT; kt++) {
        const int buf = kt & 1;
        if (kt + 1 < KT) {
            preload(kt + 1, buf ^ 1);
            asm volatile("cp.async.wait_group 1;" ::: "memory");
        } else {
            asm volatile("cp.async.wait_group 0;" ::: "memory");
        }
        __syncthreads();

        const __nv_bfloat16* a_s = As + buf * TILEB + wm * TRB;
        const __nv_bfloat16* b_s = Bs + buf * TILEB + wn * TRB;
        #pragma unroll
        for (int ks = 0; ks < 2; ks++) {
            const int kc = ks * 16;
            uint32_t af[4][4], bf[4][2];
            #pragma unroll
            for (int mt = 0; mt < 4; mt++) {
                const __nv_bfloat16* ap = a_s + (mt*16 + g) * TRB + kc + tig*2;
                af[mt][0] = *reinterpret_cast<const uint32_t*>(ap);
                af[mt][1] = *reinterpret_cast<const uint32_t*>(ap + 8*TRB);
                af[mt][2] = *reinterpret_cast<const uint32_t*>(ap + 8);
                af[mt][3] = *reinterpret_cast<const uint32_t*>(ap + 8*TRB + 8);
            }
            #pragma unroll
            for (int nt = 0; nt < 4; nt++) {
                const __nv_bfloat16* bp = b_s + (nt*8 + g) * TRB + kc + tig*2;
                bf[nt][0] = *reinterpret_cast<const uint32_t*>(bp);
                bf[nt][1] = *reinterpret_cast<const uint32_t*>(bp + 8);
            }
            #pragma unroll
            for (int mt = 0; mt < 4; mt++)
                #pragma unroll
                for (int nt = 0; nt < 4; nt++)
                    MMA_BF16(acc[mt][nt], af[mt], bf[nt]);
        }
        __syncthreads();
    }

    // epilogue
    #pragma unroll
    for (int mt = 0; mt < 4; mt++) {
        const int r0 = n0 + wm + mt * 16 + g;
        #pragma unroll
        for (int nt = 0; nt < 4; nt++) {
            const int c = m0 + wn + nt * 8 + 2 * tig;
            const float2 bv = *reinterpret_cast<const float2*>(bias + c);
            float v00 = acc[mt][nt][0] + bv.x;
            float v01 = acc[mt][nt][1] + bv.y;
            float v10 = acc[mt][nt][2] + bv.x;
            float v11 = acc[mt][nt][3] + bv.y;
            if (EPI == 1) {
                v00 = fmaxf(v00, 0.f); v01 = fmaxf(v01, 0.f);
                v10 = fmaxf(v10, 0.f); v11 = fmaxf(v11, 0.f);
            }
            if (EPI == 2) {
                float2 q0 = *reinterpret_cast<const float2*>(resid + (size_t)r0 * M + c);
                float2 q1 = *reinterpret_cast<const float2*>(resid + (size_t)(r0 + 8) * M + c);
                v00 += q0.x; v01 += q0.y; v10 += q1.x; v11 += q1.y;
            }
            if (EPI == 1 || EPI == 3) {
                __nv_bfloat162 z0 = __floats2bfloat162_rn(v00, v01);
                __nv_bfloat162 z1 = __floats2bfloat162_rn(v10, v11);
                *reinterpret_cast<__nv_bfloat162*>(Cb + (size_t)r0 * M + c)       = z0;
                *reinterpret_cast<__nv_bfloat162*>(Cb + (size_t)(r0 + 8) * M + c) = z1;
            } else {
                *reinterpret_cast<float2*>(Cf + (size_t)r0 * M + c)       = make_float2(v00, v01);
                *reinterpret_cast<float2*>(Cf + (size_t)(r0 + 8) * M + c) = make_float2(v10, v11);
            }
        }
    }
}

// ---------------- block reductions ----------------------------------------
__device__ __forceinline__ float block_reduce_sum(float v, float* sh) {
    int lane = threadIdx.x & 31, w = threadIdx.x >> 5;
    #pragma unroll
    for (int off = 16; off; off >>= 1) v += __shfl_xor_sync(0xffffffffu, v, off);
    if (lane == 0) sh[w] = v;
    __syncthreads();
    int nw = blockDim.x >> 5;
    if (w == 0) {
        float r = (lane < nw) ? sh[lane] : 0.f;
        #pragma unroll
        for (int off = 4; off; off >>= 1) r += __shfl_xor_sync(0xffffffffu, r, off);
        if (lane == 0) sh[0] = r;
    }
    __syncthreads();
    float res = sh[0];
    __syncthreads();
    return res;
}

__device__ __forceinline__ float block_reduce_max(float v, float* sh) {
    int lane = threadIdx.x & 31, w = threadIdx.x >> 5;
    #pragma unroll
    for (int off = 16; off; off >>= 1) v = fmaxf(v, __shfl_xor_sync(0xffffffffu, v, off));
    if (lane == 0) sh[w] = v;
    __syncthreads();
    int nw = blockDim.x >> 5;
    if (w == 0) {
        float r = (lane < nw) ? sh[lane] : -1e30f;
        #pragma unroll
        for (int off = 4; off; off >>= 1) r = fmaxf(r, __shfl_xor_sync(0xffffffffu, r, off));
        if (lane == 0) sh[0] = r;
    }
    __syncthreads();
    float res = sh[0];
    __syncthreads();
    return res;
}

// ---------------- fp32 SIMT GEMM for the cdist epilogue ---------------------
#define BM 128
#define BN 64
#define BK 16
#define PAD_A (BM+4)
#define PAD_B (BN+4)

__global__ void __launch_bounds__(256)
gemm_cdist(const float* __restrict__ A, const float* __restrict__ Bw,
           float* C, int N, int M, int K,
           const float* __restrict__ B2,
           const float* __restrict__ nx, const float* __restrict__ ny,
           const float* __restrict__ ny2)
{
    __shared__ float As[BK][PAD_A];
    __shared__ float Bs[BK][PAD_B];
    const int tid = threadIdx.x;
    const int tx = tid & 15, ty = tid >> 4;
    const int n0 = blockIdx.y * BM;
    const int m0 = blockIdx.x * BN;

    const int ar0 = tid >> 2;
    const int ac4 = (tid & 3) << 2;
    const float* aptr0 = A + (size_t)(n0 + ar0)      * K + ac4;
    const float* aptr1 = A + (size_t)(n0 + ar0 + 64) * K + ac4;

    const int brow = tid >> 2;
    const int bc4  = (tid & 3) << 2;
    const int m_ld = m0 + brow;
    const float* bptr = (m_ld >= 512) ? B2 + (size_t)(m_ld - 512) * K + bc4
                                      : Bw + (size_t)m_ld * K + bc4;

    float acc[8][4];
    #pragma unroll
    for (int i = 0; i < 8; i++)
        #pragma unroll
        for (int j = 0; j < 4; j++) acc[i][j] = 0.f;

    for (int k0 = 0; k0 < K; k0 += BK) {
        float4 a0 = *reinterpret_cast<const float4*>(aptr0 + k0);
        float4 a1 = *reinterpret_cast<const float4*>(aptr1 + k0);
        float4 b0 = *reinterpret_cast<const float4*>(bptr + k0);
        As[ac4+0][ar0]    = a0.x; As[ac4+1][ar0]    = a0.y; As[ac4+2][ar0]    = a0.z; As[ac4+3][ar0]    = a0.w;
        As[ac4+0][ar0+64] = a1.x; As[ac4+1][ar0+64] = a1.y; As[ac4+2][ar0+64] = a1.z; As[ac4+3][ar0+64] = a1.w;
        Bs[bc4+0][brow] = b0.x; Bs[bc4+1][brow] = b0.y; Bs[bc4+2][brow] = b0.z; Bs[bc4+3][brow] = b0.w;
        __syncthreads();
        #pragma unroll
        for (int k = 0; k < BK; k++) {
            float4 af0 = *reinterpret_cast<const float4*>(&As[k][ty*8]);
            float4 af1 = *reinterpret_cast<const float4*>(&As[k][ty*8+4]);
            float4 bf  = *reinterpret_cast<const float4*>(&Bs[k][tx*4]);
            float a_[8] = {af0.x, af0.y, af0.z, af0.w, af1.x, af1.y, af1.z, af1.w};
            float b_[4] = {bf.x, bf.y, bf.z, bf.w};
            #pragma unroll
            for (int i = 0; i < 8; i++)
                #pragma unroll
                for (int j = 0; j < 4; j++) acc[i][j] += a_[i] * b_[j];
        }
        __syncthreads();
    }

    const int nr0 = n0 + ty * 8;
    const int mc0 = m0 + tx * 4;
    #pragma unroll
    for (int i = 0; i < 8; i++) {
        int nn = nr0 + i;
        float nxi = nx[nn];
        float rr[4];
        #pragma unroll
        for (int j = 0; j < 4; j++) {
            int m = mc0 + j;
            float nyv = (m < 512) ? ny[m] : ny2[m - 512];
            float d2 = nxi + nyv - 2.f * acc[i][j];
            float a = -sqrtf(fmaxf(d2, 0.f));
            if (m >= 512 && (m - 512) == nn) a -= 1e6f;
            rr[j] = a;
        }
        *reinterpret_cast<float4*>(C + (size_t)nn * M + mc0) =
            make_float4(rr[0], rr[1], rr[2], rr[3]);
    }
}

// ---------------- NN GEMM with fused squared-sum: V = W @ Y, sum(V^2) ------
__global__ void __launch_bounds__(256)
vgemm_sq(const float* __restrict__ W, const float* __restrict__ P,
         const float* __restrict__ XF, float* __restrict__ part)
{
    const int K = 1024, M = XFD;
    __shared__ float As[BK][PAD_A];
    __shared__ float Bs[BK][PAD_B];
    __shared__ float shred[32];
    const int tid = threadIdx.x;
    const int tx = tid & 15, ty = tid >> 4;
    const int n0 = blockIdx.y * BM;
    const int m0 = blockIdx.x * BN;

    const int ar0 = tid >> 2;
    const int ac4 = (tid & 3) << 2;
    const float* aptr0 = W + (size_t)(n0 + ar0)      * K + ac4;
    const float* aptr1 = W + (size_t)(n0 + ar0 + 64) * K + ac4;
    const int brow = tid >> 4;
    const int bc4  = (tid & 15) << 2;

    float acc[8][4];
    #pragma unroll
    for (int i = 0; i < 8; i++)
        #pragma unroll
        for (int j = 0; j < 4; j++) acc[i][j] = 0.f;

    for (int k0 = 0; k0 < K; k0 += BK) {
        float4 a0 = *reinterpret_cast<const float4*>(aptr0 + k0);
        float4 a1 = *reinterpret_cast<const float4*>(aptr1 + k0);
        int krow = k0 + brow;
        const float* ysrc = (krow < 512) ? P + (size_t)krow * M
                                         : XF + (size_t)(krow - 512) * M;
        float4 b0 = *reinterpret_cast<const float4*>(ysrc + m0 + bc4);
        As[ac4+0][ar0]    = a0.x; As[ac4+1][ar0]    = a0.y; As[ac4+2][ar0]    = a0.z; As[ac4+3][ar0]    = a0.w;
        As[ac4+0][ar0+64] = a1.x; As[ac4+1][ar0+64] = a1.y; As[ac4+2][ar0+64] = a1.z; As[ac4+3][ar0+64] = a1.w;
        *reinterpret_cast<float4*>(&Bs[brow][bc4]) = b0;
        __syncthreads();
        #pragma unroll
        for (int k = 0; k < BK; k++) {
            float4 af0 = *reinterpret_cast<const float4*>(&As[k][ty*8]);
            float4 af1 = *reinterpret_cast<const float4*>(&As[k][ty*8+4]);
            float4 bf  = *reinterpret_cast<const float4*>(&Bs[k][tx*4]);
            float a_[8] = {af0.x, af0.y, af0.z, af0.w, af1.x, af1.y, af1.z, af1.w};
            float b_[4] = {bf.x, bf.y, bf.z, bf.w};
            #pragma unroll
            for (int i = 0; i < 8; i++)
                #pragma unroll
                for (int j = 0; j < 4; j++) acc[i][j] += a_[i] * b_[j];
        }
        __syncthreads();
    }

    float ss = 0.f;
    #pragma unroll
    for (int i = 0; i < 8; i++)
        #pragma unroll
        for (int j = 0; j < 4; j++) ss += acc[i][j] * acc[i][j];
    float tot = block_reduce_sum(ss, shred);
    if (tid == 0) part[blockIdx.y * gridDim.x + blockIdx.x] = tot;
}

// ---------------- LayerNorm (bf16 output feeds MMA) ------------------------
__global__ void __launch_bounds__(128)
ln_kernel(const float* __restrict__ x, const float* __restrict__ g,
          const float* __restrict__ b, __nv_bfloat16* __restrict__ out)
{
    int t = blockIdx.x;
    int tid = threadIdx.x;
    const float* xr = x + (size_t)t * DM;
    float4 v = *reinterpret_cast<const float4*>(xr + tid * 4);
    float s  = v.x + v.y + v.z + v.w;
    float sq = v.x*v.x + v.y*v.y + v.z*v.z + v.w*v.w;
    int lane = tid & 31, w = tid >> 5;
    #pragma unroll
    for (int off = 16; off; off >>= 1) {
        s  += __shfl_xor_sync(0xffffffffu, s,  off);
        sq += __shfl_xor_sync(0xffffffffu, sq, off);
    }
    __shared__ float shs[4], shq[4];
    if (lane == 0) { shs[w] = s; shq[w] = sq; }
    __syncthreads();
    s  = shs[0] + shs[1] + shs[2] + shs[3];
    sq = shq[0] + shq[1] + shq[2] + shq[3];
    float mean = s * (1.f / 512.f);
    float var  = sq * (1.f / 512.f) - mean * mean;
    float inv  = rsqrtf(var + 1e-5f);
    float4 gv = *reinterpret_cast<const float4*>(g + tid * 4);
    float4 bv = *reinterpret_cast<const float4*>(b + tid * 4);
    __nv_bfloat162 p0 = __floats2bfloat162_rn((v.x - mean) * inv * gv.x + bv.x,
                                              (v.y - mean) * inv * gv.y + bv.y);
    __nv_bfloat162 p1 = __floats2bfloat162_rn((v.z - mean) * inv * gv.z + bv.z,
                                              (v.w - mean) * inv * gv.w + bv.w);
    uint2 pk;
    pk.x = *reinterpret_cast<uint32_t*>(&p0);
    pk.y = *reinterpret_cast<uint32_t*>(&p1);
    *reinterpret_cast<uint2*>(out + (size_t)t * DM + tid * 4) = pk;
}

// ---------------- attention: one (batch, head) per block --------------------
__global__ void __launch_bounds__(256)
attn_kernel(const __nv_bfloat16* __restrict__ qkv, __nv_bfloat16* __restrict__ o)
{
    __shared__ float qs[32][68];
    __shared__ float kt[64][36];   // transposed: kt[d][j]
    __shared__ float vs[32][64];
    __shared__ float ps[32][33];
    int bh = blockIdx.x;
    int b = bh >> 3, h = bh & 7;
    int tid = threadIdx.x;
    size_t base = (size_t)(b * 32) * QKVD + h * 64;
    #pragma unroll
    for (int l = 0; l < 2; l++) {
        int idx = tid + l * 256;
        int i = idx >> 4;
        int c = (idx & 15) << 2;
        uint2 qv = *reinterpret_cast<const uint2*>(qkv + base + (size_t)i * QKVD + c);
        uint2 kv = *reinterpret_cast<const uint2*>(qkv + base + (size_t)i * QKVD + 512 + c);
        uint2 vv = *reinterpret_cast<const uint2*>(qkv + base + (size_t)i * QKVD + 1024 + c);
        float2 q01 = __bfloat1622float2(*reinterpret_cast<__nv_bfloat162*>(&qv.x));
        float2 q23 = __bfloat1622float2(*reinterpret_cast<__nv_bfloat162*>(&qv.y));
        float2 k01 = __bfloat1622float2(*reinterpret_cast<__nv_bfloat162*>(&kv.x));
        float2 k23 = __bfloat1622float2(*reinterpret_cast<__nv_bfloat162*>(&kv.y));
        float2 v01 = __bfloat1622float2(*reinterpret_cast<__nv_bfloat162*>(&vv.x));
        float2 v23 = __bfloat1622float2(*reinterpret_cast<__nv_bfloat162*>(&vv.y));
        qs[i][c] = q01.x; qs[i][c+1] = q01.y; qs[i][c+2] = q23.x; qs[i][c+3] = q23.y;
        kt[c][i] = k01.x; kt[c+1][i] = k01.y; kt[c+2][i] = k23.x; kt[c+3][i] = k23.y;
        vs[i][c] = v01.x; vs[i][c+1] = v01.y; vs[i][c+2] = v23.x; vs[i][c+3] = v23.y;
    }
    __syncthreads();
    {   // scores: thread (i, j0..j0+3)
        int i = tid >> 3;
        int j0 = (tid & 7) << 2;
        float s0 = 0.f, s1 = 0.f, s2 = 0.f, s3 = 0.f;
        #pragma unroll
        for (int d = 0; d < 64; d += 4) {
            float4 q  = *reinterpret_cast<const float4*>(&qs[i][d]);
            float4 k0 = *reinterpret_cast<const float4*>(&kt[d  ][j0]);
            float4 k1 = *reinterpret_cast<const float4*>(&kt[d+1][j0]);
            float4 k2 = *reinterpret_cast<const float4*>(&kt[d+2][j0]);
            float4 k3 = *reinterpret_cast<const float4*>(&kt[d+3][j0]);
            s0 += q.x*k0.x + q.y*k1.x + q.z*k2.x + q.w*k3.x;
            s1 += q.x*k0.y + q.y*k1.y + q.z*k2.y + q.w*k3.y;
            s2 += q.x*k0.z + q.y*k1.z + q.z*k2.z + q.w*k3.z;
            s3 += q.x*k0.w + q.y*k1.w + q.z*k2.w + q.w*k3.w;
        }
        ps[i][j0]   = s0 * 0.125f;
        ps[i][j0+1] = s1 * 0.125f;
        ps[i][j0+2] = s2 * 0.125f;
        ps[i][j0+3] = s3 * 0.125f;
    }
    __syncthreads();
    {   // softmax per row
        int w = tid >> 5, lane = tid & 31;
        #pragma unroll
        for (int r = 0; r < 4; r++) {
            int i = w + (r << 3);
            float v = ps[i][lane];
            float mx = v;
            #pragma unroll
            for (int off = 16; off; off >>= 1) mx = fmaxf(mx, __shfl_xor_sync(0xffffffffu, mx, off));
            float e = __expf(v - mx);
            float sm = e;
            #pragma unroll
            for (int off = 16; off; off >>= 1) sm += __shfl_xor_sync(0xffffffffu, sm, off);
            ps[i][lane] = e / sm;
        }
    }
    __syncthreads();
    {   // o = p @ v
        int i = tid >> 3;
        int d0 = (tid & 7) << 3;
        float4 a0 = make_float4(0.f,0.f,0.f,0.f);
        float4 a1 = make_float4(0.f,0.f,0.f,0.f);
        #pragma unroll
        for (int j = 0; j < 32; j++) {
            float pv = ps[i][j];
            float4 v0 = *reinterpret_cast<const float4*>(&vs[j][d0]);
            float4 v1 = *reinterpret_cast<const float4*>(&vs[j][d0+4]);
            a0.x += pv*v0.x; a0.y += pv*v0.y; a0.z += pv*v0.z; a0.w += pv*v0.w;
            a1.x += pv*v1.x; a1.y += pv*v1.y; a1.z += pv*v1.z; a1.w += pv*v1.w;
        }
        __nv_bfloat162 c0 = __floats2bfloat162_rn(a0.x, a0.y);
        __nv_bfloat162 c1 = __floats2bfloat162_rn(a0.z, a0.w);
        __nv_bfloat162 c2 = __floats2bfloat162_rn(a1.x, a1.y);
        __nv_bfloat162 c3 = __floats2bfloat162_rn(a1.z, a1.w);
        uint4 pk;
        pk.x = *reinterpret_cast<uint32_t*>(&c0);
        pk.y = *reinterpret_cast<uint32_t*>(&c1);
        pk.z = *reinterpret_cast<uint32_t*>(&c2);
        pk.w = *reinterpret_cast<uint32_t*>(&c3);
        *reinterpret_cast<uint4*>(o + (size_t)(b * 32 + i) * DM + h * 64 + d0) = pk;
    }
}

// ---------------- squared norms of xf rows and p rows -----------------------
__global__ void __launch_bounds__(256)
sqnorm_kernel(const float* __restrict__ xf, const float* __restrict__ p,
              float* __restrict__ nx, float* __restrict__ np)
{
    int r = blockIdx.x;
    const float* src = (r < 512) ? xf + (size_t)r * XFD : p + (size_t)(r - 512) * XFD;
    float s = 0.f;
    for (int c = threadIdx.x * 4; c < XFD; c += 256 * 4) {
        float4 v = *reinterpret_cast<const float4*>(src + c);
        s += v.x*v.x + v.y*v.y + v.z*v.z + v.w*v.w;
    }
    __shared__ float sh[32];
    float tot = block_reduce_sum(s, sh);
    if (threadIdx.x == 0) { if (r < 512) nx[r] = tot; else np[r - 512] = tot; }
}

// ---------------- row stats of A (max, sum of exp) ---------------------------
__global__ void __launch_bounds__(256)
rowstats_kernel(const float* __restrict__ A, float* __restrict__ rmax,
                float* __restrict__ rsum)
{
    int r = blockIdx.x;
    const float* ar = A + (size_t)r * 1024;
    float v[4];
    float mx = -1e30f;
    #pragma unroll
    for (int l = 0; l < 4; l++) { v[l] = ar[threadIdx.x + l * 256]; mx = fmaxf(mx, v[l]); }
    __shared__ float sh[32];
    mx = block_reduce_max(mx, sh);
    float s = 0.f;
    #pragma unroll
    for (int l = 0; l < 4; l++) s += __expf(v[l] - mx);
    s = block_reduce_sum(s, sh);
    if (threadIdx.x == 0) { rmax[r] = mx; rsum[r] = s; }
}

// ---------------- column stats of A ----------------------------------------
__global__ void __launch_bounds__(256)
colstats_kernel(const float* __restrict__ A, float* __restrict__ cmax,
                float* __restrict__ csum)
{
    int c = blockIdx.x * 256 + threadIdx.x;
    float mx = -1e30f;
    for (int i = 0; i < 512; i++) mx = fmaxf(mx, A[(size_t)i * 1024 + c]);
    float s = 0.f;
    for (int i = 0; i < 512; i++) s += __expf(A[(size_t)i * 1024 + c] - mx);
    cmax[c] = mx; csum[c] = s;
}

// ---------------- build W = [A_pos*sneg | -(A_neg*spos)] --------------------
__global__ void __launch_bounds__(256)
wbuild_kernel(const float* __restrict__ A, const float* __restrict__ rmax,
              const float* __restrict__ rsum, const float* __restrict__ cmax,
              const float* __restrict__ csum, float* __restrict__ W)
{
    int r = blockIdx.x;
    int j0 = threadIdx.x * 4;
    float rm = rmax[r];
    float rs = rsum[r];
    float4 a = *reinterpret_cast<const float4*>(A + (size_t)r * 1024 + j0);
    float av[4] = {a.x, a.y, a.z, a.w};
    float soft[4];
    float lsum = 0.f;
    #pragma unroll
    for (int l = 0; l < 4; l++) {
        int j = j0 + l;
        float s = __expf(av[l] - 0.5f * (rm + cmax[j])) * rsqrtf(rs * csum[j]);
        soft[l] = s;
        lsum += s;
    }
    bool isneg = (threadIdx.x >= 128);
    __shared__ float sh[32];
    float sp = block_reduce_sum(isneg ? 0.f : lsum, sh);
    float sn = block_reduce_sum(isneg ? lsum : 0.f, sh);
    float scale = isneg ? -(sp * sn) : sn;
    float4 o = make_float4(soft[0]*scale, soft[1]*scale, soft[2]*scale, soft[3]*scale);
    *reinterpret_cast<float4*>(W + (size_t)r * 1024 + j0) = o;
}

// ---------------- final reduce → mean(V^2) ----------------------------------
__global__ void __launch_bounds__(256)
finalize_kernel(const float* __restrict__ part, float* __restrict__ out)
{
    __shared__ float sh[32];
    float v = part[threadIdx.x];
    float tot = block_reduce_sum(v, sh);
    if (threadIdx.x == 0) out[0] = tot * (1.f / (512.f * 4096.f));
}

// ---------------- host launch ------------------------------------------------
extern "C" void kernel_launch(void* const* d_in, const int* in_sizes, int n_in,
                              void* d_out, int out_size)
{
    (void)in_sizes; (void)n_in; (void)out_size;
    const float* p     = (const float*)d_in[0];
    const float* eps   = (const float*)d_in[1];
    const float* in_w  = (const float*)d_in[2];
    const float* in_b  = (const float*)d_in[3];
    const float* Wqkv  = (const float*)d_in[4];
    const float* bqkv  = (const float*)d_in[5];
    const float* Wo    = (const float*)d_in[6];
    const float* bo    = (const float*)d_in[7];
    const float* ln1g  = (const float*)d_in[8];
    const float* ln1b  = (const float*)d_in[9];
    const float* W1    = (const float*)d_in[10];
    const float* b1    = (const float*)d_in[11];
    const float* W2    = (const float*)d_in[12];
    const float* b2    = (const float*)d_in[13];
    const float* ln2g  = (const float*)d_in[14];
    const float* ln2b  = (const float*)d_in[15];
    const float* out_w = (const float*)d_in[16];
    const float* out_b = (const float*)d_in[17];
    float* out = (float*)d_out;

    float *px, *pxf, *pA, *pW;
    float *pnx, *pnp, *prmax, *prsum, *pcmax, *pcsum, *ppart;
    __nv_bfloat16 *peps, *phb, *pattn, *pqkvb, *pffb, *pxb, *pwb;
    cudaGetSymbolAddress((void**)&px,    g_x);
    cudaGetSymbolAddress((void**)&pxf,   g_xf);
    cudaGetSymbolAddress((void**)&pA,    g_A);
    cudaGetSymbolAddress((void**)&pW,    g_W);
    cudaGetSymbolAddress((void**)&pnx,   g_nx);
    cudaGetSymbolAddress((void**)&pnp,   g_np);
    cudaGetSymbolAddress((void**)&prmax, g_rmax);
    cudaGetSymbolAddress((void**)&prsum, g_rsum);
    cudaGetSymbolAddress((void**)&pcmax, g_cmax);
    cudaGetSymbolAddress((void**)&pcsum, g_csum);
    cudaGetSymbolAddress((void**)&ppart, g_part);
    cudaGetSymbolAddress((void**)&peps,  b_eps);
    cudaGetSymbolAddress((void**)&phb,   b_h);
    cudaGetSymbolAddress((void**)&pattn, b_attn);
    cudaGetSymbolAddress((void**)&pqkvb, b_qkv);
    cudaGetSymbolAddress((void**)&pffb,  b_ff);
    cudaGetSymbolAddress((void**)&pxb,   b_x);
    cudaGetSymbolAddress((void**)&pwb,   b_wts);

    dim3 blk(256);
    auto rblocks = [](int n) { return (n / 4 + 255) / 256; };

    // convert weights + eps to bf16 (round-nearest)
    cvt_bf16_kernel<<<rblocks(DM*CHD),    blk>>>(in_w,  pwb + R_INW,  DM*CHD);
    cvt_bf16_kernel<<<rblocks(4*QKVD*DM), blk>>>(Wqkv,  pwb + R_QKV,  4*QKVD*DM);
    cvt_bf16_kernel<<<rblocks(4*DM*DM),   blk>>>(Wo,    pwb + R_WO,   4*DM*DM);
    cvt_bf16_kernel<<<rblocks(4*FFD*DM),  blk>>>(W1,    pwb + R_W1,   4*FFD*DM);
    cvt_bf16_kernel<<<rblocks(4*DM*FFD),  blk>>>(W2,    pwb + R_W2,   4*DM*FFD);
    cvt_bf16_kernel<<<rblocks(CHD*DM),    blk>>>(out_w, pwb + R_OUTW, CHD*DM);
    cvt_bf16_kernel<<<rblocks(NTOK*CHD),  blk>>>(eps,   peps,         NTOK*CHD);

    // x = eps @ in_w^T + in_b   (fp32 out)
    mma_gemm<0><<<dim3(DM/128, NTOK/128), blk>>>(peps, pwb + R_INW, in_b,
                                                 nullptr, px, nullptr, DM, CHD);
    for (int i = 0; i < 4; i++) {
        ln_kernel<<<NTOK, 128>>>(px, ln1g + i*DM, ln1b + i*DM, phb);
        mma_gemm<3><<<dim3(QKVD/128, NTOK/128), blk>>>(
            phb, pwb + R_QKV + (size_t)i*QKVD*DM, bqkv + (size_t)i*QKVD,
            nullptr, nullptr, pqkvb, QKVD, DM);
        attn_kernel<<<4096, 256>>>(pqkvb, pattn);
        mma_gemm<2><<<dim3(DM/128, NTOK/128), blk>>>(
            pattn, pwb + R_WO + (size_t)i*DM*DM, bo + (size_t)i*DM,
            px, px, nullptr, DM, DM);
        ln_kernel<<<NTOK, 128>>>(px, ln2g + i*DM, ln2b + i*DM, phb);
        mma_gemm<1><<<dim3(FFD/128, NTOK/128), blk>>>(
            phb, pwb + R_W1 + (size_t)i*FFD*DM, b1 + (size_t)i*FFD,
            nullptr, nullptr, pffb, FFD, DM);
        mma_gemm<2><<<dim3(DM/128, NTOK/128), blk>>>(
            pffb, pwb + R_W2 + (size_t)i*DM*FFD, b2 + (size_t)i*DM,
            px, px, nullptr, DM, FFD);
    }
    // xf = x @ out_w^T + out_b
    cvt_bf16_kernel<<<rblocks(NTOK*DM), blk>>>(px, pxb, NTOK*DM);
    mma_gemm<0><<<dim3(CHD/128, NTOK/128), blk>>>(pxb, pwb + R_OUTW, out_b,
                                                  nullptr, pxf, nullptr, CHD, DM);

    // compute_V (exact fp32 path)
    sqnorm_kernel<<<1024, 256>>>(pxf, p, pnx, pnp);
    gemm_cdist<<<dim3(1024/BN, NB/BM), blk>>>(pxf, p, pA, NB, 1024, XFD,
                                              pxf, pnx, pnp, pnx);
    rowstats_kernel<<<NB, 256>>>(pA, prmax, prsum);
    colstats_kernel<<<4, 256>>>(pA, pcmax, pcsum);
    wbuild_kernel<<<NB, 256>>>(pA, prmax, prsum, pcmax, pcsum, pW);
    vgemm_sq<<<dim3(XFD/BN, NB/BM), blk>>>(pW, p, pxf, ppart);
    finalize_kernel<<<1, 256>>>(ppart, out);
}

// round 15
// speedup vs baseline: 3.8166x; 1.0584x over previous
#include <cuda_runtime.h>
#include <cuda_bf16.h>
#include <cstdint>

#define NTOK 16384
#define DM   512
#define FFD  2048
#define QKVD 1536
#define CHD  128
#define XFD  4096
#define NB   512

// ---------------- scratch (device globals; no cudaMalloc allowed) ----------
__device__ float g_x   [NTOK*DM];      // fp32 residual stream
__device__ float g_xf  [NTOK*CHD];     // == (512, 4096) row-major
__device__ float g_A   [NB*1024];
__device__ float g_W   [NB*1024];
__device__ float g_nx  [NB];
__device__ float g_np  [NB];
__device__ float g_rmax[NB];
__device__ float g_rsum[NB];
__device__ float g_cmax[1024];
__device__ float g_csum[1024];
__device__ float g_part[256];
// bf16 activation buffers
__device__ __nv_bfloat16 b_eps [NTOK*CHD];
__device__ __nv_bfloat16 b_h   [NTOK*DM];
__device__ __nv_bfloat16 b_attn[NTOK*DM];
__device__ __nv_bfloat16 b_qkv [NTOK*QKVD];
__device__ __nv_bfloat16 b_ff  [NTOK*FFD];
__device__ __nv_bfloat16 b_x   [NTOK*DM];
// bf16 weights: in_w | Wqkv | Wo | W1 | W2 | out_w
#define R_INW  0
#define R_QKV  65536
#define R_WO   (R_QKV + 4*QKVD*DM)
#define R_W1   (R_WO  + 4*DM*DM)
#define R_W2   (R_W1  + 4*FFD*DM)
#define R_OUTW (R_W2  + 4*DM*FFD)
#define R_TOT  (R_OUTW + CHD*DM)
__device__ __nv_bfloat16 b_wts[R_TOT];

// ---------------- fp32 -> bf16 conversion ----------------------------------
__global__ void __launch_bounds__(256)
cvt_bf16_kernel(const float* __restrict__ src, __nv_bfloat16* __restrict__ dst, int n)
{
    int i = (blockIdx.x * 256 + threadIdx.x) * 4;
    if (i < n) {
        float4 v = *reinterpret_cast<const float4*>(src + i);
        __nv_bfloat162 p0 = __floats2bfloat162_rn(v.x, v.y);
        __nv_bfloat162 p1 = __floats2bfloat162_rn(v.z, v.w);
        uint2 pk;
        pk.x = *reinterpret_cast<uint32_t*>(&p0);
        pk.y = *reinterpret_cast<uint32_t*>(&p1);
        *reinterpret_cast<uint2*>(dst + i) = pk;
    }
}

__device__ __forceinline__ uint32_t smem_u32(const void* p) {
    uint32_t a;
    asm("{ .reg .u64 t; cvta.to.shared.u64 t, %1; cvt.u32.u64 %0, t; }" : "=r"(a) : "l"(p));
    return a;
}

#define MMA_BF16(c, a, b)                                                     \
    asm volatile("mma.sync.aligned.m16n8k16.row.col.f32.bf16.bf16.f32 "       \
        "{%0,%1,%2,%3}, {%4,%5,%6,%7}, {%8,%9}, {%0,%1,%2,%3};"               \
        : "+f"((c)[0]), "+f"((c)[1]), "+f"((c)[2]), "+f"((c)[3])              \
        : "r"((a)[0]), "r"((a)[1]), "r"((a)[2]), "r"((a)[3]),                 \
          "r"((b)[0]), "r"((b)[1]))

#define LDSM_X4(r0, r1, r2, r3, addr)                                         \
    asm volatile("ldmatrix.sync.aligned.m8n8.x4.shared.b16 {%0,%1,%2,%3}, [%4];" \
        : "=r"(r0), "=r"(r1), "=r"(r2), "=r"(r3) : "r"(addr))

// ---------------- bf16 mma.sync GEMM: C = A(NxK) @ Bw(MxK)^T ---------------
// block tile 128 (tokens) x 128 (features) x 32, 8 warps, warp tile 64x32
// EPI 0: +bias->f32 | 1: relu(+bias)->bf16 | 2: +bias+resid->f32 | 3: +bias->bf16
#define TRB 40               // bf16 per smem row (32 data + 8 pad), 80 bytes
#define TILEB (128*TRB)

template<int EPI>
__global__ void __launch_bounds__(256)
mma_gemm(const __nv_bfloat16* __restrict__ A, const __nv_bfloat16* __restrict__ Bw,
         const float* __restrict__ bias, const float* resid,
         float* __restrict__ Cf, __nv_bfloat16* __restrict__ Cb, int M, int K)
{
    __shared__ __nv_bfloat16 sm[4*TILEB];   // [2 stages][A,B] = 40960 bytes
    __nv_bfloat16* As = sm;
    __nv_bfloat16* Bs = sm + 2*TILEB;

    const int tid  = threadIdx.x;
    const int w    = tid >> 5;
    const int lane = tid & 31;
    const int g    = lane >> 2;
    const int tig  = lane & 3;
    const int wm   = (w & 1) * 64;
    const int wn   = (w >> 1) * 32;
    const int n0   = blockIdx.y * 128;
    const int m0   = blockIdx.x * 128;

    // cp.async geometry: each k-tile row = 32 bf16 = 64B = 4 x 16B chunks
    const int rb = tid >> 2;          // 0..63
    const int cc = (tid & 3) * 8;     // bf16 col of chunk

    // ldmatrix per-lane source addresses (bytes)
    // A x4: groups (lane>>3): rows lane&15, k-halves lane>>4
    const uint32_t aBase0 = smem_u32(As) +
        (uint32_t)((wm + (lane & 15)) * TRB) * 2u + (uint32_t)(lane >> 4) * 16u;
    // B x4: group bg=lane>>3: n-half (bg>>1)*8 + (lane&7), k-half (bg&1)
    const int bg = lane >> 3;
    const uint32_t bBase0 = smem_u32(Bs) +
        (uint32_t)((wn + ((bg >> 1) << 3) + (lane & 7)) * TRB) * 2u +
        (uint32_t)(bg & 1) * 16u;

    float acc[4][4][4];
    #pragma unroll
    for (int mt = 0; mt < 4; mt++)
        #pragma unroll
        for (int nt = 0; nt < 4; nt++)
            #pragma unroll
            for (int r = 0; r < 4; r++) acc[mt][nt][r] = 0.f;

    auto preload = [&](int kt, int buf) {
        __nv_bfloat16* sa = As + buf * TILEB;
        __nv_bfloat16* sb = Bs + buf * TILEB;
        const __nv_bfloat16* gA = A  + (size_t)(n0 + rb) * K + kt * 32 + cc;
        const __nv_bfloat16* gB = Bw + (size_t)(m0 + rb) * K + kt * 32 + cc;
        #pragma unroll
        for (int i = 0; i < 2; i++) {
            uint32_t da = smem_u32(sa + (rb + i*64) * TRB + cc);
            uint32_t db = smem_u32(sb + (rb + i*64) * TRB + cc);
            asm volatile("cp.async.cg.shared.global [%0], [%1], 16;"
                         :: "r"(da), "l"(gA + (size_t)i * 64 * K));
            asm volatile("cp.async.cg.shared.global [%0], [%1], 16;"
                         :: "r"(db), "l"(gB + (size_t)i * 64 * K));
        }
        asm volatile("cp.async.commit_group;" ::: "memory");
    };

    const int KT = K >> 5;
    preload(0, 0);
    for (int kt = 0; kt < KT; kt++) {
        const int buf = kt & 1;
        if (kt + 1 < KT) {
            preload(kt + 1, buf ^ 1);
            asm volatile("cp.async.wait_group 1;" ::: "memory");
        } else {
            asm volatile("cp.async.wait_group 0;" ::: "memory");
        }
        __syncthreads();

        const uint32_t aB = aBase0 + (uint32_t)buf * (TILEB * 2u);
        const uint32_t bB = bBase0 + (uint32_t)buf * (TILEB * 2u);
        #pragma unroll
        for (int ks = 0; ks < 2; ks++) {
            uint32_t af[4][4], bf[4][2];
            #pragma unroll
            for (int mt = 0; mt < 4; mt++)
                LDSM_X4(af[mt][0], af[mt][1], af[mt][2], af[mt][3],
                        aB + (uint32_t)(mt * 16 * TRB * 2) + (uint32_t)(ks * 32));
            #pragma unroll
            for (int pp = 0; pp < 2; pp++)
                LDSM_X4(bf[2*pp][0], bf[2*pp][1], bf[2*pp+1][0], bf[2*pp+1][1],
                        bB + (uint32_t)(pp * 16 * TRB * 2) + (uint32_t)(ks * 32));
            #pragma unroll
            for (int mt = 0; mt < 4; mt++)
                #pragma unroll
                for (int nt = 0; nt < 4; nt++)
                    MMA_BF16(acc[mt][nt], af[mt], bf[nt]);
        }
        __syncthreads();
    }

    // epilogue
    #pragma unroll
    for (int mt = 0; mt < 4; mt++) {
        const int r0 = n0 + wm + mt * 16 + g;
        #pragma unroll
        for (int nt = 0; nt < 4; nt++) {
            const int c = m0 + wn + nt * 8 + 2 * tig;
            const float2 bv = *reinterpret_cast<const float2*>(bias + c);
            float v00 = acc[mt][nt][0] + bv.x;
            float v01 = acc[mt][nt][1] + bv.y;
            float v10 = acc[mt][nt][2] + bv.x;
            float v11 = acc[mt][nt][3] + bv.y;
            if (EPI == 1) {
                v00 = fmaxf(v00, 0.f); v01 = fmaxf(v01, 0.f);
                v10 = fmaxf(v10, 0.f); v11 = fmaxf(v11, 0.f);
            }
            if (EPI == 2) {
                float2 q0 = *reinterpret_cast<const float2*>(resid + (size_t)r0 * M + c);
                float2 q1 = *reinterpret_cast<const float2*>(resid + (size_t)(r0 + 8) * M + c);
                v00 += q0.x; v01 += q0.y; v10 += q1.x; v11 += q1.y;
            }
            if (EPI == 1 || EPI == 3) {
                __nv_bfloat162 z0 = __floats2bfloat162_rn(v00, v01);
                __nv_bfloat162 z1 = __floats2bfloat162_rn(v10, v11);
                *reinterpret_cast<__nv_bfloat162*>(Cb + (size_t)r0 * M + c)       = z0;
                *reinterpret_cast<__nv_bfloat162*>(Cb + (size_t)(r0 + 8) * M + c) = z1;
            } else {
                *reinterpret_cast<float2*>(Cf + (size_t)r0 * M + c)       = make_float2(v00, v01);
                *reinterpret_cast<float2*>(Cf + (size_t)(r0 + 8) * M + c) = make_float2(v10, v11);
            }
        }
    }
}

// ---------------- block reductions ----------------------------------------
__device__ __forceinline__ float block_reduce_sum(float v, float* sh) {
    int lane = threadIdx.x & 31, w = threadIdx.x >> 5;
    #pragma unroll
    for (int off = 16; off; off >>= 1) v += __shfl_xor_sync(0xffffffffu, v, off);
    if (lane == 0) sh[w] = v;
    __syncthreads();
    int nw = blockDim.x >> 5;
    if (w == 0) {
        float r = (lane < nw) ? sh[lane] : 0.f;
        #pragma unroll
        for (int off = 4; off; off >>= 1) r += __shfl_xor_sync(0xffffffffu, r, off);
        if (lane == 0) sh[0] = r;
    }
    __syncthreads();
    float res = sh[0];
    __syncthreads();
    return res;
}

__device__ __forceinline__ float block_reduce_max(float v, float* sh) {
    int lane = threadIdx.x & 31, w = threadIdx.x >> 5;
    #pragma unroll
    for (int off = 16; off; off >>= 1) v = fmaxf(v, __shfl_xor_sync(0xffffffffu, v, off));
    if (lane == 0) sh[w] = v;
    __syncthreads();
    int nw = blockDim.x >> 5;
    if (w == 0) {
        float r = (lane < nw) ? sh[lane] : -1e30f;
        #pragma unroll
        for (int off = 4; off; off >>= 1) r = fmaxf(r, __shfl_xor_sync(0xffffffffu, r, off));
        if (lane == 0) sh[0] = r;
    }
    __syncthreads();
    float res = sh[0];
    __syncthreads();
    return res;
}

// ---------------- fp32 SIMT GEMM for the cdist epilogue ---------------------
#define BM 128
#define BN 64
#define BK 16
#define PAD_A (BM+4)
#define PAD_B (BN+4)

__global__ void __launch_bounds__(256)
gemm_cdist(const float* __restrict__ A, const float* __restrict__ Bw,
           float* C, int N, int M, int K,
           const float* __restrict__ B2,
           const float* __restrict__ nx, const float* __restrict__ ny,
           const float* __restrict__ ny2)
{
    __shared__ float As[BK][PAD_A];
    __shared__ float Bs[BK][PAD_B];
    const int tid = threadIdx.x;
    const int tx = tid & 15, ty = tid >> 4;
    const int n0 = blockIdx.y * BM;
    const int m0 = blockIdx.x * BN;

    const int ar0 = tid >> 2;
    const int ac4 = (tid & 3) << 2;
    const float* aptr0 = A + (size_t)(n0 + ar0)      * K + ac4;
    const float* aptr1 = A + (size_t)(n0 + ar0 + 64) * K + ac4;

    const int brow = tid >> 2;
    const int bc4  = (tid & 3) << 2;
    const int m_ld = m0 + brow;
    const float* bptr = (m_ld >= 512) ? B2 + (size_t)(m_ld - 512) * K + bc4
                                      : Bw + (size_t)m_ld * K + bc4;

    float acc[8][4];
    #pragma unroll
    for (int i = 0; i < 8; i++)
        #pragma unroll
        for (int j = 0; j < 4; j++) acc[i][j] = 0.f;

    for (int k0 = 0; k0 < K; k0 += BK) {
        float4 a0 = *reinterpret_cast<const float4*>(aptr0 + k0);
        float4 a1 = *reinterpret_cast<const float4*>(aptr1 + k0);
        float4 b0 = *reinterpret_cast<const float4*>(bptr + k0);
        As[ac4+0][ar0]    = a0.x; As[ac4+1][ar0]    = a0.y; As[ac4+2][ar0]    = a0.z; As[ac4+3][ar0]    = a0.w;
        As[ac4+0][ar0+64] = a1.x; As[ac4+1][ar0+64] = a1.y; As[ac4+2][ar0+64] = a1.z; As[ac4+3][ar0+64] = a1.w;
        Bs[bc4+0][brow] = b0.x; Bs[bc4+1][brow] = b0.y; Bs[bc4+2][brow] = b0.z; Bs[bc4+3][brow] = b0.w;
        __syncthreads();
        #pragma unroll
        for (int k = 0; k < BK; k++) {
            float4 af0 = *reinterpret_cast<const float4*>(&As[k][ty*8]);
            float4 af1 = *reinterpret_cast<const float4*>(&As[k][ty*8+4]);
            float4 bf  = *reinterpret_cast<const float4*>(&Bs[k][tx*4]);
            float a_[8] = {af0.x, af0.y, af0.z, af0.w, af1.x, af1.y, af1.z, af1.w};
            float b_[4] = {bf.x, bf.y, bf.z, bf.w};
            #pragma unroll
            for (int i = 0; i < 8; i++)
                #pragma unroll
                for (int j = 0; j < 4; j++) acc[i][j] += a_[i] * b_[j];
        }
        __syncthreads();
    }

    const int nr0 = n0 + ty * 8;
    const int mc0 = m0 + tx * 4;
    #pragma unroll
    for (int i = 0; i < 8; i++) {
        int nn = nr0 + i;
        float nxi = nx[nn];
        float rr[4];
        #pragma unroll
        for (int j = 0; j < 4; j++) {
            int m = mc0 + j;
            float nyv = (m < 512) ? ny[m] : ny2[m - 512];
            float d2 = nxi + nyv - 2.f * acc[i][j];
            float a = -sqrtf(fmaxf(d2, 0.f));
            if (m >= 512 && (m - 512) == nn) a -= 1e6f;
            rr[j] = a;
        }
        *reinterpret_cast<float4*>(C + (size_t)nn * M + mc0) =
            make_float4(rr[0], rr[1], rr[2], rr[3]);
    }
}

// ---------------- NN GEMM with fused squared-sum: V = W @ Y, sum(V^2) ------
__global__ void __launch_bounds__(256)
vgemm_sq(const float* __restrict__ W, const float* __restrict__ P,
         const float* __restrict__ XF, float* __restrict__ part)
{
    const int K = 1024, M = XFD;
    __shared__ float As[BK][PAD_A];
    __shared__ float Bs[BK][PAD_B];
    __shared__ float shred[32];
    const int tid = threadIdx.x;
    const int tx = tid & 15, ty = tid >> 4;
    const int n0 = blockIdx.y * BM;
    const int m0 = blockIdx.x * BN;

    const int ar0 = tid >> 2;
    const int ac4 = (tid & 3) << 2;
    const float* aptr0 = W + (size_t)(n0 + ar0)      * K + ac4;
    const float* aptr1 = W + (size_t)(n0 + ar0 + 64) * K + ac4;
    const int brow = tid >> 4;
    const int bc4  = (tid & 15) << 2;

    float acc[8][4];
    #pragma unroll
    for (int i = 0; i < 8; i++)
        #pragma unroll
        for (int j = 0; j < 4; j++) acc[i][j] = 0.f;

    for (int k0 = 0; k0 < K; k0 += BK) {
        float4 a0 = *reinterpret_cast<const float4*>(aptr0 + k0);
        float4 a1 = *reinterpret_cast<const float4*>(aptr1 + k0);
        int krow = k0 + brow;
        const float* ysrc = (krow < 512) ? P + (size_t)krow * M
                                         : XF + (size_t)(krow - 512) * M;
        float4 b0 = *reinterpret_cast<const float4*>(ysrc + m0 + bc4);
        As[ac4+0][ar0]    = a0.x; As[ac4+1][ar0]    = a0.y; As[ac4+2][ar0]    = a0.z; As[ac4+3][ar0]    = a0.w;
        As[ac4+0][ar0+64] = a1.x; As[ac4+1][ar0+64] = a1.y; As[ac4+2][ar0+64] = a1.z; As[ac4+3][ar0+64] = a1.w;
        *reinterpret_cast<float4*>(&Bs[brow][bc4]) = b0;
        __syncthreads();
        #pragma unroll
        for (int k = 0; k < BK; k++) {
            float4 af0 = *reinterpret_cast<const float4*>(&As[k][ty*8]);
            float4 af1 = *reinterpret_cast<const float4*>(&As[k][ty*8+4]);
            float4 bf  = *reinterpret_cast<const float4*>(&Bs[k][tx*4]);
            float a_[8] = {af0.x, af0.y, af0.z, af0.w, af1.x, af1.y, af1.z, af1.w};
            float b_[4] = {bf.x, bf.y, bf.z, bf.w};
            #pragma unroll
            for (int i = 0; i < 8; i++)
                #pragma unroll
                for (int j = 0; j < 4; j++) acc[i][j] += a_[i] * b_[j];
        }
        __syncthreads();
    }

    float ss = 0.f;
    #pragma unroll
    for (int i = 0; i < 8; i++)
        #pragma unroll
        for (int j = 0; j < 4; j++) ss += acc[i][j] * acc[i][j];
    float tot = block_reduce_sum(ss, shred);
    if (tid == 0) part[blockIdx.y * gridDim.x + blockIdx.x] = tot;
}

// ---------------- LayerNorm (bf16 output feeds MMA) ------------------------
__global__ void __launch_bounds__(128)
ln_kernel(const float* __restrict__ x, const float* __restrict__ g,
          const float* __restrict__ b, __nv_bfloat16* __restrict__ out)
{
    int t = blockIdx.x;
    int tid = threadIdx.x;
    const float* xr = x + (size_t)t * DM;
    float4 v = *reinterpret_cast<const float4*>(xr + tid * 4);
    float s  = v.x + v.y + v.z + v.w;
    float sq = v.x*v.x + v.y*v.y + v.z*v.z + v.w*v.w;
    int lane = tid & 31, w = tid >> 5;
    #pragma unroll
    for (int off = 16; off; off >>= 1) {
        s  += __shfl_xor_sync(0xffffffffu, s,  off);
        sq += __shfl_xor_sync(0xffffffffu, sq, off);
    }
    __shared__ float shs[4], shq[4];
    if (lane == 0) { shs[w] = s; shq[w] = sq; }
    __syncthreads();
    s  = shs[0] + shs[1] + shs[2] + shs[3];
    sq = shq[0] + shq[1] + shq[2] + shq[3];
    float mean = s * (1.f / 512.f);
    float var  = sq * (1.f / 512.f) - mean * mean;
    float inv  = rsqrtf(var + 1e-5f);
    float4 gv = *reinterpret_cast<const float4*>(g + tid * 4);
    float4 bv = *reinterpret_cast<const float4*>(b + tid * 4);
    __nv_bfloat162 p0 = __floats2bfloat162_rn((v.x - mean) * inv * gv.x + bv.x,
                                              (v.y - mean) * inv * gv.y + bv.y);
    __nv_bfloat162 p1 = __floats2bfloat162_rn((v.z - mean) * inv * gv.z + bv.z,
                                              (v.w - mean) * inv * gv.w + bv.w);
    uint2 pk;
    pk.x = *reinterpret_cast<uint32_t*>(&p0);
    pk.y = *reinterpret_cast<uint32_t*>(&p1);
    *reinterpret_cast<uint2*>(out + (size_t)t * DM + tid * 4) = pk;
}

// ---------------- attention: one (batch, head) per block --------------------
__global__ void __launch_bounds__(256)
attn_kernel(const __nv_bfloat16* __restrict__ qkv, __nv_bfloat16* __restrict__ o)
{
    __shared__ float qs[32][68];
    __shared__ float kt[64][36];   // transposed: kt[d][j]
    __shared__ float vs[32][64];
    __shared__ float ps[32][33];
    int bh = blockIdx.x;
    int b = bh >> 3, h = bh & 7;
    int tid = threadIdx.x;
    size_t base = (size_t)(b * 32) * QKVD + h * 64;
    #pragma unroll
    for (int l = 0; l < 2; l++) {
        int idx = tid + l * 256;
        int i = idx >> 4;
        int c = (idx & 15) << 2;
        uint2 qv = *reinterpret_cast<const uint2*>(qkv + base + (size_t)i * QKVD + c);
        uint2 kv = *reinterpret_cast<const uint2*>(qkv + base + (size_t)i * QKVD + 512 + c);
        uint2 vv = *reinterpret_cast<const uint2*>(qkv + base + (size_t)i * QKVD + 1024 + c);
        float2 q01 = __bfloat1622float2(*reinterpret_cast<__nv_bfloat162*>(&qv.x));
        float2 q23 = __bfloat1622float2(*reinterpret_cast<__nv_bfloat162*>(&qv.y));
        float2 k01 = __bfloat1622float2(*reinterpret_cast<__nv_bfloat162*>(&kv.x));
        float2 k23 = __bfloat1622float2(*reinterpret_cast<__nv_bfloat162*>(&kv.y));
        float2 v01 = __bfloat1622float2(*reinterpret_cast<__nv_bfloat162*>(&vv.x));
        float2 v23 = __bfloat1622float2(*reinterpret_cast<__nv_bfloat162*>(&vv.y));
        qs[i][c] = q01.x; qs[i][c+1] = q01.y; qs[i][c+2] = q23.x; qs[i][c+3] = q23.y;
        kt[c][i] = k01.x; kt[c+1][i] = k01.y; kt[c+2][i] = k23.x; kt[c+3][i] = k23.y;
        vs[i][c] = v01.x; vs[i][c+1] = v01.y; vs[i][c+2] = v23.x; vs[i][c+3] = v23.y;
    }
    __syncthreads();
    {   // scores: thread (i, j0..j0+3)
        int i = tid >> 3;
        int j0 = (tid & 7) << 2;
        float s0 = 0.f, s1 = 0.f, s2 = 0.f, s3 = 0.f;
        #pragma unroll
        for (int d = 0; d < 64; d += 4) {
            float4 q  = *reinterpret_cast<const float4*>(&qs[i][d]);
            float4 k0 = *reinterpret_cast<const float4*>(&kt[d  ][j0]);
            float4 k1 = *reinterpret_cast<const float4*>(&kt[d+1][j0]);
            float4 k2 = *reinterpret_cast<const float4*>(&kt[d+2][j0]);
            float4 k3 = *reinterpret_cast<const float4*>(&kt[d+3][j0]);
            s0 += q.x*k0.x + q.y*k1.x + q.z*k2.x + q.w*k3.x;
            s1 += q.x*k0.y + q.y*k1.y + q.z*k2.y + q.w*k3.y;
            s2 += q.x*k0.z + q.y*k1.z + q.z*k2.z + q.w*k3.z;
            s3 += q.x*k0.w + q.y*k1.w + q.z*k2.w + q.w*k3.w;
        }
        ps[i][j0]   = s0 * 0.125f;
        ps[i][j0+1] = s1 * 0.125f;
        ps[i][j0+2] = s2 * 0.125f;
        ps[i][j0+3] = s3 * 0.125f;
    }
    __syncthreads();
    {   // softmax per row
        int w = tid >> 5, lane = tid & 31;
        #pragma unroll
        for (int r = 0; r < 4; r++) {
            int i = w + (r << 3);
            float v = ps[i][lane];
            float mx = v;
            #pragma unroll
            for (int off = 16; off; off >>= 1) mx = fmaxf(mx, __shfl_xor_sync(0xffffffffu, mx, off));
            float e = __expf(v - mx);
            float sm = e;
            #pragma unroll
            for (int off = 16; off; off >>= 1) sm += __shfl_xor_sync(0xffffffffu, sm, off);
            ps[i][lane] = e / sm;
        }
    }
    __syncthreads();
    {   // o = p @ v
        int i = tid >> 3;
        int d0 = (tid & 7) << 3;
        float4 a0 = make_float4(0.f,0.f,0.f,0.f);
        float4 a1 = make_float4(0.f,0.f,0.f,0.f);
        #pragma unroll
        for (int j = 0; j < 32; j++) {
            float pv = ps[i][j];
            float4 v0 = *reinterpret_cast<const float4*>(&vs[j][d0]);
            float4 v1 = *reinterpret_cast<const float4*>(&vs[j][d0+4]);
            a0.x += pv*v0.x; a0.y += pv*v0.y; a0.z += pv*v0.z; a0.w += pv*v0.w;
            a1.x += pv*v1.x; a1.y += pv*v1.y; a1.z += pv*v1.z; a1.w += pv*v1.w;
        }
        __nv_bfloat162 c0 = __floats2bfloat162_rn(a0.x, a0.y);
        __nv_bfloat162 c1 = __floats2bfloat162_rn(a0.z, a0.w);
        __nv_bfloat162 c2 = __floats2bfloat162_rn(a1.x, a1.y);
        __nv_bfloat162 c3 = __floats2bfloat162_rn(a1.z, a1.w);
        uint4 pk;
        pk.x = *reinterpret_cast<uint32_t*>(&c0);
        pk.y = *reinterpret_cast<uint32_t*>(&c1);
        pk.z = *reinterpret_cast<uint32_t*>(&c2);
        pk.w = *reinterpret_cast<uint32_t*>(&c3);
        *reinterpret_cast<uint4*>(o + (size_t)(b * 32 + i) * DM + h * 64 + d0) = pk;
    }
}

// ---------------- squared norms of xf rows and p rows -----------------------
__global__ void __launch_bounds__(256)
sqnorm_kernel(const float* __restrict__ xf, const float* __restrict__ p,
              float* __restrict__ nx, float* __restrict__ np)
{
    int r = blockIdx.x;
    const float* src = (r < 512) ? xf + (size_t)r * XFD : p + (size_t)(r - 512) * XFD;
    float s = 0.f;
    for (int c = threadIdx.x * 4; c < XFD; c += 256 * 4) {
        float4 v = *reinterpret_cast<const float4*>(src + c);
        s += v.x*v.x + v.y*v.y + v.z*v.z + v.w*v.w;
    }
    __shared__ float sh[32];
    float tot = block_reduce_sum(s, sh);
    if (threadIdx.x == 0) { if (r < 512) nx[r] = tot; else np[r - 512] = tot; }
}

// ---------------- row stats of A (max, sum of exp) ---------------------------
__global__ void __launch_bounds__(256)
rowstats_kernel(const float* __restrict__ A, float* __restrict__ rmax,
                float* __restrict__ rsum)
{
    int r = blockIdx.x;
    const float* ar = A + (size_t)r * 1024;
    float v[4];
    float mx = -1e30f;
    #pragma unroll
    for (int l = 0; l < 4; l++) { v[l] = ar[threadIdx.x + l * 256]; mx = fmaxf(mx, v[l]); }
    __shared__ float sh[32];
    mx = block_reduce_max(mx, sh);
    float s = 0.f;
    #pragma unroll
    for (int l = 0; l < 4; l++) s += __expf(v[l] - mx);
    s = block_reduce_sum(s, sh);
    if (threadIdx.x == 0) { rmax[r] = mx; rsum[r] = s; }
}

// ---------------- column stats of A ----------------------------------------
__global__ void __launch_bounds__(256)
colstats_kernel(const float* __restrict__ A, float* __restrict__ cmax,
                float* __restrict__ csum)
{
    int c = blockIdx.x * 256 + threadIdx.x;
    float mx = -1e30f;
    for (int i = 0; i < 512; i++) mx = fmaxf(mx, A[(size_t)i * 1024 + c]);
    float s = 0.f;
    for (int i = 0; i < 512; i++) s += __expf(A[(size_t)i * 1024 + c] - mx);
    cmax[c] = mx; csum[c] = s;
}

// ---------------- build W = [A_pos*sneg | -(A_neg*spos)] --------------------
__global__ void __launch_bounds__(256)
wbuild_kernel(const float* __restrict__ A, const float* __restrict__ rmax,
              const float* __restrict__ rsum, const float* __restrict__ cmax,
              const float* __restrict__ csum, float* __restrict__ W)
{
    int r = blockIdx.x;
    int j0 = threadIdx.x * 4;
    float rm = rmax[r];
    float rs = rsum[r];
    float4 a = *reinterpret_cast<const float4*>(A + (size_t)r * 1024 + j0);
    float av[4] = {a.x, a.y, a.z, a.w};
    float soft[4];
    float lsum = 0.f;
    #pragma unroll
    for (int l = 0; l < 4; l++) {
        int j = j0 + l;
        float s = __expf(av[l] - 0.5f * (rm + cmax[j])) * rsqrtf(rs * csum[j]);
        soft[l] = s;
        lsum += s;
    }
    bool isneg = (threadIdx.x >= 128);
    __shared__ float sh[32];
    float sp = block_reduce_sum(isneg ? 0.f : lsum, sh);
    float sn = block_reduce_sum(isneg ? lsum : 0.f, sh);
    float scale = isneg ? -(sp * sn) : sn;
    float4 o = make_float4(soft[0]*scale, soft[1]*scale, soft[2]*scale, soft[3]*scale);
    *reinterpret_cast<float4*>(W + (size_t)r * 1024 + j0) = o;
}

// ---------------- final reduce → mean(V^2) ----------------------------------
__global__ void __launch_bounds__(256)
finalize_kernel(const float* __restrict__ part, float* __restrict__ out)
{
    __shared__ float sh[32];
    float v = part[threadIdx.x];
    float tot = block_reduce_sum(v, sh);
    if (threadIdx.x == 0) out[0] = tot * (1.f / (512.f * 4096.f));
}

// ---------------- host launch ------------------------------------------------
extern "C" void kernel_launch(void* const* d_in, const int* in_sizes, int n_in,
                              void* d_out, int out_size)
{
    (void)in_sizes; (void)n_in; (void)out_size;
    const float* p     = (const float*)d_in[0];
    const float* eps   = (const float*)d_in[1];
    const float* in_w  = (const float*)d_in[2];
    const float* in_b  = (const float*)d_in[3];
    const float* Wqkv  = (const float*)d_in[4];
    const float* bqkv  = (const float*)d_in[5];
    const float* Wo    = (const float*)d_in[6];
    const float* bo    = (const float*)d_in[7];
    const float* ln1g  = (const float*)d_in[8];
    const float* ln1b  = (const float*)d_in[9];
    const float* W1    = (const float*)d_in[10];
    const float* b1    = (const float*)d_in[11];
    const float* W2    = (const float*)d_in[12];
    const float* b2    = (const float*)d_in[13];
    const float* ln2g  = (const float*)d_in[14];
    const float* ln2b  = (const float*)d_in[15];
    const float* out_w = (const float*)d_in[16];
    const float* out_b = (const float*)d_in[17];
    float* out = (float*)d_out;

    float *px, *pxf, *pA, *pW;
    float *pnx, *pnp, *prmax, *prsum, *pcmax, *pcsum, *ppart;
    __nv_bfloat16 *peps, *phb, *pattn, *pqkvb, *pffb, *pxb, *pwb;
    cudaGetSymbolAddress((void**)&px,    g_x);
    cudaGetSymbolAddress((void**)&pxf,   g_xf);
    cudaGetSymbolAddress((void**)&pA,    g_A);
    cudaGetSymbolAddress((void**)&pW,    g_W);
    cudaGetSymbolAddress((void**)&pnx,   g_nx);
    cudaGetSymbolAddress((void**)&pnp,   g_np);
    cudaGetSymbolAddress((void**)&prmax, g_rmax);
    cudaGetSymbolAddress((void**)&prsum, g_rsum);
    cudaGetSymbolAddress((void**)&pcmax, g_cmax);
    cudaGetSymbolAddress((void**)&pcsum, g_csum);
    cudaGetSymbolAddress((void**)&ppart, g_part);
    cudaGetSymbolAddress((void**)&peps,  b_eps);
    cudaGetSymbolAddress((void**)&phb,   b_h);
    cudaGetSymbolAddress((void**)&pattn, b_attn);
    cudaGetSymbolAddress((void**)&pqkvb, b_qkv);
    cudaGetSymbolAddress((void**)&pffb,  b_ff);
    cudaGetSymbolAddress((void**)&pxb,   b_x);
    cudaGetSymbolAddress((void**)&pwb,   b_wts);

    dim3 blk(256);
    auto rblocks = [](int n) { return (n / 4 + 255) / 256; };

    // convert weights + eps to bf16 (round-nearest)
    cvt_bf16_kernel<<<rblocks(DM*CHD),    blk>>>(in_w,  pwb + R_INW,  DM*CHD);
    cvt_bf16_kernel<<<rblocks(4*QKVD*DM), blk>>>(Wqkv,  pwb + R_QKV,  4*QKVD*DM);
    cvt_bf16_kernel<<<rblocks(4*DM*DM),   blk>>>(Wo,    pwb + R_WO,   4*DM*DM);
    cvt_bf16_kernel<<<rblocks(4*FFD*DM),  blk>>>(W1,    pwb + R_W1,   4*FFD*DM);
    cvt_bf16_kernel<<<rblocks(4*DM*FFD),  blk>>>(W2,    pwb + R_W2,   4*DM*FFD);
    cvt_bf16_kernel<<<rblocks(CHD*DM),    blk>>>(out_w, pwb + R_OUTW, CHD*DM);
    cvt_bf16_kernel<<<rblocks(NTOK*CHD),  blk>>>(eps,   peps,         NTOK*CHD);

    // x = eps @ in_w^T + in_b   (fp32 out)
    mma_gemm<0><<<dim3(DM/128, NTOK/128), blk>>>(peps, pwb + R_INW, in_b,
                                                 nullptr, px, nullptr, DM, CHD);
    for (int i = 0; i < 4; i++) {
        ln_kernel<<<NTOK, 128>>>(px, ln1g + i*DM, ln1b + i*DM, phb);
        mma_gemm<3><<<dim3(QKVD/128, NTOK/128), blk>>>(
            phb, pwb + R_QKV + (size_t)i*QKVD*DM, bqkv + (size_t)i*QKVD,
            nullptr, nullptr, pqkvb, QKVD, DM);
        attn_kernel<<<4096, 256>>>(pqkvb, pattn);
        mma_gemm<2><<<dim3(DM/128, NTOK/128), blk>>>(
            pattn, pwb + R_WO + (size_t)i*DM*DM, bo + (size_t)i*DM,
            px, px, nullptr, DM, DM);
        ln_kernel<<<NTOK, 128>>>(px, ln2g + i*DM, ln2b + i*DM, phb);
        mma_gemm<1><<<dim3(FFD/128, NTOK/128), blk>>>(
            phb, pwb + R_W1 + (size_t)i*FFD*DM, b1 + (size_t)i*FFD,
            nullptr, nullptr, pffb, FFD, DM);
        mma_gemm<2><<<dim3(DM/128, NTOK/128), blk>>>(
            pffb, pwb + R_W2 + (size_t)i*DM*FFD, b2 + (size_t)i*DM,
            px, px, nullptr, DM, FFD);
    }
    // xf = x @ out_w^T + out_b
    cvt_bf16_kernel<<<rblocks(NTOK*DM), blk>>>(px, pxb, NTOK*DM);
    mma_gemm<0><<<dim3(CHD/128, NTOK/128), blk>>>(pxb, pwb + R_OUTW, out_b,
                                                  nullptr, pxf, nullptr, CHD, DM);

    // compute_V (exact fp32 path)
    sqnorm_kernel<<<1024, 256>>>(pxf, p, pnx, pnp);
    gemm_cdist<<<dim3(1024/BN, NB/BM), blk>>>(pxf, p, pA, NB, 1024, XFD,
                                              pxf, pnx, pnp, pnx);
    rowstats_kernel<<<NB, 256>>>(pA, prmax, prsum);
    colstats_kernel<<<4, 256>>>(pA, pcmax, pcsum);
    wbuild_kernel<<<NB, 256>>>(pA, prmax, prsum, pcmax, pcsum, pW);
    vgemm_sq<<<dim3(XFD/BN, NB/BM), blk>>>(pW, p, pxf, ppart);
    finalize_kernel<<<1, 256>>>(ppart, out);
}

// round 16
// speedup vs baseline: 3.8928x; 1.0200x over previous
#include <cuda_runtime.h>
#include <cuda_bf16.h>
#include <cstdint>

#define NTOK 16384
#define DM   512
#define FFD  2048
#define QKVD 1536
#define CHD  128
#define XFD  4096
#define NB   512

// ---------------- scratch (device globals; no cudaMalloc allowed) ----------
__device__ float g_x   [NTOK*DM];      // fp32 residual stream
__device__ float g_xf  [NTOK*CHD];     // == (512, 4096) row-major
__device__ float g_A   [NB*1024];
__device__ float g_W   [NB*1024];
__device__ float g_nx  [NB];
__device__ float g_np  [NB];
__device__ float g_rmax[NB];
__device__ float g_rsum[NB];
__device__ float g_cmax[1024];
__device__ float g_csum[1024];
__device__ float g_part[256];
// bf16 activation buffers
__device__ __nv_bfloat16 b_eps [NTOK*CHD];
__device__ __nv_bfloat16 b_h   [NTOK*DM];
__device__ __nv_bfloat16 b_attn[NTOK*DM];
__device__ __nv_bfloat16 b_qkv [NTOK*QKVD];
__device__ __nv_bfloat16 b_ff  [NTOK*FFD];
__device__ __nv_bfloat16 b_x   [NTOK*DM];
// bf16 weights: in_w | Wqkv | Wo | W1 | W2 | out_w
#define R_INW  0
#define R_QKV  65536
#define R_WO   (R_QKV + 4*QKVD*DM)
#define R_W1   (R_WO  + 4*DM*DM)
#define R_W2   (R_W1  + 4*FFD*DM)
#define R_OUTW (R_W2  + 4*DM*FFD)
#define R_TOT  (R_OUTW + CHD*DM)
__device__ __nv_bfloat16 b_wts[R_TOT];

// ---------------- fp32 -> bf16 conversion ----------------------------------
__global__ void __launch_bounds__(256)
cvt_bf16_kernel(const float* __restrict__ src, __nv_bfloat16* __restrict__ dst, int n)
{
    int i = (blockIdx.x * 256 + threadIdx.x) * 4;
    if (i < n) {
        float4 v = *reinterpret_cast<const float4*>(src + i);
        __nv_bfloat162 p0 = __floats2bfloat162_rn(v.x, v.y);
        __nv_bfloat162 p1 = __floats2bfloat162_rn(v.z, v.w);
        uint2 pk;
        pk.x = *reinterpret_cast<uint32_t*>(&p0);
        pk.y = *reinterpret_cast<uint32_t*>(&p1);
        *reinterpret_cast<uint2*>(dst + i) = pk;
    }
}

__device__ __forceinline__ uint32_t smem_u32(const void* p) {
    uint32_t a;
    asm("{ .reg .u64 t; cvta.to.shared.u64 t, %1; cvt.u32.u64 %0, t; }" : "=r"(a) : "l"(p));
    return a;
}

#define MMA_BF16(c, a, b)                                                     \
    asm volatile("mma.sync.aligned.m16n8k16.row.col.f32.bf16.bf16.f32 "       \
        "{%0,%1,%2,%3}, {%4,%5,%6,%7}, {%8,%9}, {%0,%1,%2,%3};"               \
        : "+f"((c)[0]), "+f"((c)[1]), "+f"((c)[2]), "+f"((c)[3])              \
        : "r"((a)[0]), "r"((a)[1]), "r"((a)[2]), "r"((a)[3]),                 \
          "r"((b)[0]), "r"((b)[1]))

#define LDSM_X4(r0, r1, r2, r3, addr)                                         \
    asm volatile("ldmatrix.sync.aligned.m8n8.x4.shared.b16 {%0,%1,%2,%3}, [%4];" \
        : "=r"(r0), "=r"(r1), "=r"(r2), "=r"(r3) : "r"(addr))

// ---------------- bf16 mma.sync GEMM: C = A(NxK) @ Bw(MxK)^T ---------------
// block tile 128 (tokens) x 128 (features) x 32, 8 warps, warp tile 64x32
// 3-stage cp.async ring, 1 __syncthreads per k-tile, all LDSM before all MMA
// EPI 0: +bias->f32 | 1: relu(+bias)->bf16 | 2: +bias+resid->f32
// EPI 3: +bias->bf16 | 4: +bias+resid-> f32 AND bf16
#define TRB 40               // bf16 per smem row (32 data + 8 pad), 80 bytes
#define TILEB (128*TRB)
#define STAGES 3
#define MM_SMEM (STAGES*2*TILEB*2)   // 61440 bytes

template<int EPI>
__global__ void __launch_bounds__(256)
mma_gemm(const __nv_bfloat16* __restrict__ A, const __nv_bfloat16* __restrict__ Bw,
         const float* __restrict__ bias, const float* resid,
         float* __restrict__ Cf, __nv_bfloat16* __restrict__ Cb, int M, int K)
{
    extern __shared__ __nv_bfloat16 smd[];   // [STAGES][A|B][TILEB]

    const int tid  = threadIdx.x;
    const int w    = tid >> 5;
    const int lane = tid & 31;
    const int g    = lane >> 2;
    const int tig  = lane & 3;
    const int wm   = (w & 1) * 64;
    const int wn   = (w >> 1) * 32;
    const int n0   = blockIdx.y * 128;
    const int m0   = blockIdx.x * 128;

    // cp.async geometry: each k-tile row = 32 bf16 = 64B = 4 x 16B chunks
    const int rb = tid >> 2;          // 0..63
    const int cc = (tid & 3) * 8;     // bf16 col of chunk

    const uint32_t smBase = smem_u32(smd);
    // ldmatrix per-lane offsets (bytes, relative to stage base)
    const uint32_t aOff0 =
        (uint32_t)((wm + (lane & 15)) * TRB) * 2u + (uint32_t)(lane >> 4) * 16u;
    const int bg = lane >> 3;
    const uint32_t bOff0 = (uint32_t)(TILEB * 2) +
        (uint32_t)((wn + ((bg >> 1) << 3) + (lane & 7)) * TRB) * 2u +
        (uint32_t)(bg & 1) * 16u;

    float acc[4][4][4];
    #pragma unroll
    for (int mt = 0; mt < 4; mt++)
        #pragma unroll
        for (int nt = 0; nt < 4; nt++)
            #pragma unroll
            for (int r = 0; r < 4; r++) acc[mt][nt][r] = 0.f;

    auto preload = [&](int kt, int s) {
        __nv_bfloat16* sa = smd + s * 2 * TILEB;
        __nv_bfloat16* sb = sa + TILEB;
        const __nv_bfloat16* gA = A  + (size_t)(n0 + rb) * K + kt * 32 + cc;
        const __nv_bfloat16* gB = Bw + (size_t)(m0 + rb) * K + kt * 32 + cc;
        #pragma unroll
        for (int i = 0; i < 2; i++) {
            uint32_t da = smem_u32(sa + (rb + i*64) * TRB + cc);
            uint32_t db = smem_u32(sb + (rb + i*64) * TRB + cc);
            asm volatile("cp.async.cg.shared.global [%0], [%1], 16;"
                         :: "r"(da), "l"(gA + (size_t)i * 64 * K));
            asm volatile("cp.async.cg.shared.global [%0], [%1], 16;"
                         :: "r"(db), "l"(gB + (size_t)i * 64 * K));
        }
        asm volatile("cp.async.commit_group;" ::: "memory");
    };

    const int KT = K >> 5;
    #pragma unroll
    for (int s = 0; s < STAGES - 1; s++) preload(s, s);

    for (int kt = 0; kt < KT; kt++) {
        const int s = kt % STAGES;
        asm volatile("cp.async.wait_group %0;" :: "n"(STAGES - 2));
        __syncthreads();
        {
            int pk = kt + STAGES - 1;
            if (pk < KT) preload(pk, pk % STAGES);
            else asm volatile("cp.async.commit_group;" ::: "memory");
        }

        const uint32_t sbase = smBase + (uint32_t)s * (uint32_t)(2 * TILEB * 2);
        uint32_t af[2][4][4], bfr[2][4][2];
        #pragma unroll
        for (int ks = 0; ks < 2; ks++) {
            #pragma unroll
            for (int mt = 0; mt < 4; mt++)
                LDSM_X4(af[ks][mt][0], af[ks][mt][1], af[ks][mt][2], af[ks][mt][3],
                        sbase + aOff0 + (uint32_t)(mt * 16 * TRB * 2) + (uint32_t)(ks * 32));
            #pragma unroll
            for (int pp = 0; pp < 2; pp++)
                LDSM_X4(bfr[ks][2*pp][0], bfr[ks][2*pp][1],
                        bfr[ks][2*pp+1][0], bfr[ks][2*pp+1][1],
                        sbase + bOff0 + (uint32_t)(pp * 16 * TRB * 2) + (uint32_t)(ks * 32));
        }
        #pragma unroll
        for (int ks = 0; ks < 2; ks++)
            #pragma unroll
            for (int mt = 0; mt < 4; mt++)
                #pragma unroll
                for (int nt = 0; nt < 4; nt++)
                    MMA_BF16(acc[mt][nt], af[ks][mt], bfr[ks][nt]);
    }

    // epilogue
    #pragma unroll
    for (int mt = 0; mt < 4; mt++) {
        const int r0 = n0 + wm + mt * 16 + g;
        #pragma unroll
        for (int nt = 0; nt < 4; nt++) {
            const int c = m0 + wn + nt * 8 + 2 * tig;
            const float2 bv = *reinterpret_cast<const float2*>(bias + c);
            float v00 = acc[mt][nt][0] + bv.x;
            float v01 = acc[mt][nt][1] + bv.y;
            float v10 = acc[mt][nt][2] + bv.x;
            float v11 = acc[mt][nt][3] + bv.y;
            if (EPI == 1) {
                v00 = fmaxf(v00, 0.f); v01 = fmaxf(v01, 0.f);
                v10 = fmaxf(v10, 0.f); v11 = fmaxf(v11, 0.f);
            }
            if (EPI == 2 || EPI == 4) {
                float2 q0 = *reinterpret_cast<const float2*>(resid + (size_t)r0 * M + c);
                float2 q1 = *reinterpret_cast<const float2*>(resid + (size_t)(r0 + 8) * M + c);
                v00 += q0.x; v01 += q0.y; v10 += q1.x; v11 += q1.y;
            }
            if (EPI == 1 || EPI == 3 || EPI == 4) {
                __nv_bfloat162 z0 = __floats2bfloat162_rn(v00, v01);
                __nv_bfloat162 z1 = __floats2bfloat162_rn(v10, v11);
                *reinterpret_cast<__nv_bfloat162*>(Cb + (size_t)r0 * M + c)       = z0;
                *reinterpret_cast<__nv_bfloat162*>(Cb + (size_t)(r0 + 8) * M + c) = z1;
            }
            if (EPI == 0 || EPI == 2 || EPI == 4) {
                *reinterpret_cast<float2*>(Cf + (size_t)r0 * M + c)       = make_float2(v00, v01);
                *reinterpret_cast<float2*>(Cf + (size_t)(r0 + 8) * M + c) = make_float2(v10, v11);
            }
        }
    }
}

// ---------------- block reductions ----------------------------------------
__device__ __forceinline__ float block_reduce_sum(float v, float* sh) {
    int lane = threadIdx.x & 31, w = threadIdx.x >> 5;
    #pragma unroll
    for (int off = 16; off; off >>= 1) v += __shfl_xor_sync(0xffffffffu, v, off);
    if (lane == 0) sh[w] = v;
    __syncthreads();
    int nw = blockDim.x >> 5;
    if (w == 0) {
        float r = (lane < nw) ? sh[lane] : 0.f;
        #pragma unroll
        for (int off = 4; off; off >>= 1) r += __shfl_xor_sync(0xffffffffu, r, off);
        if (lane == 0) sh[0] = r;
    }
    __syncthreads();
    float res = sh[0];
    __syncthreads();
    return res;
}

__device__ __forceinline__ float block_reduce_max(float v, float* sh) {
    int lane = threadIdx.x & 31, w = threadIdx.x >> 5;
    #pragma unroll
    for (int off = 16; off; off >>= 1) v = fmaxf(v, __shfl_xor_sync(0xffffffffu, v, off));
    if (lane == 0) sh[w] = v;
    __syncthreads();
    int nw = blockDim.x >> 5;
    if (w == 0) {
        float r = (lane < nw) ? sh[lane] : -1e30f;
        #pragma unroll
        for (int off = 4; off; off >>= 1) r = fmaxf(r, __shfl_xor_sync(0xffffffffu, r, off));
        if (lane == 0) sh[0] = r;
    }
    __syncthreads();
    float res = sh[0];
    __syncthreads();
    return res;
}

// ---------------- fp32 SIMT GEMM for the cdist epilogue ---------------------
#define BM 128
#define BN 64
#define BK 16
#define PAD_A (BM+4)
#define PAD_B (BN+4)

__global__ void __launch_bounds__(256)
gemm_cdist(const float* __restrict__ A, const float* __restrict__ Bw,
           float* C, int N, int M, int K,
           const float* __restrict__ B2,
           const float* __restrict__ nx, const float* __restrict__ ny,
           const float* __restrict__ ny2)
{
    __shared__ float As[BK][PAD_A];
    __shared__ float Bs[BK][PAD_B];
    const int tid = threadIdx.x;
    const int tx = tid & 15, ty = tid >> 4;
    const int n0 = blockIdx.y * BM;
    const int m0 = blockIdx.x * BN;

    const int ar0 = tid >> 2;
    const int ac4 = (tid & 3) << 2;
    const float* aptr0 = A + (size_t)(n0 + ar0)      * K + ac4;
    const float* aptr1 = A + (size_t)(n0 + ar0 + 64) * K + ac4;

    const int brow = tid >> 2;
    const int bc4  = (tid & 3) << 2;
    const int m_ld = m0 + brow;
    const float* bptr = (m_ld >= 512) ? B2 + (size_t)(m_ld - 512) * K + bc4
                                      : Bw + (size_t)m_ld * K + bc4;

    float acc[8][4];
    #pragma unroll
    for (int i = 0; i < 8; i++)
        #pragma unroll
        for (int j = 0; j < 4; j++) acc[i][j] = 0.f;

    for (int k0 = 0; k0 < K; k0 += BK) {
        float4 a0 = *reinterpret_cast<const float4*>(aptr0 + k0);
        float4 a1 = *reinterpret_cast<const float4*>(aptr1 + k0);
        float4 b0 = *reinterpret_cast<const float4*>(bptr + k0);
        As[ac4+0][ar0]    = a0.x; As[ac4+1][ar0]    = a0.y; As[ac4+2][ar0]    = a0.z; As[ac4+3][ar0]    = a0.w;
        As[ac4+0][ar0+64] = a1.x; As[ac4+1][ar0+64] = a1.y; As[ac4+2][ar0+64] = a1.z; As[ac4+3][ar0+64] = a1.w;
        Bs[bc4+0][brow] = b0.x; Bs[bc4+1][brow] = b0.y; Bs[bc4+2][brow] = b0.z; Bs[bc4+3][brow] = b0.w;
        __syncthreads();
        #pragma unroll
        for (int k = 0; k < BK; k++) {
            float4 af0 = *reinterpret_cast<const float4*>(&As[k][ty*8]);
            float4 af1 = *reinterpret_cast<const float4*>(&As[k][ty*8+4]);
            float4 bf  = *reinterpret_cast<const float4*>(&Bs[k][tx*4]);
            float a_[8] = {af0.x, af0.y, af0.z, af0.w, af1.x, af1.y, af1.z, af1.w};
            float b_[4] = {bf.x, bf.y, bf.z, bf.w};
            #pragma unroll
            for (int i = 0; i < 8; i++)
                #pragma unroll
                for (int j = 0; j < 4; j++) acc[i][j] += a_[i] * b_[j];
        }
        __syncthreads();
    }

    const int nr0 = n0 + ty * 8;
    const int mc0 = m0 + tx * 4;
    #pragma unroll
    for (int i = 0; i < 8; i++) {
        int nn = nr0 + i;
        float nxi = nx[nn];
        float rr[4];
        #pragma unroll
        for (int j = 0; j < 4; j++) {
            int m = mc0 + j;
            float nyv = (m < 512) ? ny[m] : ny2[m - 512];
            float d2 = nxi + nyv - 2.f * acc[i][j];
            float a = -sqrtf(fmaxf(d2, 0.f));
            if (m >= 512 && (m - 512) == nn) a -= 1e6f;
            rr[j] = a;
        }
        *reinterpret_cast<float4*>(C + (size_t)nn * M + mc0) =
            make_float4(rr[0], rr[1], rr[2], rr[3]);
    }
}

// ---------------- NN GEMM with fused squared-sum: V = W @ Y, sum(V^2) ------
__global__ void __launch_bounds__(256)
vgemm_sq(const float* __restrict__ W, const float* __restrict__ P,
         const float* __restrict__ XF, float* __restrict__ part)
{
    const int K = 1024, M = XFD;
    __shared__ float As[BK][PAD_A];
    __shared__ float Bs[BK][PAD_B];
    __shared__ float shred[32];
    const int tid = threadIdx.x;
    const int tx = tid & 15, ty = tid >> 4;
    const int n0 = blockIdx.y * BM;
    const int m0 = blockIdx.x * BN;

    const int ar0 = tid >> 2;
    const int ac4 = (tid & 3) << 2;
    const float* aptr0 = W + (size_t)(n0 + ar0)      * K + ac4;
    const float* aptr1 = W + (size_t)(n0 + ar0 + 64) * K + ac4;
    const int brow = tid >> 4;
    const int bc4  = (tid & 15) << 2;

    float acc[8][4];
    #pragma unroll
    for (int i = 0; i < 8; i++)
        #pragma unroll
        for (int j = 0; j < 4; j++) acc[i][j] = 0.f;

    for (int k0 = 0; k0 < K; k0 += BK) {
        float4 a0 = *reinterpret_cast<const float4*>(aptr0 + k0);
        float4 a1 = *reinterpret_cast<const float4*>(aptr1 + k0);
        int krow = k0 + brow;
        const float* ysrc = (krow < 512) ? P + (size_t)krow * M
                                         : XF + (size_t)(krow - 512) * M;
        float4 b0 = *reinterpret_cast<const float4*>(ysrc + m0 + bc4);
        As[ac4+0][ar0]    = a0.x; As[ac4+1][ar0]    = a0.y; As[ac4+2][ar0]    = a0.z; As[ac4+3][ar0]    = a0.w;
        As[ac4+0][ar0+64] = a1.x; As[ac4+1][ar0+64] = a1.y; As[ac4+2][ar0+64] = a1.z; As[ac4+3][ar0+64] = a1.w;
        *reinterpret_cast<float4*>(&Bs[brow][bc4]) = b0;
        __syncthreads();
        #pragma unroll
        for (int k = 0; k < BK; k++) {
            float4 af0 = *reinterpret_cast<const float4*>(&As[k][ty*8]);
            float4 af1 = *reinterpret_cast<const float4*>(&As[k][ty*8+4]);
            float4 bf  = *reinterpret_cast<const float4*>(&Bs[k][tx*4]);
            float a_[8] = {af0.x, af0.y, af0.z, af0.w, af1.x, af1.y, af1.z, af1.w};
            float b_[4] = {bf.x, bf.y, bf.z, bf.w};
            #pragma unroll
            for (int i = 0; i < 8; i++)
                #pragma unroll
                for (int j = 0; j < 4; j++) acc[i][j] += a_[i] * b_[j];
        }
        __syncthreads();
    }

    float ss = 0.f;
    #pragma unroll
    for (int i = 0; i < 8; i++)
        #pragma unroll
        for (int j = 0; j < 4; j++) ss += acc[i][j] * acc[i][j];
    float tot = block_reduce_sum(ss, shred);
    if (tid == 0) part[blockIdx.y * gridDim.x + blockIdx.x] = tot;
}

// ---------------- LayerNorm (bf16 output feeds MMA) ------------------------
__global__ void __launch_bounds__(128)
ln_kernel(const float* __restrict__ x, const float* __restrict__ g,
          const float* __restrict__ b, __nv_bfloat16* __restrict__ out)
{
    int t = blockIdx.x;
    int tid = threadIdx.x;
    const float* xr = x + (size_t)t * DM;
    float4 v = *reinterpret_cast<const float4*>(xr + tid * 4);
    float s  = v.x + v.y + v.z + v.w;
    float sq = v.x*v.x + v.y*v.y + v.z*v.z + v.w*v.w;
    int lane = tid & 31, w = tid >> 5;
    #pragma unroll
    for (int off = 16; off; off >>= 1) {
        s  += __shfl_xor_sync(0xffffffffu, s,  off);
        sq += __shfl_xor_sync(0xffffffffu, sq, off);
    }
    __shared__ float shs[4], shq[4];
    if (lane == 0) { shs[w] = s; shq[w] = sq; }
    __syncthreads();
    s  = shs[0] + shs[1] + shs[2] + shs[3];
    sq = shq[0] + shq[1] + shq[2] + shq[3];
    float mean = s * (1.f / 512.f);
    float var  = sq * (1.f / 512.f) - mean * mean;
    float inv  = rsqrtf(var + 1e-5f);
    float4 gv = *reinterpret_cast<const float4*>(g + tid * 4);
    float4 bv = *reinterpret_cast<const float4*>(b + tid * 4);
    __nv_bfloat162 p0 = __floats2bfloat162_rn((v.x - mean) * inv * gv.x + bv.x,
                                              (v.y - mean) * inv * gv.y + bv.y);
    __nv_bfloat162 p1 = __floats2bfloat162_rn((v.z - mean) * inv * gv.z + bv.z,
                                              (v.w - mean) * inv * gv.w + bv.w);
    uint2 pk;
    pk.x = *reinterpret_cast<uint32_t*>(&p0);
    pk.y = *reinterpret_cast<uint32_t*>(&p1);
    *reinterpret_cast<uint2*>(out + (size_t)t * DM + tid * 4) = pk;
}

// ---------------- attention: one (batch, head) per block --------------------
__global__ void __launch_bounds__(256)
attn_kernel(const __nv_bfloat16* __restrict__ qkv, __nv_bfloat16* __restrict__ o)
{
    __shared__ float qs[32][68];
    __shared__ float kt[64][36];   // transposed: kt[d][j]
    __shared__ float vs[32][64];
    __shared__ float ps[32][33];
    int bh = blockIdx.x;
    int b = bh >> 3, h = bh & 7;
    int tid = threadIdx.x;
    size_t base = (size_t)(b * 32) * QKVD + h * 64;
    #pragma unroll
    for (int l = 0; l < 2; l++) {
        int idx = tid + l * 256;
        int i = idx >> 4;
        int c = (idx & 15) << 2;
        uint2 qv = *reinterpret_cast<const uint2*>(qkv + base + (size_t)i * QKVD + c);
        uint2 kv = *reinterpret_cast<const uint2*>(qkv + base + (size_t)i * QKVD + 512 + c);
        uint2 vv = *reinterpret_cast<const uint2*>(qkv + base + (size_t)i * QKVD + 1024 + c);
        float2 q01 = __bfloat1622float2(*reinterpret_cast<__nv_bfloat162*>(&qv.x));
        float2 q23 = __bfloat1622float2(*reinterpret_cast<__nv_bfloat162*>(&qv.y));
        float2 k01 = __bfloat1622float2(*reinterpret_cast<__nv_bfloat162*>(&kv.x));
        float2 k23 = __bfloat1622float2(*reinterpret_cast<__nv_bfloat162*>(&kv.y));
        float2 v01 = __bfloat1622float2(*reinterpret_cast<__nv_bfloat162*>(&vv.x));
        float2 v23 = __bfloat1622float2(*reinterpret_cast<__nv_bfloat162*>(&vv.y));
        qs[i][c] = q01.x; qs[i][c+1] = q01.y; qs[i][c+2] = q23.x; qs[i][c+3] = q23.y;
        kt[c][i] = k01.x; kt[c+1][i] = k01.y; kt[c+2][i] = k23.x; kt[c+3][i] = k23.y;
        vs[i][c] = v01.x; vs[i][c+1] = v01.y; vs[i][c+2] = v23.x; vs[i][c+3] = v23.y;
    }
    __syncthreads();
    {   // scores: thread (i, j0..j0+3)
        int i = tid >> 3;
        int j0 = (tid & 7) << 2;
        float s0 = 0.f, s1 = 0.f, s2 = 0.f, s3 = 0.f;
        #pragma unroll
        for (int d = 0; d < 64; d += 4) {
            float4 q  = *reinterpret_cast<const float4*>(&qs[i][d]);
            float4 k0 = *reinterpret_cast<const float4*>(&kt[d  ][j0]);
            float4 k1 = *reinterpret_cast<const float4*>(&kt[d+1][j0]);
            float4 k2 = *reinterpret_cast<const float4*>(&kt[d+2][j0]);
            float4 k3 = *reinterpret_cast<const float4*>(&kt[d+3][j0]);
            s0 += q.x*k0.x + q.y*k1.x + q.z*k2.x + q.w*k3.x;
            s1 += q.x*k0.y + q.y*k1.y + q.z*k2.y + q.w*k3.y;
            s2 += q.x*k0.z + q.y*k1.z + q.z*k2.z + q.w*k3.z;
            s3 += q.x*k0.w + q.y*k1.w + q.z*k2.w + q.w*k3.w;
        }
        ps[i][j0]   = s0 * 0.125f;
        ps[i][j0+1] = s1 * 0.125f;
        ps[i][j0+2] = s2 * 0.125f;
        ps[i][j0+3] = s3 * 0.125f;
    }
    __syncthreads();
    {   // softmax per row
        int w = tid >> 5, lane = tid & 31;
        #pragma unroll
        for (int r = 0; r < 4; r++) {
            int i = w + (r << 3);
            float v = ps[i][lane];
            float mx = v;
            #pragma unroll
            for (int off = 16; off; off >>= 1) mx = fmaxf(mx, __shfl_xor_sync(0xffffffffu, mx, off));
            float e = __expf(v - mx);
            float sm = e;
            #pragma unroll
            for (int off = 16; off; off >>= 1) sm += __shfl_xor_sync(0xffffffffu, sm, off);
            ps[i][lane] = e / sm;
        }
    }
    __syncthreads();
    {   // o = p @ v
        int i = tid >> 3;
        int d0 = (tid & 7) << 3;
        float4 a0 = make_float4(0.f,0.f,0.f,0.f);
        float4 a1 = make_float4(0.f,0.f,0.f,0.f);
        #pragma unroll
        for (int j = 0; j < 32; j++) {
            float pv = ps[i][j];
            float4 v0 = *reinterpret_cast<const float4*>(&vs[j][d0]);
            float4 v1 = *reinterpret_cast<const float4*>(&vs[j][d0+4]);
            a0.x += pv*v0.x; a0.y += pv*v0.y; a0.z += pv*v0.z; a0.w += pv*v0.w;
            a1.x += pv*v1.x; a1.y += pv*v1.y; a1.z += pv*v1.z; a1.w += pv*v1.w;
        }
        __nv_bfloat162 c0 = __floats2bfloat162_rn(a0.x, a0.y);
        __nv_bfloat162 c1 = __floats2bfloat162_rn(a0.z, a0.w);
        __nv_bfloat162 c2 = __floats2bfloat162_rn(a1.x, a1.y);
        __nv_bfloat162 c3 = __floats2bfloat162_rn(a1.z, a1.w);
        uint4 pk;
        pk.x = *reinterpret_cast<uint32_t*>(&c0);
        pk.y = *reinterpret_cast<uint32_t*>(&c1);
        pk.z = *reinterpret_cast<uint32_t*>(&c2);
        pk.w = *reinterpret_cast<uint32_t*>(&c3);
        *reinterpret_cast<uint4*>(o + (size_t)(b * 32 + i) * DM + h * 64 + d0) = pk;
    }
}

// ---------------- squared norms of xf rows and p rows -----------------------
__global__ void __launch_bounds__(256)
sqnorm_kernel(const float* __restrict__ xf, const float* __restrict__ p,
              float* __restrict__ nx, float* __restrict__ np)
{
    int r = blockIdx.x;
    const float* src = (r < 512) ? xf + (size_t)r * XFD : p + (size_t)(r - 512) * XFD;
    float s = 0.f;
    for (int c = threadIdx.x * 4; c < XFD; c += 256 * 4) {
        float4 v = *reinterpret_cast<const float4*>(src + c);
        s += v.x*v.x + v.y*v.y + v.z*v.z + v.w*v.w;
    }
    __shared__ float sh[32];
    float tot = block_reduce_sum(s, sh);
    if (threadIdx.x == 0) { if (r < 512) nx[r] = tot; else np[r - 512] = tot; }
}

// ---------------- row stats of A (max, sum of exp) ---------------------------
__global__ void __launch_bounds__(256)
rowstats_kernel(const float* __restrict__ A, float* __restrict__ rmax,
                float* __restrict__ rsum)
{
    int r = blockIdx.x;
    const float* ar = A + (size_t)r * 1024;
    float v[4];
    float mx = -1e30f;
    #pragma unroll
    for (int l = 0; l < 4; l++) { v[l] = ar[threadIdx.x + l * 256]; mx = fmaxf(mx, v[l]); }
    __shared__ float sh[32];
    mx = block_reduce_max(mx, sh);
    float s = 0.f;
    #pragma unroll
    for (int l = 0; l < 4; l++) s += __expf(v[l] - mx);
    s = block_reduce_sum(s, sh);
    if (threadIdx.x == 0) { rmax[r] = mx; rsum[r] = s; }
}

// ---------------- column stats of A ----------------------------------------
__global__ void __launch_bounds__(256)
colstats_kernel(const float* __restrict__ A, float* __restrict__ cmax,
                float* __restrict__ csum)
{
    int c = blockIdx.x * 256 + threadIdx.x;
    float mx = -1e30f;
    for (int i = 0; i < 512; i++) mx = fmaxf(mx, A[(size_t)i * 1024 + c]);
    float s = 0.f;
    for (int i = 0; i < 512; i++) s += __expf(A[(size_t)i * 1024 + c] - mx);
    cmax[c] = mx; csum[c] = s;
}

// ---------------- build W = [A_pos*sneg | -(A_neg*spos)] --------------------
__global__ void __launch_bounds__(256)
wbuild_kernel(const float* __restrict__ A, const float* __restrict__ rmax,
              const float* __restrict__ rsum, const float* __restrict__ cmax,
              const float* __restrict__ csum, float* __restrict__ W)
{
    int r = blockIdx.x;
    int j0 = threadIdx.x * 4;
    float rm = rmax[r];
    float rs = rsum[r];
    float4 a = *reinterpret_cast<const float4*>(A + (size_t)r * 1024 + j0);
    float av[4] = {a.x, a.y, a.z, a.w};
    float soft[4];
    float lsum = 0.f;
    #pragma unroll
    for (int l = 0; l < 4; l++) {
        int j = j0 + l;
        float s = __expf(av[l] - 0.5f * (rm + cmax[j])) * rsqrtf(rs * csum[j]);
        soft[l] = s;
        lsum += s;
    }
    bool isneg = (threadIdx.x >= 128);
    __shared__ float sh[32];
    float sp = block_reduce_sum(isneg ? 0.f : lsum, sh);
    float sn = block_reduce_sum(isneg ? lsum : 0.f, sh);
    float scale = isneg ? -(sp * sn) : sn;
    float4 o = make_float4(soft[0]*scale, soft[1]*scale, soft[2]*scale, soft[3]*scale);
    *reinterpret_cast<float4*>(W + (size_t)r * 1024 + j0) = o;
}

// ---------------- final reduce → mean(V^2) ----------------------------------
__global__ void __launch_bounds__(256)
finalize_kernel(const float* __restrict__ part, float* __restrict__ out)
{
    __shared__ float sh[32];
    float v = part[threadIdx.x];
    float tot = block_reduce_sum(v, sh);
    if (threadIdx.x == 0) out[0] = tot * (1.f / (512.f * 4096.f));
}

// ---------------- host launch ------------------------------------------------
extern "C" void kernel_launch(void* const* d_in, const int* in_sizes, int n_in,
                              void* d_out, int out_size)
{
    (void)in_sizes; (void)n_in; (void)out_size;
    const float* p     = (const float*)d_in[0];
    const float* eps   = (const float*)d_in[1];
    const float* in_w  = (const float*)d_in[2];
    const float* in_b  = (const float*)d_in[3];
    const float* Wqkv  = (const float*)d_in[4];
    const float* bqkv  = (const float*)d_in[5];
    const float* Wo    = (const float*)d_in[6];
    const float* bo    = (const float*)d_in[7];
    const float* ln1g  = (const float*)d_in[8];
    const float* ln1b  = (const float*)d_in[9];
    const float* W1    = (const float*)d_in[10];
    const float* b1    = (const float*)d_in[11];
    const float* W2    = (const float*)d_in[12];
    const float* b2    = (const float*)d_in[13];
    const float* ln2g  = (const float*)d_in[14];
    const float* ln2b  = (const float*)d_in[15];
    const float* out_w = (const float*)d_in[16];
    const float* out_b = (const float*)d_in[17];
    float* out = (float*)d_out;

    float *px, *pxf, *pA, *pW;
    float *pnx, *pnp, *prmax, *prsum, *pcmax, *pcsum, *ppart;
    __nv_bfloat16 *peps, *phb, *pattn, *pqkvb, *pffb, *pxb, *pwb;
    cudaGetSymbolAddress((void**)&px,    g_x);
    cudaGetSymbolAddress((void**)&pxf,   g_xf);
    cudaGetSymbolAddress((void**)&pA,    g_A);
    cudaGetSymbolAddress((void**)&pW,    g_W);
    cudaGetSymbolAddress((void**)&pnx,   g_nx);
    cudaGetSymbolAddress((void**)&pnp,   g_np);
    cudaGetSymbolAddress((void**)&prmax, g_rmax);
    cudaGetSymbolAddress((void**)&prsum, g_rsum);
    cudaGetSymbolAddress((void**)&pcmax, g_cmax);
    cudaGetSymbolAddress((void**)&pcsum, g_csum);
    cudaGetSymbolAddress((void**)&ppart, g_part);
    cudaGetSymbolAddress((void**)&peps,  b_eps);
    cudaGetSymbolAddress((void**)&phb,   b_h);
    cudaGetSymbolAddress((void**)&pattn, b_attn);
    cudaGetSymbolAddress((void**)&pqkvb, b_qkv);
    cudaGetSymbolAddress((void**)&pffb,  b_ff);
    cudaGetSymbolAddress((void**)&pxb,   b_x);
    cudaGetSymbolAddress((void**)&pwb,   b_wts);

    cudaFuncSetAttribute(mma_gemm<0>, cudaFuncAttributeMaxDynamicSharedMemorySize, MM_SMEM);
    cudaFuncSetAttribute(mma_gemm<1>, cudaFuncAttributeMaxDynamicSharedMemorySize, MM_SMEM);
    cudaFuncSetAttribute(mma_gemm<2>, cudaFuncAttributeMaxDynamicSharedMemorySize, MM_SMEM);
    cudaFuncSetAttribute(mma_gemm<3>, cudaFuncAttributeMaxDynamicSharedMemorySize, MM_SMEM);
    cudaFuncSetAttribute(mma_gemm<4>, cudaFuncAttributeMaxDynamicSharedMemorySize, MM_SMEM);

    dim3 blk(256);
    auto rblocks = [](int n) { return (n / 4 + 255) / 256; };

    // convert weights + eps to bf16 (round-nearest)
    cvt_bf16_kernel<<<rblocks(DM*CHD),    blk>>>(in_w,  pwb + R_INW,  DM*CHD);
    cvt_bf16_kernel<<<rblocks(4*QKVD*DM), blk>>>(Wqkv,  pwb + R_QKV,  4*QKVD*DM);
    cvt_bf16_kernel<<<rblocks(4*DM*DM),   blk>>>(Wo,    pwb + R_WO,   4*DM*DM);
    cvt_bf16_kernel<<<rblocks(4*FFD*DM),  blk>>>(W1,    pwb + R_W1,   4*FFD*DM);
    cvt_bf16_kernel<<<rblocks(4*DM*FFD),  blk>>>(W2,    pwb + R_W2,   4*DM*FFD);
    cvt_bf16_kernel<<<rblocks(CHD*DM),    blk>>>(out_w, pwb + R_OUTW, CHD*DM);
    cvt_bf16_kernel<<<rblocks(NTOK*CHD),  blk>>>(eps,   peps,         NTOK*CHD);

    // x = eps @ in_w^T + in_b   (fp32 out)
    mma_gemm<0><<<dim3(DM/128, NTOK/128), blk, MM_SMEM>>>(peps, pwb + R_INW, in_b,
                                                          nullptr, px, nullptr, DM, CHD);
    for (int i = 0; i < 4; i++) {
        ln_kernel<<<NTOK, 128>>>(px, ln1g + i*DM, ln1b + i*DM, phb);
        mma_gemm<3><<<dim3(QKVD/128, NTOK/128), blk, MM_SMEM>>>(
            phb, pwb + R_QKV + (size_t)i*QKVD*DM, bqkv + (size_t)i*QKVD,
            nullptr, nullptr, pqkvb, QKVD, DM);
        attn_kernel<<<4096, 256>>>(pqkvb, pattn);
        mma_gemm<2><<<dim3(DM/128, NTOK/128), blk, MM_SMEM>>>(
            pattn, pwb + R_WO + (size_t)i*DM*DM, bo + (size_t)i*DM,
            px, px, nullptr, DM, DM);
        ln_kernel<<<NTOK, 128>>>(px, ln2g + i*DM, ln2b + i*DM, phb);
        mma_gemm<1><<<dim3(FFD/128, NTOK/128), blk, MM_SMEM>>>(
            phb, pwb + R_W1 + (size_t)i*FFD*DM, b1 + (size_t)i*FFD,
            nullptr, nullptr, pffb, FFD, DM);
        if (i < 3) {
            mma_gemm<2><<<dim3(DM/128, NTOK/128), blk, MM_SMEM>>>(
                pffb, pwb + R_W2 + (size_t)i*DM*FFD, b2 + (size_t)i*DM,
                px, px, nullptr, DM, FFD);
        } else {
            // last layer: write fp32 x AND bf16 copy (feeds out-proj MMA)
            mma_gemm<4><<<dim3(DM/128, NTOK/128), blk, MM_SMEM>>>(
                pffb, pwb + R_W2 + (size_t)i*DM*FFD, b2 + (size_t)i*DM,
                px, px, pxb, DM, FFD);
        }
    }
    // xf = x @ out_w^T + out_b
    mma_gemm<0><<<dim3(CHD/128, NTOK/128), blk, MM_SMEM>>>(pxb, pwb + R_OUTW, out_b,
                                                           nullptr, pxf, nullptr, CHD, DM);

    // compute_V (exact fp32 path)
    sqnorm_kernel<<<1024, 256>>>(pxf, p, pnx, pnp);
    gemm_cdist<<<dim3(1024/BN, NB/BM), blk>>>(pxf, p, pA, NB, 1024, XFD,
                                              pxf, pnx, pnp, pnx);
    rowstats_kernel<<<NB, 256>>>(pA, prmax, prsum);
    colstats_kernel<<<4, 256>>>(pA, pcmax, pcsum);
    wbuild_kernel<<<NB, 256>>>(pA, prmax, prsum, pcmax, pcsum, pW);
    vgemm_sq<<<dim3(XFD/BN, NB/BM), blk>>>(pW, p, pxf, ppart);
    finalize_kernel<<<1, 256>>>(ppart, out);
}

// round 17
// speedup vs baseline: 4.3838x; 1.1261x over previous
#include <cuda_runtime.h>
#include <cuda_bf16.h>
#include <cstdint>

#define NTOK 16384
#define DM   512
#define FFD  2048
#define QKVD 1536
#define CHD  128
#define XFD  4096
#define NB   512

// ---------------- scratch (device globals; no cudaMalloc allowed) ----------
__device__ float g_x   [NTOK*DM];      // fp32 residual stream
__device__ float g_xf  [NTOK*CHD];     // == (512, 4096) row-major
__device__ float g_A   [NB*1024];
__device__ float g_nx  [NB];
__device__ float g_np  [NB];
__device__ float g_rmax[NB];
__device__ float g_rsum[NB];
__device__ float g_cmax[1024];
__device__ float g_csum[1024];
__device__ float g_part[256];
// bf16 activation buffers
__device__ __nv_bfloat16 b_eps [NTOK*CHD];
__device__ __nv_bfloat16 b_h   [NTOK*DM];
__device__ __nv_bfloat16 b_attn[NTOK*DM];
__device__ __nv_bfloat16 b_qkv [NTOK*QKVD];
__device__ __nv_bfloat16 b_ff  [NTOK*FFD];
__device__ __nv_bfloat16 b_x   [NTOK*DM];
__device__ __nv_bfloat16 b_xfb [NB*XFD];     // xf in bf16
__device__ __nv_bfloat16 b_p   [NB*XFD];     // sample_p in bf16
__device__ __nv_bfloat16 b_yt  [XFD*1024];   // [p;xf]^T in bf16 (4096 x 1024)
__device__ __nv_bfloat16 b_w16 [NB*1024];    // W in bf16
// bf16 weights: in_w | Wqkv | Wo | W1 | W2 | out_w
#define R_INW  0
#define R_QKV  65536
#define R_WO   (R_QKV + 4*QKVD*DM)
#define R_W1   (R_WO  + 4*DM*DM)
#define R_W2   (R_W1  + 4*FFD*DM)
#define R_OUTW (R_W2  + 4*DM*FFD)
#define R_TOT  (R_OUTW + CHD*DM)
__device__ __nv_bfloat16 b_wts[R_TOT];

// ---------------- fp32 -> bf16 conversion ----------------------------------
__global__ void __launch_bounds__(256)
cvt_bf16_kernel(const float* __restrict__ src, __nv_bfloat16* __restrict__ dst, int n)
{
    int i = (blockIdx.x * 256 + threadIdx.x) * 4;
    if (i < n) {
        float4 v = *reinterpret_cast<const float4*>(src + i);
        __nv_bfloat162 p0 = __floats2bfloat162_rn(v.x, v.y);
        __nv_bfloat162 p1 = __floats2bfloat162_rn(v.z, v.w);
        uint2 pk;
        pk.x = *reinterpret_cast<uint32_t*>(&p0);
        pk.y = *reinterpret_cast<uint32_t*>(&p1);
        *reinterpret_cast<uint2*>(dst + i) = pk;
    }
}

__device__ __forceinline__ uint32_t smem_u32(const void* p) {
    uint32_t a;
    asm("{ .reg .u64 t; cvta.to.shared.u64 t, %1; cvt.u32.u64 %0, t; }" : "=r"(a) : "l"(p));
    return a;
}

#define MMA_BF16(c, a, b)                                                     \
    asm volatile("mma.sync.aligned.m16n8k16.row.col.f32.bf16.bf16.f32 "       \
        "{%0,%1,%2,%3}, {%4,%5,%6,%7}, {%8,%9}, {%0,%1,%2,%3};"               \
        : "+f"((c)[0]), "+f"((c)[1]), "+f"((c)[2]), "+f"((c)[3])              \
        : "r"((a)[0]), "r"((a)[1]), "r"((a)[2]), "r"((a)[3]),                 \
          "r"((b)[0]), "r"((b)[1]))

#define LDSM_X4(r0, r1, r2, r3, addr)                                         \
    asm volatile("ldmatrix.sync.aligned.m8n8.x4.shared.b16 {%0,%1,%2,%3}, [%4];" \
        : "=r"(r0), "=r"(r1), "=r"(r2), "=r"(r3) : "r"(addr))

// ---------------- shared mainloop helpers ----------------------------------
#define TRB 40               // bf16 per smem row (32 data + 8 pad), 80 bytes
#define TILEB (128*TRB)
#define STAGES 3
#define MM_SMEM (STAGES*2*TILEB*2)   // 61440 bytes

// Macro body: runs the 3-stage cp.async + ldmatrix + mma mainloop.
// Requires in scope: smd, tid, n0, m0, A, Bw, K, acc[4][4][4], and consts.
#define MMA_MAINLOOP()                                                         \
    const int w    = tid >> 5;                                                 \
    const int lane = tid & 31;                                                 \
    const int g    = lane >> 2;                                                \
    const int tig  = lane & 3;                                                 \
    const int wm   = (w & 1) * 64;                                             \
    const int wn   = (w >> 1) * 32;                                            \
    const int rb = tid >> 2;                                                   \
    const int cc = (tid & 3) * 8;                                              \
    const uint32_t smBase = smem_u32(smd);                                     \
    const uint32_t aOff0 =                                                     \
        (uint32_t)((wm + (lane & 15)) * TRB) * 2u + (uint32_t)(lane >> 4) * 16u;\
    const int bg = lane >> 3;                                                  \
    const uint32_t bOff0 = (uint32_t)(TILEB * 2) +                             \
        (uint32_t)((wn + ((bg >> 1) << 3) + (lane & 7)) * TRB) * 2u +          \
        (uint32_t)(bg & 1) * 16u;                                              \
    _Pragma("unroll")                                                          \
    for (int mt = 0; mt < 4; mt++)                                             \
        _Pragma("unroll")                                                      \
        for (int nt = 0; nt < 4; nt++)                                         \
            _Pragma("unroll")                                                  \
            for (int r = 0; r < 4; r++) acc[mt][nt][r] = 0.f;                  \
    auto preload = [&](int kt, int s) {                                        \
        __nv_bfloat16* sa = smd + s * 2 * TILEB;                               \
        __nv_bfloat16* sb = sa + TILEB;                                        \
        const __nv_bfloat16* gA = A  + (size_t)(n0 + rb) * K + kt * 32 + cc;   \
        const __nv_bfloat16* gB = Bw + (size_t)(m0 + rb) * K + kt * 32 + cc;   \
        _Pragma("unroll")                                                      \
        for (int i = 0; i < 2; i++) {                                          \
            uint32_t da = smem_u32(sa + (rb + i*64) * TRB + cc);               \
            uint32_t db = smem_u32(sb + (rb + i*64) * TRB + cc);               \
            asm volatile("cp.async.cg.shared.global [%0], [%1], 16;"           \
                         :: "r"(da), "l"(gA + (size_t)i * 64 * K));            \
            asm volatile("cp.async.cg.shared.global [%0], [%1], 16;"           \
                         :: "r"(db), "l"(gB + (size_t)i * 64 * K));            \
        }                                                                      \
        asm volatile("cp.async.commit_group;" ::: "memory");                   \
    };                                                                         \
    const int KT = K >> 5;                                                     \
    _Pragma("unroll")                                                          \
    for (int s = 0; s < STAGES - 1; s++) preload(s, s);                        \
    for (int kt = 0; kt < KT; kt++) {                                          \
        const int s = kt % STAGES;                                             \
        asm volatile("cp.async.wait_group %0;" :: "n"(STAGES - 2));            \
        __syncthreads();                                                       \
        {                                                                      \
            int pk = kt + STAGES - 1;                                          \
            if (pk < KT) preload(pk, pk % STAGES);                             \
            else asm volatile("cp.async.commit_group;" ::: "memory");          \
        }                                                                      \
        const uint32_t sbase = smBase + (uint32_t)s * (uint32_t)(2 * TILEB * 2);\
        uint32_t af[2][4][4], bfr[2][4][2];                                    \
        _Pragma("unroll")                                                      \
        for (int ks = 0; ks < 2; ks++) {                                       \
            _Pragma("unroll")                                                  \
            for (int mt = 0; mt < 4; mt++)                                     \
                LDSM_X4(af[ks][mt][0], af[ks][mt][1], af[ks][mt][2], af[ks][mt][3], \
                        sbase + aOff0 + (uint32_t)(mt * 16 * TRB * 2) + (uint32_t)(ks * 32)); \
            _Pragma("unroll")                                                  \
            for (int pp = 0; pp < 2; pp++)                                     \
                LDSM_X4(bfr[ks][2*pp][0], bfr[ks][2*pp][1],                    \
                        bfr[ks][2*pp+1][0], bfr[ks][2*pp+1][1],                \
                        sbase + bOff0 + (uint32_t)(pp * 16 * TRB * 2) + (uint32_t)(ks * 32)); \
        }                                                                      \
        _Pragma("unroll")                                                      \
        for (int ks = 0; ks < 2; ks++)                                         \
            _Pragma("unroll")                                                  \
            for (int mt = 0; mt < 4; mt++)                                     \
                _Pragma("unroll")                                              \
                for (int nt = 0; nt < 4; nt++)                                 \
                    MMA_BF16(acc[mt][nt], af[ks][mt], bfr[ks][nt]);            \
    }

// ---------------- bf16 mma.sync GEMM: C = A(NxK) @ Bw(MxK)^T ---------------
// EPI 0: +bias->f32 | 1: relu(+bias)->bf16 | 2: +bias+resid->f32
// EPI 3: +bias->bf16 | 4: +bias+resid->f32 AND bf16 | 5: +bias->f32 AND bf16
template<int EPI>
__global__ void __launch_bounds__(256)
mma_gemm(const __nv_bfloat16* __restrict__ A, const __nv_bfloat16* __restrict__ Bw,
         const float* __restrict__ bias, const float* resid,
         float* __restrict__ Cf, __nv_bfloat16* __restrict__ Cb, int M, int K)
{
    extern __shared__ __nv_bfloat16 smd[];
    const int tid  = threadIdx.x;
    const int n0   = blockIdx.y * 128;
    const int m0   = blockIdx.x * 128;
    float acc[4][4][4];
    MMA_MAINLOOP();

    #pragma unroll
    for (int mt = 0; mt < 4; mt++) {
        const int r0 = n0 + wm + mt * 16 + g;
        #pragma unroll
        for (int nt = 0; nt < 4; nt++) {
            const int c = m0 + wn + nt * 8 + 2 * tig;
            const float2 bv = *reinterpret_cast<const float2*>(bias + c);
            float v00 = acc[mt][nt][0] + bv.x;
            float v01 = acc[mt][nt][1] + bv.y;
            float v10 = acc[mt][nt][2] + bv.x;
            float v11 = acc[mt][nt][3] + bv.y;
            if (EPI == 1) {
                v00 = fmaxf(v00, 0.f); v01 = fmaxf(v01, 0.f);
                v10 = fmaxf(v10, 0.f); v11 = fmaxf(v11, 0.f);
            }
            if (EPI == 2 || EPI == 4) {
                float2 q0 = *reinterpret_cast<const float2*>(resid + (size_t)r0 * M + c);
                float2 q1 = *reinterpret_cast<const float2*>(resid + (size_t)(r0 + 8) * M + c);
                v00 += q0.x; v01 += q0.y; v10 += q1.x; v11 += q1.y;
            }
            if (EPI == 1 || EPI == 3 || EPI == 4 || EPI == 5) {
                __nv_bfloat162 z0 = __floats2bfloat162_rn(v00, v01);
                __nv_bfloat162 z1 = __floats2bfloat162_rn(v10, v11);
                *reinterpret_cast<__nv_bfloat162*>(Cb + (size_t)r0 * M + c)       = z0;
                *reinterpret_cast<__nv_bfloat162*>(Cb + (size_t)(r0 + 8) * M + c) = z1;
            }
            if (EPI == 0 || EPI == 2 || EPI == 4 || EPI == 5) {
                *reinterpret_cast<float2*>(Cf + (size_t)r0 * M + c)       = make_float2(v00, v01);
                *reinterpret_cast<float2*>(Cf + (size_t)(r0 + 8) * M + c) = make_float2(v10, v11);
            }
        }
    }
}

// ---------------- bf16 MMA cdist: A_out = -sqrt(nx+ny-2*xf@Y^T) -------------
__global__ void __launch_bounds__(256)
mma_cdist(const __nv_bfloat16* __restrict__ XFB, const __nv_bfloat16* __restrict__ PB,
          const float* __restrict__ nx, const float* __restrict__ np,
          float* __restrict__ Aout)
{
    extern __shared__ __nv_bfloat16 smd[];
    const int tid = threadIdx.x;
    const int n0  = blockIdx.y * 128;
    const int m0  = blockIdx.x * 128;
    const int K   = XFD;
    const __nv_bfloat16* A  = XFB;
    const __nv_bfloat16* Bw = (m0 < 512) ? PB + (size_t)m0 * K
                                         : XFB + (size_t)(m0 - 512) * K;
    float acc[4][4][4];
    {
        const int m0_ = 0;  // Bw already offset
        #define m0 m0_
        MMA_MAINLOOP();
        #undef m0
        #pragma unroll
        for (int mt = 0; mt < 4; mt++) {
            const int r0 = n0 + wm + mt * 16 + g;
            const float nx0 = nx[r0], nx1 = nx[r0 + 8];
            #pragma unroll
            for (int nt = 0; nt < 4; nt++) {
                const int c = blockIdx.x * 128 + wn + nt * 8 + 2 * tig;
                float nyv0 = (c     < 512) ? np[c]     : nx[c - 512];
                float nyv1 = (c + 1 < 512) ? np[c + 1] : nx[c + 1 - 512];
                float r[4];
                r[0] = -sqrtf(fmaxf(nx0 + nyv0 - 2.f * acc[mt][nt][0], 0.f));
                r[1] = -sqrtf(fmaxf(nx0 + nyv1 - 2.f * acc[mt][nt][1], 0.f));
                r[2] = -sqrtf(fmaxf(nx1 + nyv0 - 2.f * acc[mt][nt][2], 0.f));
                r[3] = -sqrtf(fmaxf(nx1 + nyv1 - 2.f * acc[mt][nt][3], 0.f));
                if (c >= 512) {
                    if (c - 512 == r0)         r[0] -= 1e6f;
                    if (c + 1 - 512 == r0)     r[1] -= 1e6f;
                    if (c - 512 == r0 + 8)     r[2] -= 1e6f;
                    if (c + 1 - 512 == r0 + 8) r[3] -= 1e6f;
                }
                *reinterpret_cast<float2*>(Aout + (size_t)r0 * 1024 + c) =
                    make_float2(r[0], r[1]);
                *reinterpret_cast<float2*>(Aout + (size_t)(r0 + 8) * 1024 + c) =
                    make_float2(r[2], r[3]);
            }
        }
    }
}

// ---------------- bf16 MMA V-GEMM with fused sum(V^2) -----------------------
__global__ void __launch_bounds__(256)
mma_vsq(const __nv_bfloat16* __restrict__ W16, const __nv_bfloat16* __restrict__ YT,
        float* __restrict__ part)
{
    extern __shared__ __nv_bfloat16 smd[];
    const int tid = threadIdx.x;
    const int n0  = blockIdx.y * 128;
    const int m0  = blockIdx.x * 128;
    const int K   = 1024;
    const __nv_bfloat16* A  = W16;
    const __nv_bfloat16* Bw = YT;
    float acc[4][4][4];
    MMA_MAINLOOP();
    (void)tig; (void)g;

    float ss = 0.f;
    #pragma unroll
    for (int mt = 0; mt < 4; mt++)
        #pragma unroll
        for (int nt = 0; nt < 4; nt++)
            #pragma unroll
            for (int r = 0; r < 4; r++) ss += acc[mt][nt][r] * acc[mt][nt][r];
    // block reduce
    __shared__ float shred[32];
    #pragma unroll
    for (int off = 16; off; off >>= 1) ss += __shfl_xor_sync(0xffffffffu, ss, off);
    if (lane == 0) shred[w] = ss;
    __syncthreads();
    if (w == 0) {
        float r = (lane < 8) ? shred[lane] : 0.f;
        #pragma unroll
        for (int off = 4; off; off >>= 1) r += __shfl_xor_sync(0xffffffffu, r, off);
        if (lane == 0) part[blockIdx.y * gridDim.x + blockIdx.x] = r;
    }
}

// ---------------- transpose [p; xf] -> Yt (4096 x 1024) bf16 ---------------
__global__ void __launch_bounds__(256)
trans_yt_kernel(const float* __restrict__ p, const float* __restrict__ xf,
                __nv_bfloat16* __restrict__ yt)
{
    __shared__ float t[32][33];
    int k0 = blockIdx.x * 32;   // 0..1023 (rows of [p;xf])
    int j0 = blockIdx.y * 32;   // 0..4095
    int tx = threadIdx.x & 31, ty = threadIdx.x >> 5;  // 32 x 8
    #pragma unroll
    for (int i = 0; i < 4; i++) {
        int k = k0 + ty + i * 8;
        const float* src = (k < 512) ? p + (size_t)k * XFD : xf + (size_t)(k - 512) * XFD;
        t[ty + i * 8][tx] = src[j0 + tx];
    }
    __syncthreads();
    #pragma unroll
    for (int i = 0; i < 4; i++) {
        int j = j0 + ty + i * 8;
        yt[(size_t)j * 1024 + k0 + tx] = __float2bfloat16_rn(t[tx][ty + i * 8]);
    }
}

// ---------------- block reductions ----------------------------------------
__device__ __forceinline__ float block_reduce_sum(float v, float* sh) {
    int lane = threadIdx.x & 31, w = threadIdx.x >> 5;
    #pragma unroll
    for (int off = 16; off; off >>= 1) v += __shfl_xor_sync(0xffffffffu, v, off);
    if (lane == 0) sh[w] = v;
    __syncthreads();
    int nw = blockDim.x >> 5;
    if (w == 0) {
        float r = (lane < nw) ? sh[lane] : 0.f;
        #pragma unroll
        for (int off = 4; off; off >>= 1) r += __shfl_xor_sync(0xffffffffu, r, off);
        if (lane == 0) sh[0] = r;
    }
    __syncthreads();
    float res = sh[0];
    __syncthreads();
    return res;
}

__device__ __forceinline__ float block_reduce_max(float v, float* sh) {
    int lane = threadIdx.x & 31, w = threadIdx.x >> 5;
    #pragma unroll
    for (int off = 16; off; off >>= 1) v = fmaxf(v, __shfl_xor_sync(0xffffffffu, v, off));
    if (lane == 0) sh[w] = v;
    __syncthreads();
    int nw = blockDim.x >> 5;
    if (w == 0) {
        float r = (lane < nw) ? sh[lane] : -1e30f;
        #pragma unroll
        for (int off = 4; off; off >>= 1) r = fmaxf(r, __shfl_xor_sync(0xffffffffu, r, off));
        if (lane == 0) sh[0] = r;
    }
    __syncthreads();
    float res = sh[0];
    __syncthreads();
    return res;
}

// ---------------- LayerNorm (bf16 output feeds MMA) ------------------------
__global__ void __launch_bounds__(128)
ln_kernel(const float* __restrict__ x, const float* __restrict__ g,
          const float* __restrict__ b, __nv_bfloat16* __restrict__ out)
{
    int t = blockIdx.x;
    int tid = threadIdx.x;
    const float* xr = x + (size_t)t * DM;
    float4 v = *reinterpret_cast<const float4*>(xr + tid * 4);
    float s  = v.x + v.y + v.z + v.w;
    float sq = v.x*v.x + v.y*v.y + v.z*v.z + v.w*v.w;
    int lane = tid & 31, w = tid >> 5;
    #pragma unroll
    for (int off = 16; off; off >>= 1) {
        s  += __shfl_xor_sync(0xffffffffu, s,  off);
        sq += __shfl_xor_sync(0xffffffffu, sq, off);
    }
    __shared__ float shs[4], shq[4];
    if (lane == 0) { shs[w] = s; shq[w] = sq; }
    __syncthreads();
    s  = shs[0] + shs[1] + shs[2] + shs[3];
    sq = shq[0] + shq[1] + shq[2] + shq[3];
    float mean = s * (1.f / 512.f);
    float var  = sq * (1.f / 512.f) - mean * mean;
    float inv  = rsqrtf(var + 1e-5f);
    float4 gv = *reinterpret_cast<const float4*>(g + tid * 4);
    float4 bv = *reinterpret_cast<const float4*>(b + tid * 4);
    __nv_bfloat162 p0 = __floats2bfloat162_rn((v.x - mean) * inv * gv.x + bv.x,
                                              (v.y - mean) * inv * gv.y + bv.y);
    __nv_bfloat162 p1 = __floats2bfloat162_rn((v.z - mean) * inv * gv.z + bv.z,
                                              (v.w - mean) * inv * gv.w + bv.w);
    uint2 pk;
    pk.x = *reinterpret_cast<uint32_t*>(&p0);
    pk.y = *reinterpret_cast<uint32_t*>(&p1);
    *reinterpret_cast<uint2*>(out + (size_t)t * DM + tid * 4) = pk;
}

// ---------------- attention: one (batch, head) per block --------------------
__global__ void __launch_bounds__(256)
attn_kernel(const __nv_bfloat16* __restrict__ qkv, __nv_bfloat16* __restrict__ o)
{
    __shared__ float qs[32][68];
    __shared__ float kt[64][36];
    __shared__ float vs[32][64];
    __shared__ float ps[32][33];
    int bh = blockIdx.x;
    int b = bh >> 3, h = bh & 7;
    int tid = threadIdx.x;
    size_t base = (size_t)(b * 32) * QKVD + h * 64;
    #pragma unroll
    for (int l = 0; l < 2; l++) {
        int idx = tid + l * 256;
        int i = idx >> 4;
        int c = (idx & 15) << 2;
        uint2 qv = *reinterpret_cast<const uint2*>(qkv + base + (size_t)i * QKVD + c);
        uint2 kv = *reinterpret_cast<const uint2*>(qkv + base + (size_t)i * QKVD + 512 + c);
        uint2 vv = *reinterpret_cast<const uint2*>(qkv + base + (size_t)i * QKVD + 1024 + c);
        float2 q01 = __bfloat1622float2(*reinterpret_cast<__nv_bfloat162*>(&qv.x));
        float2 q23 = __bfloat1622float2(*reinterpret_cast<__nv_bfloat162*>(&qv.y));
        float2 k01 = __bfloat1622float2(*reinterpret_cast<__nv_bfloat162*>(&kv.x));
        float2 k23 = __bfloat1622float2(*reinterpret_cast<__nv_bfloat162*>(&kv.y));
        float2 v01 = __bfloat1622float2(*reinterpret_cast<__nv_bfloat162*>(&vv.x));
        float2 v23 = __bfloat1622float2(*reinterpret_cast<__nv_bfloat162*>(&vv.y));
        qs[i][c] = q01.x; qs[i][c+1] = q01.y; qs[i][c+2] = q23.x; qs[i][c+3] = q23.y;
        kt[c][i] = k01.x; kt[c+1][i] = k01.y; kt[c+2][i] = k23.x; kt[c+3][i] = k23.y;
        vs[i][c] = v01.x; vs[i][c+1] = v01.y; vs[i][c+2] = v23.x; vs[i][c+3] = v23.y;
    }
    __syncthreads();
    {
        int i = tid >> 3;
        int j0 = (tid & 7) << 2;
        float s0 = 0.f, s1 = 0.f, s2 = 0.f, s3 = 0.f;
        #pragma unroll
        for (int d = 0; d < 64; d += 4) {
            float4 q  = *reinterpret_cast<const float4*>(&qs[i][d]);
            float4 k0 = *reinterpret_cast<const float4*>(&kt[d  ][j0]);
            float4 k1 = *reinterpret_cast<const float4*>(&kt[d+1][j0]);
            float4 k2 = *reinterpret_cast<const float4*>(&kt[d+2][j0]);
            float4 k3 = *reinterpret_cast<const float4*>(&kt[d+3][j0]);
            s0 += q.x*k0.x + q.y*k1.x + q.z*k2.x + q.w*k3.x;
            s1 += q.x*k0.y + q.y*k1.y + q.z*k2.y + q.w*k3.y;
            s2 += q.x*k0.z + q.y*k1.z + q.z*k2.z + q.w*k3.z;
            s3 += q.x*k0.w + q.y*k1.w + q.z*k2.w + q.w*k3.w;
        }
        ps[i][j0]   = s0 * 0.125f;
        ps[i][j0+1] = s1 * 0.125f;
        ps[i][j0+2] = s2 * 0.125f;
        ps[i][j0+3] = s3 * 0.125f;
    }
    __syncthreads();
    {
        int w = tid >> 5, lane = tid & 31;
        #pragma unroll
        for (int r = 0; r < 4; r++) {
            int i = w + (r << 3);
            float v = ps[i][lane];
            float mx = v;
            #pragma unroll
            for (int off = 16; off; off >>= 1) mx = fmaxf(mx, __shfl_xor_sync(0xffffffffu, mx, off));
            float e = __expf(v - mx);
            float sm = e;
            #pragma unroll
            for (int off = 16; off; off >>= 1) sm += __shfl_xor_sync(0xffffffffu, sm, off);
            ps[i][lane] = e / sm;
        }
    }
    __syncthreads();
    {
        int i = tid >> 3;
        int d0 = (tid & 7) << 3;
        float4 a0 = make_float4(0.f,0.f,0.f,0.f);
        float4 a1 = make_float4(0.f,0.f,0.f,0.f);
        #pragma unroll
        for (int j = 0; j < 32; j++) {
            float pv = ps[i][j];
            float4 v0 = *reinterpret_cast<const float4*>(&vs[j][d0]);
            float4 v1 = *reinterpret_cast<const float4*>(&vs[j][d0+4]);
            a0.x += pv*v0.x; a0.y += pv*v0.y; a0.z += pv*v0.z; a0.w += pv*v0.w;
            a1.x += pv*v1.x; a1.y += pv*v1.y; a1.z += pv*v1.z; a1.w += pv*v1.w;
        }
        __nv_bfloat162 c0 = __floats2bfloat162_rn(a0.x, a0.y);
        __nv_bfloat162 c1 = __floats2bfloat162_rn(a0.z, a0.w);
        __nv_bfloat162 c2 = __floats2bfloat162_rn(a1.x, a1.y);
        __nv_bfloat162 c3 = __floats2bfloat162_rn(a1.z, a1.w);
        uint4 pk;
        pk.x = *reinterpret_cast<uint32_t*>(&c0);
        pk.y = *reinterpret_cast<uint32_t*>(&c1);
        pk.z = *reinterpret_cast<uint32_t*>(&c2);
        pk.w = *reinterpret_cast<uint32_t*>(&c3);
        *reinterpret_cast<uint4*>(o + (size_t)(b * 32 + i) * DM + h * 64 + d0) = pk;
    }
}

// ---------------- squared norms of xf rows and p rows -----------------------
__global__ void __launch_bounds__(256)
sqnorm_kernel(const float* __restrict__ xf, const float* __restrict__ p,
              float* __restrict__ nx, float* __restrict__ np)
{
    int r = blockIdx.x;
    const float* src = (r < 512) ? xf + (size_t)r * XFD : p + (size_t)(r - 512) * XFD;
    float s = 0.f;
    for (int c = threadIdx.x * 4; c < XFD; c += 256 * 4) {
        float4 v = *reinterpret_cast<const float4*>(src + c);
        s += v.x*v.x + v.y*v.y + v.z*v.z + v.w*v.w;
    }
    __shared__ float sh[32];
    float tot = block_reduce_sum(s, sh);
    if (threadIdx.x == 0) { if (r < 512) nx[r] = tot; else np[r - 512] = tot; }
}

// ---------------- row stats of A (max, sum of exp) ---------------------------
__global__ void __launch_bounds__(256)
rowstats_kernel(const float* __restrict__ A, float* __restrict__ rmax,
                float* __restrict__ rsum)
{
    int r = blockIdx.x;
    const float* ar = A + (size_t)r * 1024;
    float v[4];
    float mx = -1e30f;
    #pragma unroll
    for (int l = 0; l < 4; l++) { v[l] = ar[threadIdx.x + l * 256]; mx = fmaxf(mx, v[l]); }
    __shared__ float sh[32];
    mx = block_reduce_max(mx, sh);
    float s = 0.f;
    #pragma unroll
    for (int l = 0; l < 4; l++) s += __expf(v[l] - mx);
    s = block_reduce_sum(s, sh);
    if (threadIdx.x == 0) { rmax[r] = mx; rsum[r] = s; }
}

// ---------------- column stats of A ----------------------------------------
__global__ void __launch_bounds__(256)
colstats_kernel(const float* __restrict__ A, float* __restrict__ cmax,
                float* __restrict__ csum)
{
    int c = blockIdx.x * 256 + threadIdx.x;
    float mx = -1e30f;
    for (int i = 0; i < 512; i++) mx = fmaxf(mx, A[(size_t)i * 1024 + c]);
    float s = 0.f;
    for (int i = 0; i < 512; i++) s += __expf(A[(size_t)i * 1024 + c] - mx);
    cmax[c] = mx; csum[c] = s;
}

// ---------------- build W (bf16) = [A_pos*sneg | -(A_neg*spos)] -------------
__global__ void __launch_bounds__(256)
wbuild_kernel(const float* __restrict__ A, const float* __restrict__ rmax,
              const float* __restrict__ rsum, const float* __restrict__ cmax,
              const float* __restrict__ csum, __nv_bfloat16* __restrict__ W16)
{
    int r = blockIdx.x;
    int j0 = threadIdx.x * 4;
    float rm = rmax[r];
    float rs = rsum[r];
    float4 a = *reinterpret_cast<const float4*>(A + (size_t)r * 1024 + j0);
    float av[4] = {a.x, a.y, a.z, a.w};
    float soft[4];
    float lsum = 0.f;
    #pragma unroll
    for (int l = 0; l < 4; l++) {
        int j = j0 + l;
        float s = __expf(av[l] - 0.5f * (rm + cmax[j])) * rsqrtf(rs * csum[j]);
        soft[l] = s;
        lsum += s;
    }
    bool isneg = (threadIdx.x >= 128);
    __shared__ float sh[32];
    float sp = block_reduce_sum(isneg ? 0.f : lsum, sh);
    float sn = block_reduce_sum(isneg ? lsum : 0.f, sh);
    float scale = isneg ? -(sp * sn) : sn;
    __nv_bfloat162 z0 = __floats2bfloat162_rn(soft[0]*scale, soft[1]*scale);
    __nv_bfloat162 z1 = __floats2bfloat162_rn(soft[2]*scale, soft[3]*scale);
    uint2 pk;
    pk.x = *reinterpret_cast<uint32_t*>(&z0);
    pk.y = *reinterpret_cast<uint32_t*>(&z1);
    *reinterpret_cast<uint2*>(W16 + (size_t)r * 1024 + j0) = pk;
}

// ---------------- final reduce → mean(V^2) ----------------------------------
__global__ void __launch_bounds__(128)
finalize_kernel(const float* __restrict__ part, float* __restrict__ out)
{
    __shared__ float sh[32];
    float v = part[threadIdx.x];
    float tot = block_reduce_sum(v, sh);
    if (threadIdx.x == 0) out[0] = tot * (1.f / (512.f * 4096.f));
}

// ---------------- host launch ------------------------------------------------
extern "C" void kernel_launch(void* const* d_in, const int* in_sizes, int n_in,
                              void* d_out, int out_size)
{
    (void)in_sizes; (void)n_in; (void)out_size;
    const float* p     = (const float*)d_in[0];
    const float* eps   = (const float*)d_in[1];
    const float* in_w  = (const float*)d_in[2];
    const float* in_b  = (const float*)d_in[3];
    const float* Wqkv  = (const float*)d_in[4];
    const float* bqkv  = (const float*)d_in[5];
    const float* Wo    = (const float*)d_in[6];
    const float* bo    = (const float*)d_in[7];
    const float* ln1g  = (const float*)d_in[8];
    const float* ln1b  = (const float*)d_in[9];
    const float* W1    = (const float*)d_in[10];
    const float* b1    = (const float*)d_in[11];
    const float* W2    = (const float*)d_in[12];
    const float* b2    = (const float*)d_in[13];
    const float* ln2g  = (const float*)d_in[14];
    const float* ln2b  = (const float*)d_in[15];
    const float* out_w = (const float*)d_in[16];
    const float* out_b = (const float*)d_in[17];
    float* out = (float*)d_out;

    float *px, *pxf, *pA;
    float *pnx, *pnp, *prmax, *prsum, *pcmax, *pcsum, *ppart;
    __nv_bfloat16 *peps, *phb, *pattn, *pqkvb, *pffb, *pxb, *pwb;
    __nv_bfloat16 *pxfb, *ppb, *pyt, *pw16;
    cudaGetSymbolAddress((void**)&px,    g_x);
    cudaGetSymbolAddress((void**)&pxf,   g_xf);
    cudaGetSymbolAddress((void**)&pA,    g_A);
    cudaGetSymbolAddress((void**)&pnx,   g_nx);
    cudaGetSymbolAddress((void**)&pnp,   g_np);
    cudaGetSymbolAddress((void**)&prmax, g_rmax);
    cudaGetSymbolAddress((void**)&prsum, g_rsum);
    cudaGetSymbolAddress((void**)&pcmax, g_cmax);
    cudaGetSymbolAddress((void**)&pcsum, g_csum);
    cudaGetSymbolAddress((void**)&ppart, g_part);
    cudaGetSymbolAddress((void**)&peps,  b_eps);
    cudaGetSymbolAddress((void**)&phb,   b_h);
    cudaGetSymbolAddress((void**)&pattn, b_attn);
    cudaGetSymbolAddress((void**)&pqkvb, b_qkv);
    cudaGetSymbolAddress((void**)&pffb,  b_ff);
    cudaGetSymbolAddress((void**)&pxb,   b_x);
    cudaGetSymbolAddress((void**)&pwb,   b_wts);
    cudaGetSymbolAddress((void**)&pxfb,  b_xfb);
    cudaGetSymbolAddress((void**)&ppb,   b_p);
    cudaGetSymbolAddress((void**)&pyt,   b_yt);
    cudaGetSymbolAddress((void**)&pw16,  b_w16);

    cudaFuncSetAttribute(mma_gemm<0>, cudaFuncAttributeMaxDynamicSharedMemorySize, MM_SMEM);
    cudaFuncSetAttribute(mma_gemm<1>, cudaFuncAttributeMaxDynamicSharedMemorySize, MM_SMEM);
    cudaFuncSetAttribute(mma_gemm<2>, cudaFuncAttributeMaxDynamicSharedMemorySize, MM_SMEM);
    cudaFuncSetAttribute(mma_gemm<3>, cudaFuncAttributeMaxDynamicSharedMemorySize, MM_SMEM);
    cudaFuncSetAttribute(mma_gemm<4>, cudaFuncAttributeMaxDynamicSharedMemorySize, MM_SMEM);
    cudaFuncSetAttribute(mma_gemm<5>, cudaFuncAttributeMaxDynamicSharedMemorySize, MM_SMEM);
    cudaFuncSetAttribute(mma_cdist,   cudaFuncAttributeMaxDynamicSharedMemorySize, MM_SMEM);
    cudaFuncSetAttribute(mma_vsq,     cudaFuncAttributeMaxDynamicSharedMemorySize, MM_SMEM);

    dim3 blk(256);
    auto rblocks = [](int n) { return (n / 4 + 255) / 256; };

    // convert weights + eps + p to bf16 (round-nearest)
    cvt_bf16_kernel<<<rblocks(DM*CHD),    blk>>>(in_w,  pwb + R_INW,  DM*CHD);
    cvt_bf16_kernel<<<rblocks(4*QKVD*DM), blk>>>(Wqkv,  pwb + R_QKV,  4*QKVD*DM);
    cvt_bf16_kernel<<<rblocks(4*DM*DM),   blk>>>(Wo,    pwb + R_WO,   4*DM*DM);
    cvt_bf16_kernel<<<rblocks(4*FFD*DM),  blk>>>(W1,    pwb + R_W1,   4*FFD*DM);
    cvt_bf16_kernel<<<rblocks(4*DM*FFD),  blk>>>(W2,    pwb + R_W2,   4*DM*FFD);
    cvt_bf16_kernel<<<rblocks(CHD*DM),    blk>>>(out_w, pwb + R_OUTW, CHD*DM);
    cvt_bf16_kernel<<<rblocks(NTOK*CHD),  blk>>>(eps,   peps,         NTOK*CHD);
    cvt_bf16_kernel<<<rblocks(NB*XFD),    blk>>>(p,     ppb,          NB*XFD);

    // x = eps @ in_w^T + in_b   (fp32 out)
    mma_gemm<0><<<dim3(DM/128, NTOK/128), blk, MM_SMEM>>>(peps, pwb + R_INW, in_b,
                                                          nullptr, px, nullptr, DM, CHD);
    for (int i = 0; i < 4; i++) {
        ln_kernel<<<NTOK, 128>>>(px, ln1g + i*DM, ln1b + i*DM, phb);
        mma_gemm<3><<<dim3(QKVD/128, NTOK/128), blk, MM_SMEM>>>(
            phb, pwb + R_QKV + (size_t)i*QKVD*DM, bqkv + (size_t)i*QKVD,
            nullptr, nullptr, pqkvb, QKVD, DM);
        attn_kernel<<<4096, 256>>>(pqkvb, pattn);
        mma_gemm<2><<<dim3(DM/128, NTOK/128), blk, MM_SMEM>>>(
            pattn, pwb + R_WO + (size_t)i*DM*DM, bo + (size_t)i*DM,
            px, px, nullptr, DM, DM);
        ln_kernel<<<NTOK, 128>>>(px, ln2g + i*DM, ln2b + i*DM, phb);
        mma_gemm<1><<<dim3(FFD/128, NTOK/128), blk, MM_SMEM>>>(
            phb, pwb + R_W1 + (size_t)i*FFD*DM, b1 + (size_t)i*FFD,
            nullptr, nullptr, pffb, FFD, DM);
        if (i < 3) {
            mma_gemm<2><<<dim3(DM/128, NTOK/128), blk, MM_SMEM>>>(
                pffb, pwb + R_W2 + (size_t)i*DM*FFD, b2 + (size_t)i*DM,
                px, px, nullptr, DM, FFD);
        } else {
            mma_gemm<4><<<dim3(DM/128, NTOK/128), blk, MM_SMEM>>>(
                pffb, pwb + R_W2 + (size_t)i*DM*FFD, b2 + (size_t)i*DM,
                px, px, pxb, DM, FFD);
        }
    }
    // xf = x @ out_w^T + out_b : dual write fp32 (norms/transpose) + bf16 (MMA)
    mma_gemm<5><<<dim3(CHD/128, NTOK/128), blk, MM_SMEM>>>(pxb, pwb + R_OUTW, out_b,
                                                           nullptr, pxf, pxfb, CHD, DM);

    // compute_V: bf16 MMA GEMMs, exact fp32 stats
    sqnorm_kernel<<<1024, 256>>>(pxf, p, pnx, pnp);
    mma_cdist<<<dim3(1024/128, NB/128), blk, MM_SMEM>>>(pxfb, ppb, pnx, pnp, pA);
    rowstats_kernel<<<NB, 256>>>(pA, prmax, prsum);
    colstats_kernel<<<4, 256>>>(pA, pcmax, pcsum);
    wbuild_kernel<<<NB, 256>>>(pA, prmax, prsum, pcmax, pcsum, pw16);
    trans_yt_kernel<<<dim3(1024/32, XFD/32), 256>>>(p, pxf, pyt);
    mma_vsq<<<dim3(XFD/128, NB/128), blk, MM_SMEM>>>(pw16, pyt, ppart);
    finalize_kernel<<<1, 128>>>(ppart, out);
}